// round 1
// baseline (speedup 1.0000x reference)
#include <cuda_runtime.h>
#include <cuda_bf16.h>
#include <cstdint>

// Problem constants
#define BATCH 4
#define SEQ   2048
#define DIM   1024
#define HEADS 16
#define HD    64
#define ROWS  (BATCH * SEQ)          // 8192
#define QKV_N (HEADS * 3 * HD)       // 3072

// -------- scratch (static device globals; no allocation allowed) --------
__device__ float g_xn[ROWS * DIM];                    // layernorm output [8192,1024]
__device__ float g_q [BATCH * HEADS * SEQ * HD];      // [b,h,s,d]
__device__ float g_k [BATCH * HEADS * SEQ * HD];
__device__ float g_v [BATCH * HEADS * SEQ * HD];
__device__ float g_y [ROWS * DIM];                    // attn out in [b,s,h,d] == [8192,1024]

// ============================ LayerNorm ============================
__global__ void __launch_bounds__(256) ln_kernel(
    const float* __restrict__ x,
    const float* __restrict__ gamma,
    const float* __restrict__ beta,
    float* __restrict__ out)
{
    int row = blockIdx.x;              // 0..8191
    int t = threadIdx.x;               // 256 threads, 4 floats each
    const float4* xr = reinterpret_cast<const float4*>(x + (size_t)row * DIM);
    float4 v = xr[t];
    float s1 = v.x + v.y + v.z + v.w;
    float s2 = v.x*v.x + v.y*v.y + v.z*v.z + v.w*v.w;
    #pragma unroll
    for (int o = 16; o > 0; o >>= 1) {
        s1 += __shfl_xor_sync(0xffffffffu, s1, o);
        s2 += __shfl_xor_sync(0xffffffffu, s2, o);
    }
    __shared__ float r1[8], r2[8];
    __shared__ float sh_mu, sh_rstd;
    if ((t & 31) == 0) { r1[t >> 5] = s1; r2[t >> 5] = s2; }
    __syncthreads();
    if (t == 0) {
        float a = 0.f, b = 0.f;
        #pragma unroll
        for (int i = 0; i < 8; i++) { a += r1[i]; b += r2[i]; }
        float mu  = a * (1.0f / DIM);
        float var = b * (1.0f / DIM) - mu * mu;
        sh_mu = mu;
        sh_rstd = rsqrtf(var + 1e-6f);
    }
    __syncthreads();
    float mu = sh_mu, rstd = sh_rstd;
    float4 g = reinterpret_cast<const float4*>(gamma)[t];
    float4 b4 = reinterpret_cast<const float4*>(beta)[t];
    float4 o4;
    o4.x = (v.x - mu) * rstd * g.x + b4.x;
    o4.y = (v.y - mu) * rstd * g.y + b4.y;
    o4.z = (v.z - mu) * rstd * g.z + b4.z;
    o4.w = (v.w - mu) * rstd * g.w + b4.w;
    reinterpret_cast<float4*>(out + (size_t)row * DIM)[t] = o4;
}

// ============================ SGEMM 128x128x8 ============================
// C[M,N] = A[M,K] @ B[K,N]  (+bias). MODE 0: scatter into q/k/v with q-scale.
// MODE 1: plain C = A@B + bias.
template <int MODE>
__global__ void __launch_bounds__(256) sgemm_kernel(
    const float* __restrict__ A,
    const float* __restrict__ B,
    const float* __restrict__ bias,
    float* __restrict__ Cout,
    int M, int N, int K,
    float* __restrict__ qout,
    float* __restrict__ kout,
    float* __restrict__ vout)
{
    __shared__ float As[8][128];
    __shared__ float Bs[8][128];

    int tid = threadIdx.x;
    int tx = tid & 15, ty = tid >> 4;
    int m0 = blockIdx.y * 128;
    int n0 = blockIdx.x * 128;

    float acc[8][8];
    #pragma unroll
    for (int i = 0; i < 8; i++)
        #pragma unroll
        for (int j = 0; j < 8; j++) acc[i][j] = 0.f;

    int arow = tid >> 1;            // 0..127
    int acol = (tid & 1) * 4;       // 0 or 4
    int brow = tid >> 5;            // 0..7
    int bcol = (tid & 31) * 4;      // 0..124

    const float* Aptr = A + (size_t)(m0 + arow) * K + acol;
    const float* Bptr = B + (size_t)brow * N + n0 + bcol;

    for (int k0 = 0; k0 < K; k0 += 8) {
        float4 a = *reinterpret_cast<const float4*>(Aptr); Aptr += 8;
        float4 b = *reinterpret_cast<const float4*>(Bptr); Bptr += (size_t)8 * N;
        As[acol + 0][arow] = a.x;
        As[acol + 1][arow] = a.y;
        As[acol + 2][arow] = a.z;
        As[acol + 3][arow] = a.w;
        *reinterpret_cast<float4*>(&Bs[brow][bcol]) = b;
        __syncthreads();
        #pragma unroll
        for (int kk = 0; kk < 8; kk++) {
            float ra[8], rb[8];
            *reinterpret_cast<float4*>(ra)     = *reinterpret_cast<const float4*>(&As[kk][ty * 4]);
            *reinterpret_cast<float4*>(ra + 4) = *reinterpret_cast<const float4*>(&As[kk][64 + ty * 4]);
            *reinterpret_cast<float4*>(rb)     = *reinterpret_cast<const float4*>(&Bs[kk][tx * 4]);
            *reinterpret_cast<float4*>(rb + 4) = *reinterpret_cast<const float4*>(&Bs[kk][64 + tx * 4]);
            #pragma unroll
            for (int i = 0; i < 8; i++)
                #pragma unroll
                for (int j = 0; j < 8; j++)
                    acc[i][j] += ra[i] * rb[j];
        }
        __syncthreads();
    }

    #pragma unroll
    for (int i = 0; i < 8; i++) {
        int m = m0 + ((i < 4) ? (ty * 4 + i) : (64 + ty * 4 + i - 4));
        #pragma unroll
        for (int j = 0; j < 8; j++) {
            int n = n0 + ((j < 4) ? (tx * 4 + j) : (64 + tx * 4 + j - 4));
            float val = acc[i][j] + bias[n];
            if (MODE == 0) {
                int h = n / 192;
                int f = n - h * 192;
                int bb = m >> 11;        // /2048
                int ss = m & 2047;
                size_t base = (((size_t)(bb * HEADS + h)) * SEQ + ss) * HD;
                if (f < 64)       qout[base + f]        = val * 0.125f;  // 1/sqrt(64)
                else if (f < 128) kout[base + f - 64]   = val;
                else              vout[base + f - 128]  = val;
            } else {
                Cout[(size_t)m * N + n] = val;
            }
        }
    }
}

// ============================ Flash attention (fp32) ============================
// One block: 64 query rows of one (b,h). 256 threads = 16x16, 4x4 micro-tile.
__global__ void __launch_bounds__(256) attn_kernel(
    const float* __restrict__ q,
    const float* __restrict__ k,
    const float* __restrict__ v,
    float* __restrict__ y)
{
    extern __shared__ float sm[];
    float* Qt = sm;                 // [64][64] transposed: Qt[d*64 + r]
    float* Kt = Qt + 4096;          // [64][64] transposed: Kt[d*64 + c]
    float* Vs = Kt + 4096;          // [64][68] padded:     Vs[c*68 + d]
    float* Ps = Vs + 64 * 68;       // [64][64]:            Ps[r*64 + c]

    int qt = blockIdx.x;            // query tile 0..31
    int bh = blockIdx.y;            // 0..63
    int tid = threadIdx.x;
    int tx = tid & 15, ty = tid >> 4;

    const float* qb = q + (size_t)bh * SEQ * HD;
    const float* kb = k + (size_t)bh * SEQ * HD;
    const float* vb = v + (size_t)bh * SEQ * HD;
    int q0 = qt * 64;

    // load Q tile transposed
    #pragma unroll
    for (int i = 0; i < 4; i++) {
        int idx = tid + i * 256;
        int r = idx >> 4;
        int d4 = (idx & 15) << 2;
        float4 a = *reinterpret_cast<const float4*>(qb + (size_t)(q0 + r) * HD + d4);
        Qt[(d4 + 0) * 64 + r] = a.x;
        Qt[(d4 + 1) * 64 + r] = a.y;
        Qt[(d4 + 2) * 64 + r] = a.z;
        Qt[(d4 + 3) * 64 + r] = a.w;
    }

    float m_i[4], l_i[4], o[4][4];
    #pragma unroll
    for (int i = 0; i < 4; i++) {
        m_i[i] = -1e30f; l_i[i] = 0.f;
        #pragma unroll
        for (int j = 0; j < 4; j++) o[i][j] = 0.f;
    }

    for (int kt = 0; kt <= qt; kt++) {
        int c0 = kt * 64;
        __syncthreads();   // Qt visible (first iter); Ps/Vs consumed (later iters)
        #pragma unroll
        for (int i = 0; i < 4; i++) {
            int idx = tid + i * 256;
            int r = idx >> 4;
            int d4 = (idx & 15) << 2;
            float4 a = *reinterpret_cast<const float4*>(kb + (size_t)(c0 + r) * HD + d4);
            Kt[(d4 + 0) * 64 + r] = a.x;
            Kt[(d4 + 1) * 64 + r] = a.y;
            Kt[(d4 + 2) * 64 + r] = a.z;
            Kt[(d4 + 3) * 64 + r] = a.w;
            float4 b = *reinterpret_cast<const float4*>(vb + (size_t)(c0 + r) * HD + d4);
            *reinterpret_cast<float4*>(&Vs[r * 68 + d4]) = b;
        }
        __syncthreads();

        // scores: s[i][j] = q_row(ty*4+i) . k_col(tx*4+j)
        float s[4][4];
        #pragma unroll
        for (int i = 0; i < 4; i++)
            #pragma unroll
            for (int j = 0; j < 4; j++) s[i][j] = 0.f;

        #pragma unroll 16
        for (int dd = 0; dd < 64; dd++) {
            float qa[4], ka[4];
            *reinterpret_cast<float4*>(qa) = *reinterpret_cast<const float4*>(&Qt[dd * 64 + ty * 4]);
            *reinterpret_cast<float4*>(ka) = *reinterpret_cast<const float4*>(&Kt[dd * 64 + tx * 4]);
            #pragma unroll
            for (int i = 0; i < 4; i++)
                #pragma unroll
                for (int j = 0; j < 4; j++)
                    s[i][j] += qa[i] * ka[j];
        }

        if (kt == qt) {  // causal mask on the diagonal tile
            #pragma unroll
            for (int i = 0; i < 4; i++)
                #pragma unroll
                for (int j = 0; j < 4; j++)
                    if (tx * 4 + j > ty * 4 + i) s[i][j] = -1e30f;
        }

        // online softmax per row
        #pragma unroll
        for (int i = 0; i < 4; i++) {
            float mx = fmaxf(fmaxf(s[i][0], s[i][1]), fmaxf(s[i][2], s[i][3]));
            mx = fmaxf(mx, __shfl_xor_sync(0xffffffffu, mx, 1));
            mx = fmaxf(mx, __shfl_xor_sync(0xffffffffu, mx, 2));
            mx = fmaxf(mx, __shfl_xor_sync(0xffffffffu, mx, 4));
            mx = fmaxf(mx, __shfl_xor_sync(0xffffffffu, mx, 8));
            float mnew = fmaxf(m_i[i], mx);
            float p0 = __expf(s[i][0] - mnew);
            float p1 = __expf(s[i][1] - mnew);
            float p2 = __expf(s[i][2] - mnew);
            float p3 = __expf(s[i][3] - mnew);
            float rs = p0 + p1 + p2 + p3;
            rs += __shfl_xor_sync(0xffffffffu, rs, 1);
            rs += __shfl_xor_sync(0xffffffffu, rs, 2);
            rs += __shfl_xor_sync(0xffffffffu, rs, 4);
            rs += __shfl_xor_sync(0xffffffffu, rs, 8);
            float corr = __expf(m_i[i] - mnew);
            l_i[i] = l_i[i] * corr + rs;
            m_i[i] = mnew;
            o[i][0] *= corr; o[i][1] *= corr; o[i][2] *= corr; o[i][3] *= corr;
            *reinterpret_cast<float4*>(&Ps[(ty * 4 + i) * 64 + tx * 4]) =
                make_float4(p0, p1, p2, p3);
        }
        __syncthreads();

        // O += P @ V   (o[i][j]: rows ty*4+i, dims tx*4+j)
        #pragma unroll 8
        for (int c = 0; c < 64; c++) {
            float vv[4];
            *reinterpret_cast<float4*>(vv) = *reinterpret_cast<const float4*>(&Vs[c * 68 + tx * 4]);
            #pragma unroll
            for (int i = 0; i < 4; i++) {
                float pr = Ps[(ty * 4 + i) * 64 + c];
                o[i][0] += pr * vv[0];
                o[i][1] += pr * vv[1];
                o[i][2] += pr * vv[2];
                o[i][3] += pr * vv[3];
            }
        }
    }

    // epilogue: normalize, write y[b, s, h, d]
    int b = bh >> 4, h = bh & 15;
    #pragma unroll
    for (int i = 0; i < 4; i++) {
        float inv = 1.0f / l_i[i];
        int srow = q0 + ty * 4 + i;
        float4 ov = make_float4(o[i][0] * inv, o[i][1] * inv, o[i][2] * inv, o[i][3] * inv);
        *reinterpret_cast<float4*>(y + (((size_t)(b * SEQ + srow)) * HEADS + h) * HD + tx * 4) = ov;
    }
}

// ============================ launch ============================
extern "C" void kernel_launch(void* const* d_in, const int* in_sizes, int n_in,
                              void* d_out, int out_size)
{
    const float* x        = (const float*)d_in[0];
    // d_in[1] = mask (causal, known statically — unused)
    const float* ln_scale = (const float*)d_in[2];
    const float* ln_bias  = (const float*)d_in[3];
    const float* w_qkv    = (const float*)d_in[4];
    const float* b_qkv    = (const float*)d_in[5];
    const float* w_out    = (const float*)d_in[6];
    const float* b_out    = (const float*)d_in[7];
    float* out = (float*)d_out;

    float *xn, *q, *k, *v, *y;
    cudaGetSymbolAddress((void**)&xn, g_xn);
    cudaGetSymbolAddress((void**)&q,  g_q);
    cudaGetSymbolAddress((void**)&k,  g_k);
    cudaGetSymbolAddress((void**)&v,  g_v);
    cudaGetSymbolAddress((void**)&y,  g_y);

    // 1. LayerNorm
    ln_kernel<<<ROWS, 256>>>(x, ln_scale, ln_bias, xn);

    // 2. QKV projection with scatter + q-scale
    {
        dim3 grid(QKV_N / 128, ROWS / 128);  // (24, 64)
        sgemm_kernel<0><<<grid, 256>>>(xn, w_qkv, b_qkv, nullptr,
                                       ROWS, QKV_N, DIM, q, k, v);
    }

    // 3. causal flash attention
    {
        int smem = (4096 + 4096 + 64 * 68 + 4096) * sizeof(float);  // 66560
        cudaFuncSetAttribute(attn_kernel,
                             cudaFuncAttributeMaxDynamicSharedMemorySize, smem);
        dim3 grid(SEQ / 64, BATCH * HEADS);  // (32, 64)
        attn_kernel<<<grid, 256, smem>>>(q, k, v, y);
    }

    // 4. output projection -> d_out
    {
        dim3 grid(DIM / 128, ROWS / 128);    // (8, 64)
        sgemm_kernel<1><<<grid, 256>>>(y, w_out, b_out, out,
                                       ROWS, DIM, DIM, nullptr, nullptr, nullptr);
    }
}

// round 2
// speedup vs baseline: 1.4249x; 1.4249x over previous
#include <cuda_runtime.h>
#include <cuda_bf16.h>
#include <cstdint>

// Problem constants
#define BATCH 4
#define SEQ   2048
#define DIM   1024
#define HEADS 16
#define HD    64
#define ROWS  (BATCH * SEQ)          // 8192
#define QKV_N (HEADS * 3 * HD)       // 3072

// -------- scratch (static device globals; no allocation allowed) --------
__device__ __nv_bfloat16 g_xn_hi[ROWS * DIM];
__device__ __nv_bfloat16 g_xn_lo[ROWS * DIM];
__device__ __nv_bfloat16 g_wq_hi[DIM * QKV_N];
__device__ __nv_bfloat16 g_wq_lo[DIM * QKV_N];
__device__ __nv_bfloat16 g_wo_hi[DIM * DIM];
__device__ __nv_bfloat16 g_wo_lo[DIM * DIM];
__device__ float g_q [BATCH * HEADS * SEQ * HD];      // [b,h,s,d]
__device__ float g_k [BATCH * HEADS * SEQ * HD];
__device__ float g_v [BATCH * HEADS * SEQ * HD];
__device__ __nv_bfloat16 g_y_hi[ROWS * DIM];          // attn out [b,s,h,d]
__device__ __nv_bfloat16 g_y_lo[ROWS * DIM];

// ============================ helpers ============================
__device__ __forceinline__ uint32_t s2u(const void* p) {
    return (uint32_t)__cvta_generic_to_shared(p);
}
__device__ __forceinline__ void ldsm4(uint32_t* r, uint32_t addr) {
    asm volatile("ldmatrix.sync.aligned.m8n8.x4.shared.b16 {%0,%1,%2,%3}, [%4];\n"
                 : "=r"(r[0]), "=r"(r[1]), "=r"(r[2]), "=r"(r[3]) : "r"(addr));
}
__device__ __forceinline__ void ldsm4t(uint32_t* r, uint32_t addr) {
    asm volatile("ldmatrix.sync.aligned.m8n8.x4.trans.shared.b16 {%0,%1,%2,%3}, [%4];\n"
                 : "=r"(r[0]), "=r"(r[1]), "=r"(r[2]), "=r"(r[3]) : "r"(addr));
}
__device__ __forceinline__ void mma_bf16(float* c, const uint32_t* a, const uint32_t* b) {
    asm volatile(
        "mma.sync.aligned.m16n8k16.row.col.f32.bf16.bf16.f32 "
        "{%0,%1,%2,%3}, {%4,%5,%6,%7}, {%8,%9}, {%0,%1,%2,%3};\n"
        : "+f"(c[0]), "+f"(c[1]), "+f"(c[2]), "+f"(c[3])
        : "r"(a[0]), "r"(a[1]), "r"(a[2]), "r"(a[3]), "r"(b[0]), "r"(b[1]));
}
__device__ __forceinline__ void split_bf16(float x, __nv_bfloat16& h, __nv_bfloat16& l) {
    h = __float2bfloat16_rn(x);
    l = __float2bfloat16_rn(x - __bfloat162float(h));
}

// ============================ LayerNorm -> hi/lo bf16 ============================
__global__ void __launch_bounds__(256) ln_kernel(
    const float* __restrict__ x,
    const float* __restrict__ gamma,
    const float* __restrict__ beta,
    __nv_bfloat16* __restrict__ out_hi,
    __nv_bfloat16* __restrict__ out_lo)
{
    int row = blockIdx.x;
    int t = threadIdx.x;
    const float4* xr = reinterpret_cast<const float4*>(x + (size_t)row * DIM);
    float4 v = xr[t];
    float s1 = v.x + v.y + v.z + v.w;
    float s2 = v.x*v.x + v.y*v.y + v.z*v.z + v.w*v.w;
    #pragma unroll
    for (int o = 16; o > 0; o >>= 1) {
        s1 += __shfl_xor_sync(0xffffffffu, s1, o);
        s2 += __shfl_xor_sync(0xffffffffu, s2, o);
    }
    __shared__ float r1[8], r2[8];
    __shared__ float sh_mu, sh_rstd;
    if ((t & 31) == 0) { r1[t >> 5] = s1; r2[t >> 5] = s2; }
    __syncthreads();
    if (t == 0) {
        float a = 0.f, b = 0.f;
        #pragma unroll
        for (int i = 0; i < 8; i++) { a += r1[i]; b += r2[i]; }
        float mu  = a * (1.0f / DIM);
        float var = b * (1.0f / DIM) - mu * mu;
        sh_mu = mu;
        sh_rstd = rsqrtf(var + 1e-6f);
    }
    __syncthreads();
    float mu = sh_mu, rstd = sh_rstd;
    float4 g = reinterpret_cast<const float4*>(gamma)[t];
    float4 b4 = reinterpret_cast<const float4*>(beta)[t];
    float o4[4];
    o4[0] = (v.x - mu) * rstd * g.x + b4.x;
    o4[1] = (v.y - mu) * rstd * g.y + b4.y;
    o4[2] = (v.z - mu) * rstd * g.z + b4.z;
    o4[3] = (v.w - mu) * rstd * g.w + b4.w;
    size_t base = (size_t)row * DIM + t * 4;
    #pragma unroll
    for (int i = 0; i < 4; i++) {
        __nv_bfloat16 h, l;
        split_bf16(o4[i], h, l);
        out_hi[base + i] = h;
        out_lo[base + i] = l;
    }
}

// ============================ weight decomposition ============================
__global__ void __launch_bounds__(256) decomp_kernel(
    const float* __restrict__ w,
    __nv_bfloat16* __restrict__ hi,
    __nv_bfloat16* __restrict__ lo,
    int n)
{
    int i = blockIdx.x * blockDim.x + threadIdx.x;
    int stride = gridDim.x * blockDim.x;
    for (; i < n; i += stride) {
        __nv_bfloat16 h, l;
        split_bf16(w[i], h, l);
        hi[i] = h;
        lo[i] = l;
    }
}

// ============================ bf16x3 MMA GEMM 128x128x16 ============================
// C = A@B + bias where A = Ah+Al, B = Bh+Bl (bf16 splits of fp32).
// MODE 0: scatter into q/k/v with q-scale. MODE 1: plain C.
template <int MODE>
__global__ void __launch_bounds__(256, 2) mma_gemm(
    const __nv_bfloat16* __restrict__ Ahg, const __nv_bfloat16* __restrict__ Alg,
    const __nv_bfloat16* __restrict__ Bhg, const __nv_bfloat16* __restrict__ Blg,
    const float* __restrict__ bias,
    float* __restrict__ Cout,
    int M, int N, int K,
    float* __restrict__ qout, float* __restrict__ kout, float* __restrict__ vout)
{
    __shared__ __align__(16) __nv_bfloat16 sAh[128][24];
    __shared__ __align__(16) __nv_bfloat16 sAl[128][24];
    __shared__ __align__(16) __nv_bfloat16 sBh[16][136];
    __shared__ __align__(16) __nv_bfloat16 sBl[16][136];

    int tid = threadIdx.x;
    int lane = tid & 31;
    int wid = tid >> 5;
    int wm = wid & 1;          // warp row (0..1) -> 64 rows each
    int wn = wid >> 1;         // warp col (0..3) -> 32 cols each
    int m0 = blockIdx.y * 128;
    int n0 = blockIdx.x * 128;

    // gmem load coords
    int arow = tid >> 1;            // 0..127
    int acol = (tid & 1) * 8;       // 0 or 8
    int brow = tid >> 4;            // 0..15
    int bcol = (tid & 15) * 8;      // 0..120

    const __nv_bfloat16* pAh = Ahg + (size_t)(m0 + arow) * K + acol;
    const __nv_bfloat16* pAl = Alg + (size_t)(m0 + arow) * K + acol;
    const __nv_bfloat16* pBh = Bhg + (size_t)brow * N + n0 + bcol;
    const __nv_bfloat16* pBl = Blg + (size_t)brow * N + n0 + bcol;

    float acc[4][4][4];
    #pragma unroll
    for (int i = 0; i < 4; i++)
        #pragma unroll
        for (int j = 0; j < 4; j++)
            #pragma unroll
            for (int e = 0; e < 4; e++) acc[i][j][e] = 0.f;

    // prefetch k-slice 0
    uint4 ra_h = *reinterpret_cast<const uint4*>(pAh);
    uint4 ra_l = *reinterpret_cast<const uint4*>(pAl);
    uint4 rb_h = *reinterpret_cast<const uint4*>(pBh);
    uint4 rb_l = *reinterpret_cast<const uint4*>(pBl);

    // ldmatrix smem addresses (loop-invariant)
    int lrow = lane & 15;
    int lcol = (lane >> 4) * 8;
    uint32_t addrAh[4], addrAl[4];
    #pragma unroll
    for (int i = 0; i < 4; i++) {
        addrAh[i] = s2u(&sAh[wm * 64 + i * 16 + lrow][lcol]);
        addrAl[i] = s2u(&sAl[wm * 64 + i * 16 + lrow][lcol]);
    }
    uint32_t addrBh[2], addrBl[2];
    #pragma unroll
    for (int jj = 0; jj < 2; jj++) {
        addrBh[jj] = s2u(&sBh[lrow][wn * 32 + jj * 16 + lcol]);
        addrBl[jj] = s2u(&sBl[lrow][wn * 32 + jj * 16 + lcol]);
    }

    int niter = K / 16;
    for (int kt = 0; kt < niter; kt++) {
        *reinterpret_cast<uint4*>(&sAh[arow][acol]) = ra_h;
        *reinterpret_cast<uint4*>(&sAl[arow][acol]) = ra_l;
        *reinterpret_cast<uint4*>(&sBh[brow][bcol]) = rb_h;
        *reinterpret_cast<uint4*>(&sBl[brow][bcol]) = rb_l;
        __syncthreads();

        if (kt + 1 < niter) {
            int ko = (kt + 1) * 16;
            ra_h = *reinterpret_cast<const uint4*>(pAh + ko);
            ra_l = *reinterpret_cast<const uint4*>(pAl + ko);
            rb_h = *reinterpret_cast<const uint4*>(pBh + (size_t)ko * N);
            rb_l = *reinterpret_cast<const uint4*>(pBl + (size_t)ko * N);
        }

        uint32_t ah[4][4], al[4][4], bb[4][2];
        #pragma unroll
        for (int i = 0; i < 4; i++) {
            ldsm4(ah[i], addrAh[i]);
            ldsm4(al[i], addrAl[i]);
        }
        #pragma unroll
        for (int jj = 0; jj < 2; jj++) {
            uint32_t r[4];
            ldsm4t(r, addrBh[jj]);
            bb[jj * 2][0] = r[0]; bb[jj * 2][1] = r[1];
            bb[jj * 2 + 1][0] = r[2]; bb[jj * 2 + 1][1] = r[3];
        }
        // pass 1: Ah*Bh, pass 2: Al*Bh
        #pragma unroll
        for (int i = 0; i < 4; i++)
            #pragma unroll
            for (int j = 0; j < 4; j++) {
                mma_bf16(acc[i][j], ah[i], bb[j]);
                mma_bf16(acc[i][j], al[i], bb[j]);
            }
        // pass 3: Ah*Bl
        #pragma unroll
        for (int jj = 0; jj < 2; jj++) {
            uint32_t r[4];
            ldsm4t(r, addrBl[jj]);
            bb[jj * 2][0] = r[0]; bb[jj * 2][1] = r[1];
            bb[jj * 2 + 1][0] = r[2]; bb[jj * 2 + 1][1] = r[3];
        }
        #pragma unroll
        for (int i = 0; i < 4; i++)
            #pragma unroll
            for (int j = 0; j < 4; j++)
                mma_bf16(acc[i][j], ah[i], bb[j]);
        __syncthreads();
    }

    // epilogue
    int gid = lane >> 2, tig = lane & 3;
    #pragma unroll
    for (int i = 0; i < 4; i++) {
        #pragma unroll
        for (int j = 0; j < 4; j++) {
            #pragma unroll
            for (int e = 0; e < 4; e++) {
                int m = m0 + wm * 64 + i * 16 + gid + ((e >> 1) ? 8 : 0);
                int n = n0 + wn * 32 + j * 8 + 2 * tig + (e & 1);
                float val = acc[i][j][e] + bias[n];
                if (MODE == 0) {
                    int h = n / 192;
                    int f = n - h * 192;
                    int bb2 = m >> 11;
                    int ss = m & 2047;
                    size_t base = (((size_t)(bb2 * HEADS + h)) * SEQ + ss) * HD;
                    if (f < 64)       qout[base + f]       = val * 0.125f;
                    else if (f < 128) kout[base + f - 64]  = val;
                    else              vout[base + f - 128] = val;
                } else {
                    Cout[(size_t)m * N + n] = val;
                }
            }
        }
    }
}

// ============================ Flash attention (fp32) ============================
__global__ void __launch_bounds__(256) attn_kernel(
    const float* __restrict__ q,
    const float* __restrict__ k,
    const float* __restrict__ v,
    __nv_bfloat16* __restrict__ y_hi,
    __nv_bfloat16* __restrict__ y_lo)
{
    extern __shared__ float sm[];
    float* Qt = sm;                 // [64][64] transposed
    float* Kt = Qt + 4096;          // [64][64] transposed
    float* Vs = Kt + 4096;          // [64][68] padded
    float* Ps = Vs + 64 * 68;       // [64][64]

    int qt = blockIdx.x;
    int bh = blockIdx.y;
    int tid = threadIdx.x;
    int tx = tid & 15, ty = tid >> 4;

    const float* qb = q + (size_t)bh * SEQ * HD;
    const float* kb = k + (size_t)bh * SEQ * HD;
    const float* vb = v + (size_t)bh * SEQ * HD;
    int q0 = qt * 64;

    #pragma unroll
    for (int i = 0; i < 4; i++) {
        int idx = tid + i * 256;
        int r = idx >> 4;
        int d4 = (idx & 15) << 2;
        float4 a = *reinterpret_cast<const float4*>(qb + (size_t)(q0 + r) * HD + d4);
        Qt[(d4 + 0) * 64 + r] = a.x;
        Qt[(d4 + 1) * 64 + r] = a.y;
        Qt[(d4 + 2) * 64 + r] = a.z;
        Qt[(d4 + 3) * 64 + r] = a.w;
    }

    float m_i[4], l_i[4], o[4][4];
    #pragma unroll
    for (int i = 0; i < 4; i++) {
        m_i[i] = -1e30f; l_i[i] = 0.f;
        #pragma unroll
        for (int j = 0; j < 4; j++) o[i][j] = 0.f;
    }

    for (int kt = 0; kt <= qt; kt++) {
        int c0 = kt * 64;
        __syncthreads();
        #pragma unroll
        for (int i = 0; i < 4; i++) {
            int idx = tid + i * 256;
            int r = idx >> 4;
            int d4 = (idx & 15) << 2;
            float4 a = *reinterpret_cast<const float4*>(kb + (size_t)(c0 + r) * HD + d4);
            Kt[(d4 + 0) * 64 + r] = a.x;
            Kt[(d4 + 1) * 64 + r] = a.y;
            Kt[(d4 + 2) * 64 + r] = a.z;
            Kt[(d4 + 3) * 64 + r] = a.w;
            float4 b = *reinterpret_cast<const float4*>(vb + (size_t)(c0 + r) * HD + d4);
            *reinterpret_cast<float4*>(&Vs[r * 68 + d4]) = b;
        }
        __syncthreads();

        float s[4][4];
        #pragma unroll
        for (int i = 0; i < 4; i++)
            #pragma unroll
            for (int j = 0; j < 4; j++) s[i][j] = 0.f;

        #pragma unroll 16
        for (int dd = 0; dd < 64; dd++) {
            float qa[4], ka[4];
            *reinterpret_cast<float4*>(qa) = *reinterpret_cast<const float4*>(&Qt[dd * 64 + ty * 4]);
            *reinterpret_cast<float4*>(ka) = *reinterpret_cast<const float4*>(&Kt[dd * 64 + tx * 4]);
            #pragma unroll
            for (int i = 0; i < 4; i++)
                #pragma unroll
                for (int j = 0; j < 4; j++)
                    s[i][j] += qa[i] * ka[j];
        }

        if (kt == qt) {
            #pragma unroll
            for (int i = 0; i < 4; i++)
                #pragma unroll
                for (int j = 0; j < 4; j++)
                    if (tx * 4 + j > ty * 4 + i) s[i][j] = -1e30f;
        }

        #pragma unroll
        for (int i = 0; i < 4; i++) {
            float mx = fmaxf(fmaxf(s[i][0], s[i][1]), fmaxf(s[i][2], s[i][3]));
            mx = fmaxf(mx, __shfl_xor_sync(0xffffffffu, mx, 1));
            mx = fmaxf(mx, __shfl_xor_sync(0xffffffffu, mx, 2));
            mx = fmaxf(mx, __shfl_xor_sync(0xffffffffu, mx, 4));
            mx = fmaxf(mx, __shfl_xor_sync(0xffffffffu, mx, 8));
            float mnew = fmaxf(m_i[i], mx);
            float p0 = __expf(s[i][0] - mnew);
            float p1 = __expf(s[i][1] - mnew);
            float p2 = __expf(s[i][2] - mnew);
            float p3 = __expf(s[i][3] - mnew);
            float rs = p0 + p1 + p2 + p3;
            rs += __shfl_xor_sync(0xffffffffu, rs, 1);
            rs += __shfl_xor_sync(0xffffffffu, rs, 2);
            rs += __shfl_xor_sync(0xffffffffu, rs, 4);
            rs += __shfl_xor_sync(0xffffffffu, rs, 8);
            float corr = __expf(m_i[i] - mnew);
            l_i[i] = l_i[i] * corr + rs;
            m_i[i] = mnew;
            o[i][0] *= corr; o[i][1] *= corr; o[i][2] *= corr; o[i][3] *= corr;
            *reinterpret_cast<float4*>(&Ps[(ty * 4 + i) * 64 + tx * 4]) =
                make_float4(p0, p1, p2, p3);
        }
        __syncthreads();

        #pragma unroll 8
        for (int c = 0; c < 64; c++) {
            float vv[4];
            *reinterpret_cast<float4*>(vv) = *reinterpret_cast<const float4*>(&Vs[c * 68 + tx * 4]);
            #pragma unroll
            for (int i = 0; i < 4; i++) {
                float pr = Ps[(ty * 4 + i) * 64 + c];
                o[i][0] += pr * vv[0];
                o[i][1] += pr * vv[1];
                o[i][2] += pr * vv[2];
                o[i][3] += pr * vv[3];
            }
        }
    }

    // epilogue: normalize and write y_hi/y_lo [b, s, h, d]
    int b = bh >> 4, h = bh & 15;
    #pragma unroll
    for (int i = 0; i < 4; i++) {
        float inv = 1.0f / l_i[i];
        int srow = q0 + ty * 4 + i;
        size_t base = (((size_t)(b * SEQ + srow)) * HEADS + h) * HD + tx * 4;
        #pragma unroll
        for (int j = 0; j < 4; j++) {
            float val = o[i][j] * inv;
            __nv_bfloat16 hh, ll;
            split_bf16(val, hh, ll);
            y_hi[base + j] = hh;
            y_lo[base + j] = ll;
        }
    }
}

// ============================ launch ============================
extern "C" void kernel_launch(void* const* d_in, const int* in_sizes, int n_in,
                              void* d_out, int out_size)
{
    const float* x        = (const float*)d_in[0];
    const float* ln_scale = (const float*)d_in[2];
    const float* ln_bias  = (const float*)d_in[3];
    const float* w_qkv    = (const float*)d_in[4];
    const float* b_qkv    = (const float*)d_in[5];
    const float* w_out    = (const float*)d_in[6];
    const float* b_out    = (const float*)d_in[7];
    float* out = (float*)d_out;

    __nv_bfloat16 *xn_hi, *xn_lo, *wq_hi, *wq_lo, *wo_hi, *wo_lo, *y_hi, *y_lo;
    float *q, *k, *v;
    cudaGetSymbolAddress((void**)&xn_hi, g_xn_hi);
    cudaGetSymbolAddress((void**)&xn_lo, g_xn_lo);
    cudaGetSymbolAddress((void**)&wq_hi, g_wq_hi);
    cudaGetSymbolAddress((void**)&wq_lo, g_wq_lo);
    cudaGetSymbolAddress((void**)&wo_hi, g_wo_hi);
    cudaGetSymbolAddress((void**)&wo_lo, g_wo_lo);
    cudaGetSymbolAddress((void**)&y_hi,  g_y_hi);
    cudaGetSymbolAddress((void**)&y_lo,  g_y_lo);
    cudaGetSymbolAddress((void**)&q,  g_q);
    cudaGetSymbolAddress((void**)&k,  g_k);
    cudaGetSymbolAddress((void**)&v,  g_v);

    // 1. LayerNorm -> bf16 hi/lo
    ln_kernel<<<ROWS, 256>>>(x, ln_scale, ln_bias, xn_hi, xn_lo);

    // 1b. weight decomposition
    decomp_kernel<<<512, 256>>>(w_qkv, wq_hi, wq_lo, DIM * QKV_N);
    decomp_kernel<<<256, 256>>>(w_out, wo_hi, wo_lo, DIM * DIM);

    // 2. QKV projection (bf16x3 tensor) with scatter + q-scale
    {
        dim3 grid(QKV_N / 128, ROWS / 128);  // (24, 64)
        mma_gemm<0><<<grid, 256>>>(xn_hi, xn_lo, wq_hi, wq_lo, b_qkv, nullptr,
                                   ROWS, QKV_N, DIM, q, k, v);
    }

    // 3. causal flash attention (fp32), writes y hi/lo
    {
        int smem = (4096 + 4096 + 64 * 68 + 4096) * sizeof(float);  // 66560
        cudaFuncSetAttribute(attn_kernel,
                             cudaFuncAttributeMaxDynamicSharedMemorySize, smem);
        dim3 grid(SEQ / 64, BATCH * HEADS);  // (32, 64)
        attn_kernel<<<grid, 256, smem>>>(q, k, v, y_hi, y_lo);
    }

    // 4. output projection (bf16x3 tensor) -> d_out
    {
        dim3 grid(DIM / 128, ROWS / 128);    // (8, 64)
        mma_gemm<1><<<grid, 256>>>(y_hi, y_lo, wo_hi, wo_lo, b_out, out,
                                   ROWS, DIM, DIM, nullptr, nullptr, nullptr);
    }
}

// round 3
// speedup vs baseline: 2.5534x; 1.7920x over previous
#include <cuda_runtime.h>
#include <cuda_bf16.h>
#include <cstdint>

// Problem constants
#define BATCH 4
#define SEQ   2048
#define DIM   1024
#define HEADS 16
#define HD    64
#define ROWS  (BATCH * SEQ)          // 8192
#define QKV_N (HEADS * 3 * HD)       // 3072
#define BHSD  (BATCH * HEADS * SEQ * HD)

// -------- scratch (static device globals; no allocation allowed) --------
__device__ __nv_bfloat16 g_xn_hi[ROWS * DIM];
__device__ __nv_bfloat16 g_xn_lo[ROWS * DIM];
__device__ __nv_bfloat16 g_wq_hi[DIM * QKV_N];
__device__ __nv_bfloat16 g_wq_lo[DIM * QKV_N];
__device__ __nv_bfloat16 g_wo_hi[DIM * DIM];
__device__ __nv_bfloat16 g_wo_lo[DIM * DIM];
__device__ __nv_bfloat16 g_qh[BHSD];   // [b,h,s,d] bf16 hi/lo
__device__ __nv_bfloat16 g_ql[BHSD];
__device__ __nv_bfloat16 g_kh[BHSD];
__device__ __nv_bfloat16 g_kl[BHSD];
__device__ __nv_bfloat16 g_vh[BHSD];
__device__ __nv_bfloat16 g_vl[BHSD];
__device__ __nv_bfloat16 g_y_hi[ROWS * DIM];   // attn out [b,s,h,d]
__device__ __nv_bfloat16 g_y_lo[ROWS * DIM];

// ============================ helpers ============================
__device__ __forceinline__ uint32_t s2u(const void* p) {
    return (uint32_t)__cvta_generic_to_shared(p);
}
__device__ __forceinline__ void ldsm4(uint32_t* r, uint32_t addr) {
    asm volatile("ldmatrix.sync.aligned.m8n8.x4.shared.b16 {%0,%1,%2,%3}, [%4];\n"
                 : "=r"(r[0]), "=r"(r[1]), "=r"(r[2]), "=r"(r[3]) : "r"(addr));
}
__device__ __forceinline__ void ldsm4t(uint32_t* r, uint32_t addr) {
    asm volatile("ldmatrix.sync.aligned.m8n8.x4.trans.shared.b16 {%0,%1,%2,%3}, [%4];\n"
                 : "=r"(r[0]), "=r"(r[1]), "=r"(r[2]), "=r"(r[3]) : "r"(addr));
}
__device__ __forceinline__ void mma_bf16(float* c, const uint32_t* a, const uint32_t* b) {
    asm volatile(
        "mma.sync.aligned.m16n8k16.row.col.f32.bf16.bf16.f32 "
        "{%0,%1,%2,%3}, {%4,%5,%6,%7}, {%8,%9}, {%0,%1,%2,%3};\n"
        : "+f"(c[0]), "+f"(c[1]), "+f"(c[2]), "+f"(c[3])
        : "r"(a[0]), "r"(a[1]), "r"(a[2]), "r"(a[3]), "r"(b[0]), "r"(b[1]));
}
__device__ __forceinline__ void split_bf16(float x, __nv_bfloat16& h, __nv_bfloat16& l) {
    h = __float2bfloat16_rn(x);
    l = __float2bfloat16_rn(x - __bfloat162float(h));
}
// pack two floats into bf16x2 hi reg + residual lo reg
__device__ __forceinline__ void pack_hi_lo(float a, float b, uint32_t& hi, uint32_t& lo) {
    __nv_bfloat162 h2 = __floats2bfloat162_rn(a, b);     // low = a
    float ra = a - __low2float(h2);
    float rb = b - __high2float(h2);
    __nv_bfloat162 l2 = __floats2bfloat162_rn(ra, rb);
    hi = *reinterpret_cast<uint32_t*>(&h2);
    lo = *reinterpret_cast<uint32_t*>(&l2);
}
// fast exp on FMA pipe (no MUFU). valid for x <= 0, handles very negative x.
__device__ __forceinline__ float fast_exp(float x) {
    float t = x * 1.4426950408889634f;
    t = fmaxf(t, -126.0f);
    float fi = rintf(t);
    float g = (t - fi) * 0.6931471805599453f;  // |g| <= 0.347
    float p = 8.3333333e-3f;
    p = fmaf(p, g, 4.1666667e-2f);
    p = fmaf(p, g, 0.16666667f);
    p = fmaf(p, g, 0.5f);
    p = fmaf(p, g, 1.0f);
    p = fmaf(p, g, 1.0f);
    int ei = (int)fi;
    float sc = __int_as_float((ei + 127) << 23);
    return sc * p;
}

// ============================ LayerNorm -> hi/lo bf16 ============================
__global__ void __launch_bounds__(256) ln_kernel(
    const float* __restrict__ x,
    const float* __restrict__ gamma,
    const float* __restrict__ beta,
    __nv_bfloat16* __restrict__ out_hi,
    __nv_bfloat16* __restrict__ out_lo)
{
    int row = blockIdx.x;
    int t = threadIdx.x;
    const float4* xr = reinterpret_cast<const float4*>(x + (size_t)row * DIM);
    float4 v = xr[t];
    float s1 = v.x + v.y + v.z + v.w;
    float s2 = v.x*v.x + v.y*v.y + v.z*v.z + v.w*v.w;
    #pragma unroll
    for (int o = 16; o > 0; o >>= 1) {
        s1 += __shfl_xor_sync(0xffffffffu, s1, o);
        s2 += __shfl_xor_sync(0xffffffffu, s2, o);
    }
    __shared__ float r1[8], r2[8];
    __shared__ float sh_mu, sh_rstd;
    if ((t & 31) == 0) { r1[t >> 5] = s1; r2[t >> 5] = s2; }
    __syncthreads();
    if (t == 0) {
        float a = 0.f, b = 0.f;
        #pragma unroll
        for (int i = 0; i < 8; i++) { a += r1[i]; b += r2[i]; }
        float mu  = a * (1.0f / DIM);
        float var = b * (1.0f / DIM) - mu * mu;
        sh_mu = mu;
        sh_rstd = rsqrtf(var + 1e-6f);
    }
    __syncthreads();
    float mu = sh_mu, rstd = sh_rstd;
    float4 g = reinterpret_cast<const float4*>(gamma)[t];
    float4 b4 = reinterpret_cast<const float4*>(beta)[t];
    float o4[4];
    o4[0] = (v.x - mu) * rstd * g.x + b4.x;
    o4[1] = (v.y - mu) * rstd * g.y + b4.y;
    o4[2] = (v.z - mu) * rstd * g.z + b4.z;
    o4[3] = (v.w - mu) * rstd * g.w + b4.w;
    size_t base = (size_t)row * DIM + t * 4;
    #pragma unroll
    for (int i = 0; i < 4; i++) {
        __nv_bfloat16 h, l;
        split_bf16(o4[i], h, l);
        out_hi[base + i] = h;
        out_lo[base + i] = l;
    }
}

// ============================ weight decomposition ============================
__global__ void __launch_bounds__(256) decomp_kernel(
    const float* __restrict__ w,
    __nv_bfloat16* __restrict__ hi,
    __nv_bfloat16* __restrict__ lo,
    int n)
{
    int i = blockIdx.x * blockDim.x + threadIdx.x;
    int stride = gridDim.x * blockDim.x;
    for (; i < n; i += stride) {
        __nv_bfloat16 h, l;
        split_bf16(w[i], h, l);
        hi[i] = h;
        lo[i] = l;
    }
}

// ============================ bf16x3 MMA GEMM 128x128x16 ============================
// MODE 0: QKV — scatter bf16 hi/lo into q/k/v ([b,h,s,d]) with q-scale.
// MODE 1: plain fp32 C = A@B + bias.
template <int MODE>
__global__ void __launch_bounds__(256, 2) mma_gemm(
    const __nv_bfloat16* __restrict__ Ahg, const __nv_bfloat16* __restrict__ Alg,
    const __nv_bfloat16* __restrict__ Bhg, const __nv_bfloat16* __restrict__ Blg,
    const float* __restrict__ bias,
    float* __restrict__ Cout,
    int M, int N, int K,
    __nv_bfloat16* __restrict__ qh, __nv_bfloat16* __restrict__ ql,
    __nv_bfloat16* __restrict__ kh, __nv_bfloat16* __restrict__ kl,
    __nv_bfloat16* __restrict__ vh, __nv_bfloat16* __restrict__ vl)
{
    __shared__ __align__(16) __nv_bfloat16 sAh[128][24];
    __shared__ __align__(16) __nv_bfloat16 sAl[128][24];
    __shared__ __align__(16) __nv_bfloat16 sBh[16][136];
    __shared__ __align__(16) __nv_bfloat16 sBl[16][136];

    int tid = threadIdx.x;
    int lane = tid & 31;
    int wid = tid >> 5;
    int wm = wid & 1;
    int wn = wid >> 1;
    int m0 = blockIdx.y * 128;
    int n0 = blockIdx.x * 128;

    int arow = tid >> 1;
    int acol = (tid & 1) * 8;
    int brow = tid >> 4;
    int bcol = (tid & 15) * 8;

    const __nv_bfloat16* pAh = Ahg + (size_t)(m0 + arow) * K + acol;
    const __nv_bfloat16* pAl = Alg + (size_t)(m0 + arow) * K + acol;
    const __nv_bfloat16* pBh = Bhg + (size_t)brow * N + n0 + bcol;
    const __nv_bfloat16* pBl = Blg + (size_t)brow * N + n0 + bcol;

    float acc[4][4][4];
    #pragma unroll
    for (int i = 0; i < 4; i++)
        #pragma unroll
        for (int j = 0; j < 4; j++)
            #pragma unroll
            for (int e = 0; e < 4; e++) acc[i][j][e] = 0.f;

    uint4 ra_h = *reinterpret_cast<const uint4*>(pAh);
    uint4 ra_l = *reinterpret_cast<const uint4*>(pAl);
    uint4 rb_h = *reinterpret_cast<const uint4*>(pBh);
    uint4 rb_l = *reinterpret_cast<const uint4*>(pBl);

    int lrow = lane & 15;
    int lcol = (lane >> 4) * 8;
    uint32_t addrAh[4], addrAl[4];
    #pragma unroll
    for (int i = 0; i < 4; i++) {
        addrAh[i] = s2u(&sAh[wm * 64 + i * 16 + lrow][lcol]);
        addrAl[i] = s2u(&sAl[wm * 64 + i * 16 + lrow][lcol]);
    }
    uint32_t addrBh[2], addrBl[2];
    #pragma unroll
    for (int jj = 0; jj < 2; jj++) {
        addrBh[jj] = s2u(&sBh[lrow][wn * 32 + jj * 16 + lcol]);
        addrBl[jj] = s2u(&sBl[lrow][wn * 32 + jj * 16 + lcol]);
    }

    int niter = K / 16;
    for (int kt = 0; kt < niter; kt++) {
        *reinterpret_cast<uint4*>(&sAh[arow][acol]) = ra_h;
        *reinterpret_cast<uint4*>(&sAl[arow][acol]) = ra_l;
        *reinterpret_cast<uint4*>(&sBh[brow][bcol]) = rb_h;
        *reinterpret_cast<uint4*>(&sBl[brow][bcol]) = rb_l;
        __syncthreads();

        if (kt + 1 < niter) {
            int ko = (kt + 1) * 16;
            ra_h = *reinterpret_cast<const uint4*>(pAh + ko);
            ra_l = *reinterpret_cast<const uint4*>(pAl + ko);
            rb_h = *reinterpret_cast<const uint4*>(pBh + (size_t)ko * N);
            rb_l = *reinterpret_cast<const uint4*>(pBl + (size_t)ko * N);
        }

        uint32_t ah[4][4], al[4][4], bb[4][2];
        #pragma unroll
        for (int i = 0; i < 4; i++) {
            ldsm4(ah[i], addrAh[i]);
            ldsm4(al[i], addrAl[i]);
        }
        #pragma unroll
        for (int jj = 0; jj < 2; jj++) {
            uint32_t r[4];
            ldsm4t(r, addrBh[jj]);
            bb[jj * 2][0] = r[0]; bb[jj * 2][1] = r[1];
            bb[jj * 2 + 1][0] = r[2]; bb[jj * 2 + 1][1] = r[3];
        }
        #pragma unroll
        for (int i = 0; i < 4; i++)
            #pragma unroll
            for (int j = 0; j < 4; j++) {
                mma_bf16(acc[i][j], ah[i], bb[j]);
                mma_bf16(acc[i][j], al[i], bb[j]);
            }
        #pragma unroll
        for (int jj = 0; jj < 2; jj++) {
            uint32_t r[4];
            ldsm4t(r, addrBl[jj]);
            bb[jj * 2][0] = r[0]; bb[jj * 2][1] = r[1];
            bb[jj * 2 + 1][0] = r[2]; bb[jj * 2 + 1][1] = r[3];
        }
        #pragma unroll
        for (int i = 0; i < 4; i++)
            #pragma unroll
            for (int j = 0; j < 4; j++)
                mma_bf16(acc[i][j], ah[i], bb[j]);
        __syncthreads();
    }

    int gid = lane >> 2, tig = lane & 3;
    #pragma unroll
    for (int i = 0; i < 4; i++) {
        #pragma unroll
        for (int j = 0; j < 4; j++) {
            int n = n0 + wn * 32 + j * 8 + 2 * tig;
            if (MODE == 0) {
                int hq = n / 192;
                int f = n - hq * 192;
                #pragma unroll
                for (int rh = 0; rh < 2; rh++) {
                    int m = m0 + wm * 64 + i * 16 + gid + rh * 8;
                    float v0 = acc[i][j][rh * 2 + 0] + bias[n];
                    float v1 = acc[i][j][rh * 2 + 1] + bias[n + 1];
                    int bb2 = m >> 11;
                    int ss = m & 2047;
                    size_t base = (((size_t)(bb2 * HEADS + hq)) * SEQ + ss) * HD;
                    __nv_bfloat16 *dh, *dl;
                    int off;
                    if (f < 64)       { v0 *= 0.125f; v1 *= 0.125f; dh = qh; dl = ql; off = f; }
                    else if (f < 128) { dh = kh; dl = kl; off = f - 64; }
                    else              { dh = vh; dl = vl; off = f - 128; }
                    uint32_t hi, lo;
                    pack_hi_lo(v0, v1, hi, lo);
                    *reinterpret_cast<uint32_t*>(&dh[base + off]) = hi;
                    *reinterpret_cast<uint32_t*>(&dl[base + off]) = lo;
                }
            } else {
                #pragma unroll
                for (int rh = 0; rh < 2; rh++) {
                    int m = m0 + wm * 64 + i * 16 + gid + rh * 8;
                    float v0 = acc[i][j][rh * 2 + 0] + bias[n];
                    float v1 = acc[i][j][rh * 2 + 1] + bias[n + 1];
                    float2 st = make_float2(v0, v1);
                    *reinterpret_cast<float2*>(&Cout[(size_t)m * N + n]) = st;
                }
            }
        }
    }
}

// ============================ Tensor-core flash attention ============================
// BM=128 query rows per block (8 warps x m16), BN=64 keys per tile.
// bf16x3 compensated QK^T and P.V; exp via FMA-pipe polynomial.
__global__ void __launch_bounds__(256) attn_mma_kernel(
    const __nv_bfloat16* __restrict__ qh_g, const __nv_bfloat16* __restrict__ ql_g,
    const __nv_bfloat16* __restrict__ kh_g, const __nv_bfloat16* __restrict__ kl_g,
    const __nv_bfloat16* __restrict__ vh_g, const __nv_bfloat16* __restrict__ vl_g,
    __nv_bfloat16* __restrict__ y_hi, __nv_bfloat16* __restrict__ y_lo)
{
    extern __shared__ __nv_bfloat16 smb[];
    __nv_bfloat16* sQh = smb;                 // [128][72]
    __nv_bfloat16* sQl = sQh + 128 * 72;
    __nv_bfloat16* sKh = sQl + 128 * 72;      // [64][72]
    __nv_bfloat16* sKl = sKh + 64 * 72;
    __nv_bfloat16* sVh = sKl + 64 * 72;
    __nv_bfloat16* sVl = sVh + 64 * 72;

    int bh = blockIdx.x;                // 0..63
    int qt = (gridDim.y - 1) - blockIdx.y;   // heavy tiles launch first
    int tid = threadIdx.x;
    int lane = tid & 31;
    int w = tid >> 5;
    int gid = lane >> 2, tig = lane & 3;
    int lrow = lane & 15, lcol = (lane >> 4) * 8;

    int q0 = qt * 128;
    const size_t bhoff = (size_t)bh * SEQ * HD;

    // load Q tile (128 x 64) hi/lo
    #pragma unroll
    for (int i = 0; i < 4; i++) {
        int chunk = tid + i * 256;       // 0..1023
        int r = chunk >> 3, d8 = (chunk & 7) * 8;
        size_t g = bhoff + (size_t)(q0 + r) * HD + d8;
        *reinterpret_cast<uint4*>(&sQh[r * 72 + d8]) = *reinterpret_cast<const uint4*>(&qh_g[g]);
        *reinterpret_cast<uint4*>(&sQl[r * 72 + d8]) = *reinterpret_cast<const uint4*>(&ql_g[g]);
    }
    __syncthreads();

    // hoist Q fragments (resident across key loop)
    uint32_t qfh[4][4], qfl[4][4];
    #pragma unroll
    for (int kk = 0; kk < 4; kk++) {
        ldsm4(qfh[kk], s2u(&sQh[(w * 16 + lrow) * 72 + kk * 16 + lcol]));
        ldsm4(qfl[kk], s2u(&sQl[(w * 16 + lrow) * 72 + kk * 16 + lcol]));
    }

    float m_r[2] = {-1e30f, -1e30f};
    float l_r[2] = {0.f, 0.f};
    float o[8][4];
    #pragma unroll
    for (int j = 0; j < 8; j++)
        #pragma unroll
        for (int c = 0; c < 4; c++) o[j][c] = 0.f;

    int ktmax = 2 * qt + 1;
    for (int kt = 0; kt <= ktmax; kt++) {
        int c0 = kt * 64;
        __syncthreads();
        #pragma unroll
        for (int i = 0; i < 2; i++) {
            int chunk = tid + i * 256;   // 0..511
            int r = chunk >> 3, d8 = (chunk & 7) * 8;
            size_t g = bhoff + (size_t)(c0 + r) * HD + d8;
            *reinterpret_cast<uint4*>(&sKh[r * 72 + d8]) = *reinterpret_cast<const uint4*>(&kh_g[g]);
            *reinterpret_cast<uint4*>(&sKl[r * 72 + d8]) = *reinterpret_cast<const uint4*>(&kl_g[g]);
            *reinterpret_cast<uint4*>(&sVh[r * 72 + d8]) = *reinterpret_cast<const uint4*>(&vh_g[g]);
            *reinterpret_cast<uint4*>(&sVl[r * 72 + d8]) = *reinterpret_cast<const uint4*>(&vl_g[g]);
        }
        __syncthreads();

        // ---- S = Q K^T (compensated) ----
        float s[8][4];
        #pragma unroll
        for (int j = 0; j < 8; j++)
            #pragma unroll
            for (int c = 0; c < 4; c++) s[j][c] = 0.f;

        #pragma unroll
        for (int kk = 0; kk < 4; kk++) {
            #pragma unroll
            for (int g2 = 0; g2 < 4; g2++) {
                uint32_t rh[4], rl[4];
                ldsm4(rh, s2u(&sKh[(g2 * 16 + lrow) * 72 + kk * 16 + lcol]));
                ldsm4(rl, s2u(&sKl[(g2 * 16 + lrow) * 72 + kk * 16 + lcol]));
                uint32_t b0h[2] = {rh[0], rh[2]}, b1h[2] = {rh[1], rh[3]};
                uint32_t b0l[2] = {rl[0], rl[2]}, b1l[2] = {rl[1], rl[3]};
                mma_bf16(s[g2 * 2],     qfh[kk], b0h);
                mma_bf16(s[g2 * 2],     qfl[kk], b0h);
                mma_bf16(s[g2 * 2],     qfh[kk], b0l);
                mma_bf16(s[g2 * 2 + 1], qfh[kk], b1h);
                mma_bf16(s[g2 * 2 + 1], qfl[kk], b1h);
                mma_bf16(s[g2 * 2 + 1], qfh[kk], b1l);
            }
        }

        // causal mask on boundary tiles
        if (kt >= 2 * qt) {
            int row0 = q0 + w * 16 + gid;
            #pragma unroll
            for (int j = 0; j < 8; j++) {
                int col = c0 + j * 8 + 2 * tig;
                if (col     > row0)     s[j][0] = -1e30f;
                if (col + 1 > row0)     s[j][1] = -1e30f;
                if (col     > row0 + 8) s[j][2] = -1e30f;
                if (col + 1 > row0 + 8) s[j][3] = -1e30f;
            }
        }

        // ---- online softmax ----
        float mx0 = -1e30f, mx1 = -1e30f;
        #pragma unroll
        for (int j = 0; j < 8; j++) {
            mx0 = fmaxf(mx0, fmaxf(s[j][0], s[j][1]));
            mx1 = fmaxf(mx1, fmaxf(s[j][2], s[j][3]));
        }
        mx0 = fmaxf(mx0, __shfl_xor_sync(0xffffffffu, mx0, 1));
        mx0 = fmaxf(mx0, __shfl_xor_sync(0xffffffffu, mx0, 2));
        mx1 = fmaxf(mx1, __shfl_xor_sync(0xffffffffu, mx1, 1));
        mx1 = fmaxf(mx1, __shfl_xor_sync(0xffffffffu, mx1, 2));
        float mn0 = fmaxf(m_r[0], mx0);
        float mn1 = fmaxf(m_r[1], mx1);
        float corr0 = fast_exp(m_r[0] - mn0);
        float corr1 = fast_exp(m_r[1] - mn1);
        float rs0 = 0.f, rs1 = 0.f;
        #pragma unroll
        for (int j = 0; j < 8; j++) {
            s[j][0] = fast_exp(s[j][0] - mn0); rs0 += s[j][0];
            s[j][1] = fast_exp(s[j][1] - mn0); rs0 += s[j][1];
            s[j][2] = fast_exp(s[j][2] - mn1); rs1 += s[j][2];
            s[j][3] = fast_exp(s[j][3] - mn1); rs1 += s[j][3];
        }
        rs0 += __shfl_xor_sync(0xffffffffu, rs0, 1);
        rs0 += __shfl_xor_sync(0xffffffffu, rs0, 2);
        rs1 += __shfl_xor_sync(0xffffffffu, rs1, 1);
        rs1 += __shfl_xor_sync(0xffffffffu, rs1, 2);
        l_r[0] = l_r[0] * corr0 + rs0;
        l_r[1] = l_r[1] * corr1 + rs1;
        m_r[0] = mn0; m_r[1] = mn1;
        #pragma unroll
        for (int j = 0; j < 8; j++) {
            o[j][0] *= corr0; o[j][1] *= corr0;
            o[j][2] *= corr1; o[j][3] *= corr1;
        }

        // ---- O += P V (compensated) ----
        #pragma unroll
        for (int kk = 0; kk < 4; kk++) {
            uint32_t ph[4], pl[4];
            pack_hi_lo(s[2 * kk][0],     s[2 * kk][1],     ph[0], pl[0]);
            pack_hi_lo(s[2 * kk][2],     s[2 * kk][3],     ph[1], pl[1]);
            pack_hi_lo(s[2 * kk + 1][0], s[2 * kk + 1][1], ph[2], pl[2]);
            pack_hi_lo(s[2 * kk + 1][2], s[2 * kk + 1][3], ph[3], pl[3]);
            #pragma unroll
            for (int g2 = 0; g2 < 4; g2++) {
                uint32_t rvh[4], rvl[4];
                ldsm4t(rvh, s2u(&sVh[(kk * 16 + lrow) * 72 + g2 * 16 + lcol]));
                ldsm4t(rvl, s2u(&sVl[(kk * 16 + lrow) * 72 + g2 * 16 + lcol]));
                uint32_t bh0[2] = {rvh[0], rvh[1]}, bh1[2] = {rvh[2], rvh[3]};
                uint32_t bl0[2] = {rvl[0], rvl[1]}, bl1[2] = {rvl[2], rvl[3]};
                mma_bf16(o[g2 * 2],     ph, bh0);
                mma_bf16(o[g2 * 2],     pl, bh0);
                mma_bf16(o[g2 * 2],     ph, bl0);
                mma_bf16(o[g2 * 2 + 1], ph, bh1);
                mma_bf16(o[g2 * 2 + 1], pl, bh1);
                mma_bf16(o[g2 * 2 + 1], ph, bl1);
            }
        }
    }

    // epilogue: normalize, split hi/lo, write y [b,s,h,d]
    int b = bh >> 4, hh = bh & 15;
    float inv0 = 1.0f / l_r[0];
    float inv1 = 1.0f / l_r[1];
    #pragma unroll
    for (int h2 = 0; h2 < 2; h2++) {
        int srow = q0 + w * 16 + gid + h2 * 8;
        float inv = h2 ? inv1 : inv0;
        size_t base = (((size_t)(b * SEQ + srow)) * HEADS + hh) * HD;
        #pragma unroll
        for (int j = 0; j < 8; j++) {
            float a = o[j][h2 * 2 + 0] * inv;
            float c = o[j][h2 * 2 + 1] * inv;
            uint32_t hi, lo;
            pack_hi_lo(a, c, hi, lo);
            int d = j * 8 + 2 * tig;
            *reinterpret_cast<uint32_t*>(&y_hi[base + d]) = hi;
            *reinterpret_cast<uint32_t*>(&y_lo[base + d]) = lo;
        }
    }
}

// ============================ launch ============================
extern "C" void kernel_launch(void* const* d_in, const int* in_sizes, int n_in,
                              void* d_out, int out_size)
{
    const float* x        = (const float*)d_in[0];
    const float* ln_scale = (const float*)d_in[2];
    const float* ln_bias  = (const float*)d_in[3];
    const float* w_qkv    = (const float*)d_in[4];
    const float* b_qkv    = (const float*)d_in[5];
    const float* w_out    = (const float*)d_in[6];
    const float* b_out    = (const float*)d_in[7];
    float* out = (float*)d_out;

    __nv_bfloat16 *xn_hi, *xn_lo, *wq_hi, *wq_lo, *wo_hi, *wo_lo, *y_hi, *y_lo;
    __nv_bfloat16 *qh, *ql, *kh, *kl, *vh, *vl;
    cudaGetSymbolAddress((void**)&xn_hi, g_xn_hi);
    cudaGetSymbolAddress((void**)&xn_lo, g_xn_lo);
    cudaGetSymbolAddress((void**)&wq_hi, g_wq_hi);
    cudaGetSymbolAddress((void**)&wq_lo, g_wq_lo);
    cudaGetSymbolAddress((void**)&wo_hi, g_wo_hi);
    cudaGetSymbolAddress((void**)&wo_lo, g_wo_lo);
    cudaGetSymbolAddress((void**)&y_hi,  g_y_hi);
    cudaGetSymbolAddress((void**)&y_lo,  g_y_lo);
    cudaGetSymbolAddress((void**)&qh, g_qh);
    cudaGetSymbolAddress((void**)&ql, g_ql);
    cudaGetSymbolAddress((void**)&kh, g_kh);
    cudaGetSymbolAddress((void**)&kl, g_kl);
    cudaGetSymbolAddress((void**)&vh, g_vh);
    cudaGetSymbolAddress((void**)&vl, g_vl);

    // 1. LayerNorm -> bf16 hi/lo
    ln_kernel<<<ROWS, 256>>>(x, ln_scale, ln_bias, xn_hi, xn_lo);

    // 1b. weight decomposition
    decomp_kernel<<<512, 256>>>(w_qkv, wq_hi, wq_lo, DIM * QKV_N);
    decomp_kernel<<<256, 256>>>(w_out, wo_hi, wo_lo, DIM * DIM);

    // 2. QKV projection -> q/k/v bf16 hi/lo (q pre-scaled)
    {
        dim3 grid(QKV_N / 128, ROWS / 128);  // (24, 64)
        mma_gemm<0><<<grid, 256>>>(xn_hi, xn_lo, wq_hi, wq_lo, b_qkv, nullptr,
                                   ROWS, QKV_N, DIM, qh, ql, kh, kl, vh, vl);
    }

    // 3. tensor-core causal flash attention
    {
        int smem = (2 * 128 * 72 + 4 * 64 * 72) * sizeof(__nv_bfloat16);  // 73728
        cudaFuncSetAttribute(attn_mma_kernel,
                             cudaFuncAttributeMaxDynamicSharedMemorySize, smem);
        dim3 grid(BATCH * HEADS, SEQ / 128);  // (64, 16)
        attn_mma_kernel<<<grid, 256, smem>>>(qh, ql, kh, kl, vh, vl, y_hi, y_lo);
    }

    // 4. output projection -> d_out
    {
        dim3 grid(DIM / 128, ROWS / 128);    // (8, 64)
        mma_gemm<1><<<grid, 256>>>(y_hi, y_lo, wo_hi, wo_lo, b_out, out,
                                   ROWS, DIM, DIM, nullptr, nullptr, nullptr, nullptr, nullptr, nullptr);
    }
}

// round 4
// speedup vs baseline: 2.6463x; 1.0364x over previous
#include <cuda_runtime.h>
#include <cuda_bf16.h>
#include <cstdint>

// Problem constants
#define BATCH 4
#define SEQ   2048
#define DIM   1024
#define HEADS 16
#define HD    64
#define ROWS  (BATCH * SEQ)          // 8192
#define QKV_N (HEADS * 3 * HD)       // 3072
#define BHSD  (BATCH * HEADS * SEQ * HD)

// -------- scratch (static device globals; no allocation allowed) --------
__device__ __nv_bfloat16 g_xn_hi[ROWS * DIM];
__device__ __nv_bfloat16 g_xn_lo[ROWS * DIM];
__device__ __nv_bfloat16 g_wq_hi[DIM * QKV_N];
__device__ __nv_bfloat16 g_wq_lo[DIM * QKV_N];
__device__ __nv_bfloat16 g_wo_hi[DIM * DIM];
__device__ __nv_bfloat16 g_wo_lo[DIM * DIM];
__device__ __nv_bfloat16 g_qh[BHSD];   // [b,h,s,d] bf16 hi/lo
__device__ __nv_bfloat16 g_ql[BHSD];
__device__ __nv_bfloat16 g_kh[BHSD];
__device__ __nv_bfloat16 g_kl[BHSD];
__device__ __nv_bfloat16 g_vh[BHSD];
__device__ __nv_bfloat16 g_vl[BHSD];
__device__ __nv_bfloat16 g_y_hi[ROWS * DIM];   // attn out [b,s,h,d]
__device__ __nv_bfloat16 g_y_lo[ROWS * DIM];

// ============================ helpers ============================
__device__ __forceinline__ uint32_t s2u(const void* p) {
    return (uint32_t)__cvta_generic_to_shared(p);
}
__device__ __forceinline__ void ldsm4(uint32_t* r, uint32_t addr) {
    asm volatile("ldmatrix.sync.aligned.m8n8.x4.shared.b16 {%0,%1,%2,%3}, [%4];\n"
                 : "=r"(r[0]), "=r"(r[1]), "=r"(r[2]), "=r"(r[3]) : "r"(addr));
}
__device__ __forceinline__ void ldsm4t(uint32_t* r, uint32_t addr) {
    asm volatile("ldmatrix.sync.aligned.m8n8.x4.trans.shared.b16 {%0,%1,%2,%3}, [%4];\n"
                 : "=r"(r[0]), "=r"(r[1]), "=r"(r[2]), "=r"(r[3]) : "r"(addr));
}
__device__ __forceinline__ void mma_bf16(float* c, const uint32_t* a, const uint32_t* b) {
    asm volatile(
        "mma.sync.aligned.m16n8k16.row.col.f32.bf16.bf16.f32 "
        "{%0,%1,%2,%3}, {%4,%5,%6,%7}, {%8,%9}, {%0,%1,%2,%3};\n"
        : "+f"(c[0]), "+f"(c[1]), "+f"(c[2]), "+f"(c[3])
        : "r"(a[0]), "r"(a[1]), "r"(a[2]), "r"(a[3]), "r"(b[0]), "r"(b[1]));
}
__device__ __forceinline__ void cp16(const void* smem_dst, const void* gmem_src) {
    asm volatile("cp.async.cg.shared.global [%0], [%1], 16;\n"
                 :: "r"(s2u(smem_dst)), "l"(gmem_src));
}
__device__ __forceinline__ void cp_commit() {
    asm volatile("cp.async.commit_group;\n");
}
template <int N>
__device__ __forceinline__ void cp_wait() {
    asm volatile("cp.async.wait_group %0;\n" :: "n"(N));
}
__device__ __forceinline__ void split_bf16(float x, __nv_bfloat16& h, __nv_bfloat16& l) {
    h = __float2bfloat16_rn(x);
    l = __float2bfloat16_rn(x - __bfloat162float(h));
}
__device__ __forceinline__ void pack_hi_lo(float a, float b, uint32_t& hi, uint32_t& lo) {
    __nv_bfloat162 h2 = __floats2bfloat162_rn(a, b);     // low = a
    float ra = a - __low2float(h2);
    float rb = b - __high2float(h2);
    __nv_bfloat162 l2 = __floats2bfloat162_rn(ra, rb);
    hi = *reinterpret_cast<uint32_t*>(&h2);
    lo = *reinterpret_cast<uint32_t*>(&l2);
}
// fast exp on FMA pipe (no MUFU). valid for x <= 0.
__device__ __forceinline__ float fast_exp(float x) {
    float t = x * 1.4426950408889634f;
    t = fmaxf(t, -126.0f);
    float fi = rintf(t);
    float g = (t - fi) * 0.6931471805599453f;
    float p = 8.3333333e-3f;
    p = fmaf(p, g, 4.1666667e-2f);
    p = fmaf(p, g, 0.16666667f);
    p = fmaf(p, g, 0.5f);
    p = fmaf(p, g, 1.0f);
    p = fmaf(p, g, 1.0f);
    int ei = (int)fi;
    float sc = __int_as_float((ei + 127) << 23);
    return sc * p;
}

// ============================ LayerNorm -> hi/lo bf16 ============================
__global__ void __launch_bounds__(256) ln_kernel(
    const float* __restrict__ x,
    const float* __restrict__ gamma,
    const float* __restrict__ beta,
    __nv_bfloat16* __restrict__ out_hi,
    __nv_bfloat16* __restrict__ out_lo)
{
    int row = blockIdx.x;
    int t = threadIdx.x;
    const float4* xr = reinterpret_cast<const float4*>(x + (size_t)row * DIM);
    float4 v = xr[t];
    float s1 = v.x + v.y + v.z + v.w;
    float s2 = v.x*v.x + v.y*v.y + v.z*v.z + v.w*v.w;
    #pragma unroll
    for (int o = 16; o > 0; o >>= 1) {
        s1 += __shfl_xor_sync(0xffffffffu, s1, o);
        s2 += __shfl_xor_sync(0xffffffffu, s2, o);
    }
    __shared__ float r1[8], r2[8];
    __shared__ float sh_mu, sh_rstd;
    if ((t & 31) == 0) { r1[t >> 5] = s1; r2[t >> 5] = s2; }
    __syncthreads();
    if (t == 0) {
        float a = 0.f, b = 0.f;
        #pragma unroll
        for (int i = 0; i < 8; i++) { a += r1[i]; b += r2[i]; }
        float mu  = a * (1.0f / DIM);
        float var = b * (1.0f / DIM) - mu * mu;
        sh_mu = mu;
        sh_rstd = rsqrtf(var + 1e-6f);
    }
    __syncthreads();
    float mu = sh_mu, rstd = sh_rstd;
    float4 g = reinterpret_cast<const float4*>(gamma)[t];
    float4 b4 = reinterpret_cast<const float4*>(beta)[t];
    float o4[4];
    o4[0] = (v.x - mu) * rstd * g.x + b4.x;
    o4[1] = (v.y - mu) * rstd * g.y + b4.y;
    o4[2] = (v.z - mu) * rstd * g.z + b4.z;
    o4[3] = (v.w - mu) * rstd * g.w + b4.w;
    size_t base = (size_t)row * DIM + t * 4;
    #pragma unroll
    for (int i = 0; i < 4; i++) {
        __nv_bfloat16 h, l;
        split_bf16(o4[i], h, l);
        out_hi[base + i] = h;
        out_lo[base + i] = l;
    }
}

// ============================ weight decomposition ============================
__global__ void __launch_bounds__(256) decomp_kernel(
    const float* __restrict__ w,
    __nv_bfloat16* __restrict__ hi,
    __nv_bfloat16* __restrict__ lo,
    int n)
{
    int i = blockIdx.x * blockDim.x + threadIdx.x;
    int stride = gridDim.x * blockDim.x;
    for (; i < n; i += stride) {
        __nv_bfloat16 h, l;
        split_bf16(w[i], h, l);
        hi[i] = h;
        lo[i] = l;
    }
}

// ============================ bf16x3 MMA GEMM 128x128x16, 4-stage cp.async ============================
// MODE 0: QKV — scatter bf16 hi/lo into q/k/v ([b,h,s,d]) with q-scale.
// MODE 1: plain fp32 C = A@B + bias.
#define ASTRIDE (128 * 24)
#define BSTRIDE (16 * 136)
template <int MODE>
__global__ void __launch_bounds__(256, 2) mma_gemm(
    const __nv_bfloat16* __restrict__ Ahg, const __nv_bfloat16* __restrict__ Alg,
    const __nv_bfloat16* __restrict__ Bhg, const __nv_bfloat16* __restrict__ Blg,
    const float* __restrict__ bias,
    float* __restrict__ Cout,
    int M, int N, int K,
    __nv_bfloat16* __restrict__ qh, __nv_bfloat16* __restrict__ ql,
    __nv_bfloat16* __restrict__ kh, __nv_bfloat16* __restrict__ kl,
    __nv_bfloat16* __restrict__ vh, __nv_bfloat16* __restrict__ vl)
{
    __shared__ __align__(16) __nv_bfloat16 sAh[4 * ASTRIDE];
    __shared__ __align__(16) __nv_bfloat16 sAl[4 * ASTRIDE];
    __shared__ __align__(16) __nv_bfloat16 sBh[4 * BSTRIDE];
    __shared__ __align__(16) __nv_bfloat16 sBl[4 * BSTRIDE];

    int tid = threadIdx.x;
    int lane = tid & 31;
    int wid = tid >> 5;
    int wm = wid & 1;
    int wn = wid >> 1;
    int m0 = blockIdx.y * 128;
    int n0 = blockIdx.x * 128;

    int arow = tid >> 1;
    int acol = (tid & 1) * 8;
    int brow = tid >> 4;
    int bcol = (tid & 15) * 8;

    const __nv_bfloat16* pAh = Ahg + (size_t)(m0 + arow) * K + acol;
    const __nv_bfloat16* pAl = Alg + (size_t)(m0 + arow) * K + acol;
    const __nv_bfloat16* pBh = Bhg + (size_t)brow * N + n0 + bcol;
    const __nv_bfloat16* pBl = Blg + (size_t)brow * N + n0 + bcol;

    float acc[4][4][4];
    #pragma unroll
    for (int i = 0; i < 4; i++)
        #pragma unroll
        for (int j = 0; j < 4; j++)
            #pragma unroll
            for (int e = 0; e < 4; e++) acc[i][j][e] = 0.f;

    int niter = K / 16;

    // issue a k-slice load into stage st
    auto issue = [&](int kt, int st) {
        int ko = kt * 16;
        cp16(&sAh[st * ASTRIDE + arow * 24 + acol], pAh + ko);
        cp16(&sAl[st * ASTRIDE + arow * 24 + acol], pAl + ko);
        cp16(&sBh[st * BSTRIDE + brow * 136 + bcol], pBh + (size_t)ko * N);
        cp16(&sBl[st * BSTRIDE + brow * 136 + bcol], pBl + (size_t)ko * N);
        cp_commit();
    };

    // prologue: 3 stages in flight
    issue(0, 0);
    issue(1, 1);
    issue(2, 2);

    // loop-invariant ldsm base addresses (stage 0)
    int lrow = lane & 15;
    int lcol = (lane >> 4) * 8;
    uint32_t baseAh[4], baseAl[4];
    #pragma unroll
    for (int i = 0; i < 4; i++) {
        baseAh[i] = s2u(&sAh[(wm * 64 + i * 16 + lrow) * 24 + lcol]);
        baseAl[i] = s2u(&sAl[(wm * 64 + i * 16 + lrow) * 24 + lcol]);
    }
    uint32_t baseBh[2], baseBl[2];
    #pragma unroll
    for (int jj = 0; jj < 2; jj++) {
        baseBh[jj] = s2u(&sBh[lrow * 136 + wn * 32 + jj * 16 + lcol]);
        baseBl[jj] = s2u(&sBl[lrow * 136 + wn * 32 + jj * 16 + lcol]);
    }

    for (int kt = 0; kt < niter; kt++) {
        // wait until stage kt's group is complete (exact tail handling)
        if (kt + 2 < niter)      cp_wait<2>();
        else if (kt + 1 < niter) cp_wait<1>();
        else                     cp_wait<0>();
        __syncthreads();   // all warps past previous iter's compute; stage data visible

        if (kt + 3 < niter) issue(kt + 3, (kt + 3) & 3);

        int st = kt & 3;
        uint32_t offA = (uint32_t)(st * ASTRIDE * 2);
        uint32_t offB = (uint32_t)(st * BSTRIDE * 2);

        uint32_t ah[4][4], al[4][4], bb[4][2];
        #pragma unroll
        for (int i = 0; i < 4; i++) {
            ldsm4(ah[i], baseAh[i] + offA);
            ldsm4(al[i], baseAl[i] + offA);
        }
        #pragma unroll
        for (int jj = 0; jj < 2; jj++) {
            uint32_t r[4];
            ldsm4t(r, baseBh[jj] + offB);
            bb[jj * 2][0] = r[0]; bb[jj * 2][1] = r[1];
            bb[jj * 2 + 1][0] = r[2]; bb[jj * 2 + 1][1] = r[3];
        }
        #pragma unroll
        for (int i = 0; i < 4; i++)
            #pragma unroll
            for (int j = 0; j < 4; j++) {
                mma_bf16(acc[i][j], ah[i], bb[j]);
                mma_bf16(acc[i][j], al[i], bb[j]);
            }
        #pragma unroll
        for (int jj = 0; jj < 2; jj++) {
            uint32_t r[4];
            ldsm4t(r, baseBl[jj] + offB);
            bb[jj * 2][0] = r[0]; bb[jj * 2][1] = r[1];
            bb[jj * 2 + 1][0] = r[2]; bb[jj * 2 + 1][1] = r[3];
        }
        #pragma unroll
        for (int i = 0; i < 4; i++)
            #pragma unroll
            for (int j = 0; j < 4; j++)
                mma_bf16(acc[i][j], ah[i], bb[j]);
    }

    int gid = lane >> 2, tig = lane & 3;
    #pragma unroll
    for (int i = 0; i < 4; i++) {
        #pragma unroll
        for (int j = 0; j < 4; j++) {
            int n = n0 + wn * 32 + j * 8 + 2 * tig;
            if (MODE == 0) {
                int hq = n / 192;
                int f = n - hq * 192;
                #pragma unroll
                for (int rh = 0; rh < 2; rh++) {
                    int m = m0 + wm * 64 + i * 16 + gid + rh * 8;
                    float v0 = acc[i][j][rh * 2 + 0] + bias[n];
                    float v1 = acc[i][j][rh * 2 + 1] + bias[n + 1];
                    int bb2 = m >> 11;
                    int ss = m & 2047;
                    size_t base = (((size_t)(bb2 * HEADS + hq)) * SEQ + ss) * HD;
                    __nv_bfloat16 *dh, *dl;
                    int off;
                    if (f < 64)       { v0 *= 0.125f; v1 *= 0.125f; dh = qh; dl = ql; off = f; }
                    else if (f < 128) { dh = kh; dl = kl; off = f - 64; }
                    else              { dh = vh; dl = vl; off = f - 128; }
                    uint32_t hi, lo;
                    pack_hi_lo(v0, v1, hi, lo);
                    *reinterpret_cast<uint32_t*>(&dh[base + off]) = hi;
                    *reinterpret_cast<uint32_t*>(&dl[base + off]) = lo;
                }
            } else {
                #pragma unroll
                for (int rh = 0; rh < 2; rh++) {
                    int m = m0 + wm * 64 + i * 16 + gid + rh * 8;
                    float v0 = acc[i][j][rh * 2 + 0] + bias[n];
                    float v1 = acc[i][j][rh * 2 + 1] + bias[n + 1];
                    float2 st2 = make_float2(v0, v1);
                    *reinterpret_cast<float2*>(&Cout[(size_t)m * N + n]) = st2;
                }
            }
        }
    }
}

// ============================ Tensor-core flash attention, 2-stage KV pipeline ============================
#define KVSTRIDE (64 * 72)
__global__ void __launch_bounds__(256) attn_mma_kernel(
    const __nv_bfloat16* __restrict__ qh_g, const __nv_bfloat16* __restrict__ ql_g,
    const __nv_bfloat16* __restrict__ kh_g, const __nv_bfloat16* __restrict__ kl_g,
    const __nv_bfloat16* __restrict__ vh_g, const __nv_bfloat16* __restrict__ vl_g,
    __nv_bfloat16* __restrict__ y_hi, __nv_bfloat16* __restrict__ y_lo)
{
    extern __shared__ __nv_bfloat16 smb[];
    __nv_bfloat16* sQh = smb;                      // [128][72]
    __nv_bfloat16* sQl = sQh + 128 * 72;
    __nv_bfloat16* sKh = sQl + 128 * 72;           // [2][64][72]
    __nv_bfloat16* sKl = sKh + 2 * KVSTRIDE;
    __nv_bfloat16* sVh = sKl + 2 * KVSTRIDE;
    __nv_bfloat16* sVl = sVh + 2 * KVSTRIDE;

    int bh = blockIdx.x;
    int qt = (gridDim.y - 1) - blockIdx.y;   // heavy tiles first
    int tid = threadIdx.x;
    int lane = tid & 31;
    int w = tid >> 5;
    int gid = lane >> 2, tig = lane & 3;
    int lrow = lane & 15, lcol = (lane >> 4) * 8;

    int q0 = qt * 128;
    const size_t bhoff = (size_t)bh * SEQ * HD;

    // KV tile issue into stage st (cp.async)
    int kvr = tid >> 3;                 // thread covers 2 rows via +32
    int kvd = (tid & 7) * 8;
    auto issue_kv = [&](int kt, int st) {
        int c0 = kt * 64;
        size_t base = st * KVSTRIDE;
        #pragma unroll
        for (int i = 0; i < 2; i++) {
            int r = kvr + i * 32;
            size_t g = bhoff + (size_t)(c0 + r) * HD + kvd;
            size_t sm = base + r * 72 + kvd;
            cp16(&sKh[sm], &kh_g[g]);
            cp16(&sKl[sm], &kl_g[g]);
            cp16(&sVh[sm], &vh_g[g]);
            cp16(&sVl[sm], &vl_g[g]);
        }
        cp_commit();
    };

    int ktmax = 2 * qt + 1;
    issue_kv(0, 0);

    // load Q tile (128 x 64) hi/lo (plain loads, once)
    #pragma unroll
    for (int i = 0; i < 4; i++) {
        int chunk = tid + i * 256;
        int r = chunk >> 3, d8 = (chunk & 7) * 8;
        size_t g = bhoff + (size_t)(q0 + r) * HD + d8;
        *reinterpret_cast<uint4*>(&sQh[r * 72 + d8]) = *reinterpret_cast<const uint4*>(&qh_g[g]);
        *reinterpret_cast<uint4*>(&sQl[r * 72 + d8]) = *reinterpret_cast<const uint4*>(&ql_g[g]);
    }
    __syncthreads();

    // hoist Q fragments
    uint32_t qfh[4][4], qfl[4][4];
    #pragma unroll
    for (int kk = 0; kk < 4; kk++) {
        ldsm4(qfh[kk], s2u(&sQh[(w * 16 + lrow) * 72 + kk * 16 + lcol]));
        ldsm4(qfl[kk], s2u(&sQl[(w * 16 + lrow) * 72 + kk * 16 + lcol]));
    }

    float m_r[2] = {-1e30f, -1e30f};
    float l_r[2] = {0.f, 0.f};
    float o[8][4];
    #pragma unroll
    for (int j = 0; j < 8; j++)
        #pragma unroll
        for (int c = 0; c < 4; c++) o[j][c] = 0.f;

    for (int kt = 0; kt <= ktmax; kt++) {
        int c0 = kt * 64;
        int st = kt & 1;
        uint32_t offKV = (uint32_t)(st * KVSTRIDE * 2);

        if (kt < ktmax) {
            issue_kv(kt + 1, (kt + 1) & 1);
            cp_wait<1>();
        } else {
            cp_wait<0>();
        }
        __syncthreads();

        // ---- S = Q K^T (compensated) ----
        float s[8][4];
        #pragma unroll
        for (int j = 0; j < 8; j++)
            #pragma unroll
            for (int c = 0; c < 4; c++) s[j][c] = 0.f;

        #pragma unroll
        for (int kk = 0; kk < 4; kk++) {
            #pragma unroll
            for (int g2 = 0; g2 < 4; g2++) {
                uint32_t rh[4], rl[4];
                ldsm4(rh, s2u(&sKh[(g2 * 16 + lrow) * 72 + kk * 16 + lcol]) + offKV);
                ldsm4(rl, s2u(&sKl[(g2 * 16 + lrow) * 72 + kk * 16 + lcol]) + offKV);
                uint32_t b0h[2] = {rh[0], rh[2]}, b1h[2] = {rh[1], rh[3]};
                uint32_t b0l[2] = {rl[0], rl[2]}, b1l[2] = {rl[1], rl[3]};
                mma_bf16(s[g2 * 2],     qfh[kk], b0h);
                mma_bf16(s[g2 * 2],     qfl[kk], b0h);
                mma_bf16(s[g2 * 2],     qfh[kk], b0l);
                mma_bf16(s[g2 * 2 + 1], qfh[kk], b1h);
                mma_bf16(s[g2 * 2 + 1], qfl[kk], b1h);
                mma_bf16(s[g2 * 2 + 1], qfh[kk], b1l);
            }
        }

        // causal mask
        if (kt >= 2 * qt) {
            int row0 = q0 + w * 16 + gid;
            #pragma unroll
            for (int j = 0; j < 8; j++) {
                int col = c0 + j * 8 + 2 * tig;
                if (col     > row0)     s[j][0] = -1e30f;
                if (col + 1 > row0)     s[j][1] = -1e30f;
                if (col     > row0 + 8) s[j][2] = -1e30f;
                if (col + 1 > row0 + 8) s[j][3] = -1e30f;
            }
        }

        // ---- online softmax ----
        float mx0 = -1e30f, mx1 = -1e30f;
        #pragma unroll
        for (int j = 0; j < 8; j++) {
            mx0 = fmaxf(mx0, fmaxf(s[j][0], s[j][1]));
            mx1 = fmaxf(mx1, fmaxf(s[j][2], s[j][3]));
        }
        mx0 = fmaxf(mx0, __shfl_xor_sync(0xffffffffu, mx0, 1));
        mx0 = fmaxf(mx0, __shfl_xor_sync(0xffffffffu, mx0, 2));
        mx1 = fmaxf(mx1, __shfl_xor_sync(0xffffffffu, mx1, 1));
        mx1 = fmaxf(mx1, __shfl_xor_sync(0xffffffffu, mx1, 2));
        float mn0 = fmaxf(m_r[0], mx0);
        float mn1 = fmaxf(m_r[1], mx1);
        float corr0 = fast_exp(m_r[0] - mn0);
        float corr1 = fast_exp(m_r[1] - mn1);
        float rs0 = 0.f, rs1 = 0.f;
        #pragma unroll
        for (int j = 0; j < 8; j++) {
            s[j][0] = fast_exp(s[j][0] - mn0); rs0 += s[j][0];
            s[j][1] = fast_exp(s[j][1] - mn0); rs0 += s[j][1];
            s[j][2] = fast_exp(s[j][2] - mn1); rs1 += s[j][2];
            s[j][3] = fast_exp(s[j][3] - mn1); rs1 += s[j][3];
        }
        rs0 += __shfl_xor_sync(0xffffffffu, rs0, 1);
        rs0 += __shfl_xor_sync(0xffffffffu, rs0, 2);
        rs1 += __shfl_xor_sync(0xffffffffu, rs1, 1);
        rs1 += __shfl_xor_sync(0xffffffffu, rs1, 2);
        l_r[0] = l_r[0] * corr0 + rs0;
        l_r[1] = l_r[1] * corr1 + rs1;
        m_r[0] = mn0; m_r[1] = mn1;
        #pragma unroll
        for (int j = 0; j < 8; j++) {
            o[j][0] *= corr0; o[j][1] *= corr0;
            o[j][2] *= corr1; o[j][3] *= corr1;
        }

        // ---- O += P V (compensated) ----
        #pragma unroll
        for (int kk = 0; kk < 4; kk++) {
            uint32_t ph[4], pl[4];
            pack_hi_lo(s[2 * kk][0],     s[2 * kk][1],     ph[0], pl[0]);
            pack_hi_lo(s[2 * kk][2],     s[2 * kk][3],     ph[1], pl[1]);
            pack_hi_lo(s[2 * kk + 1][0], s[2 * kk + 1][1], ph[2], pl[2]);
            pack_hi_lo(s[2 * kk + 1][2], s[2 * kk + 1][3], ph[3], pl[3]);
            #pragma unroll
            for (int g2 = 0; g2 < 4; g2++) {
                uint32_t rvh[4], rvl[4];
                ldsm4t(rvh, s2u(&sVh[(kk * 16 + lrow) * 72 + g2 * 16 + lcol]) + offKV);
                ldsm4t(rvl, s2u(&sVl[(kk * 16 + lrow) * 72 + g2 * 16 + lcol]) + offKV);
                uint32_t bh0[2] = {rvh[0], rvh[1]}, bh1[2] = {rvh[2], rvh[3]};
                uint32_t bl0[2] = {rvl[0], rvl[1]}, bl1[2] = {rvl[2], rvl[3]};
                mma_bf16(o[g2 * 2],     ph, bh0);
                mma_bf16(o[g2 * 2],     pl, bh0);
                mma_bf16(o[g2 * 2],     ph, bl0);
                mma_bf16(o[g2 * 2 + 1], ph, bh1);
                mma_bf16(o[g2 * 2 + 1], pl, bh1);
                mma_bf16(o[g2 * 2 + 1], ph, bl1);
            }
        }
        __syncthreads();   // all warps done reading stage st before it's overwritten
    }

    // epilogue
    int b = bh >> 4, hh = bh & 15;
    float inv0 = 1.0f / l_r[0];
    float inv1 = 1.0f / l_r[1];
    #pragma unroll
    for (int h2 = 0; h2 < 2; h2++) {
        int srow = q0 + w * 16 + gid + h2 * 8;
        float inv = h2 ? inv1 : inv0;
        size_t base = (((size_t)(b * SEQ + srow)) * HEADS + hh) * HD;
        #pragma unroll
        for (int j = 0; j < 8; j++) {
            float a = o[j][h2 * 2 + 0] * inv;
            float c = o[j][h2 * 2 + 1] * inv;
            uint32_t hi, lo;
            pack_hi_lo(a, c, hi, lo);
            int d = j * 8 + 2 * tig;
            *reinterpret_cast<uint32_t*>(&y_hi[base + d]) = hi;
            *reinterpret_cast<uint32_t*>(&y_lo[base + d]) = lo;
        }
    }
}

// ============================ launch ============================
extern "C" void kernel_launch(void* const* d_in, const int* in_sizes, int n_in,
                              void* d_out, int out_size)
{
    const float* x        = (const float*)d_in[0];
    const float* ln_scale = (const float*)d_in[2];
    const float* ln_bias  = (const float*)d_in[3];
    const float* w_qkv    = (const float*)d_in[4];
    const float* b_qkv    = (const float*)d_in[5];
    const float* w_out    = (const float*)d_in[6];
    const float* b_out    = (const float*)d_in[7];
    float* out = (float*)d_out;

    __nv_bfloat16 *xn_hi, *xn_lo, *wq_hi, *wq_lo, *wo_hi, *wo_lo, *y_hi, *y_lo;
    __nv_bfloat16 *qh, *ql, *kh, *kl, *vh, *vl;
    cudaGetSymbolAddress((void**)&xn_hi, g_xn_hi);
    cudaGetSymbolAddress((void**)&xn_lo, g_xn_lo);
    cudaGetSymbolAddress((void**)&wq_hi, g_wq_hi);
    cudaGetSymbolAddress((void**)&wq_lo, g_wq_lo);
    cudaGetSymbolAddress((void**)&wo_hi, g_wo_hi);
    cudaGetSymbolAddress((void**)&wo_lo, g_wo_lo);
    cudaGetSymbolAddress((void**)&y_hi,  g_y_hi);
    cudaGetSymbolAddress((void**)&y_lo,  g_y_lo);
    cudaGetSymbolAddress((void**)&qh, g_qh);
    cudaGetSymbolAddress((void**)&ql, g_ql);
    cudaGetSymbolAddress((void**)&kh, g_kh);
    cudaGetSymbolAddress((void**)&kl, g_kl);
    cudaGetSymbolAddress((void**)&vh, g_vh);
    cudaGetSymbolAddress((void**)&vl, g_vl);

    // 1. LayerNorm -> bf16 hi/lo
    ln_kernel<<<ROWS, 256>>>(x, ln_scale, ln_bias, xn_hi, xn_lo);

    // 1b. weight decomposition
    decomp_kernel<<<512, 256>>>(w_qkv, wq_hi, wq_lo, DIM * QKV_N);
    decomp_kernel<<<256, 256>>>(w_out, wo_hi, wo_lo, DIM * DIM);

    // 2. QKV projection -> q/k/v bf16 hi/lo (q pre-scaled)
    {
        dim3 grid(QKV_N / 128, ROWS / 128);  // (24, 64)
        mma_gemm<0><<<grid, 256>>>(xn_hi, xn_lo, wq_hi, wq_lo, b_qkv, nullptr,
                                   ROWS, QKV_N, DIM, qh, ql, kh, kl, vh, vl);
    }

    // 3. tensor-core causal flash attention (2-stage KV pipeline)
    {
        int smem = (2 * 128 * 72 + 8 * KVSTRIDE) * sizeof(__nv_bfloat16);  // 110592
        cudaFuncSetAttribute(attn_mma_kernel,
                             cudaFuncAttributeMaxDynamicSharedMemorySize, smem);
        dim3 grid(BATCH * HEADS, SEQ / 128);  // (64, 16)
        attn_mma_kernel<<<grid, 256, smem>>>(qh, ql, kh, kl, vh, vl, y_hi, y_lo);
    }

    // 4. output projection -> d_out
    {
        dim3 grid(DIM / 128, ROWS / 128);    // (8, 64)
        mma_gemm<1><<<grid, 256>>>(y_hi, y_lo, wo_hi, wo_lo, b_out, out,
                                   ROWS, DIM, DIM, nullptr, nullptr, nullptr, nullptr, nullptr, nullptr);
    }
}

// round 6
// speedup vs baseline: 2.6567x; 1.0039x over previous
#include <cuda_runtime.h>
#include <cuda_bf16.h>
#include <cstdint>

// Problem constants
#define BATCH 4
#define SEQ   2048
#define DIM   1024
#define HEADS 16
#define HD    64
#define ROWS  (BATCH * SEQ)          // 8192
#define QKV_N (HEADS * 3 * HD)       // 3072
#define BHSD  (BATCH * HEADS * SEQ * HD)

// -------- scratch (static device globals; no allocation allowed) --------
__device__ __nv_bfloat16 g_xn_hi[ROWS * DIM];
__device__ __nv_bfloat16 g_xn_lo[ROWS * DIM];
__device__ __nv_bfloat16 g_wq_hi[DIM * QKV_N];
__device__ __nv_bfloat16 g_wq_lo[DIM * QKV_N];
__device__ __nv_bfloat16 g_wo_hi[DIM * DIM];
__device__ __nv_bfloat16 g_wo_lo[DIM * DIM];
__device__ __nv_bfloat16 g_qh[BHSD];   // [b,h,s,d] bf16 hi/lo
__device__ __nv_bfloat16 g_ql[BHSD];
__device__ __nv_bfloat16 g_kh[BHSD];
__device__ __nv_bfloat16 g_kl[BHSD];
__device__ __nv_bfloat16 g_vh[BHSD];
__device__ __nv_bfloat16 g_vl[BHSD];
__device__ __nv_bfloat16 g_y_hi[ROWS * DIM];   // attn out [b,s,h,d]
__device__ __nv_bfloat16 g_y_lo[ROWS * DIM];

// ============================ helpers ============================
__device__ __forceinline__ uint32_t s2u(const void* p) {
    return (uint32_t)__cvta_generic_to_shared(p);
}
__device__ __forceinline__ void ldsm4(uint32_t* r, uint32_t addr) {
    asm volatile("ldmatrix.sync.aligned.m8n8.x4.shared.b16 {%0,%1,%2,%3}, [%4];\n"
                 : "=r"(r[0]), "=r"(r[1]), "=r"(r[2]), "=r"(r[3]) : "r"(addr));
}
__device__ __forceinline__ void ldsm4t(uint32_t* r, uint32_t addr) {
    asm volatile("ldmatrix.sync.aligned.m8n8.x4.trans.shared.b16 {%0,%1,%2,%3}, [%4];\n"
                 : "=r"(r[0]), "=r"(r[1]), "=r"(r[2]), "=r"(r[3]) : "r"(addr));
}
__device__ __forceinline__ void mma_bf16(float* c, const uint32_t* a, const uint32_t* b) {
    asm volatile(
        "mma.sync.aligned.m16n8k16.row.col.f32.bf16.bf16.f32 "
        "{%0,%1,%2,%3}, {%4,%5,%6,%7}, {%8,%9}, {%0,%1,%2,%3};\n"
        : "+f"(c[0]), "+f"(c[1]), "+f"(c[2]), "+f"(c[3])
        : "r"(a[0]), "r"(a[1]), "r"(a[2]), "r"(a[3]), "r"(b[0]), "r"(b[1]));
}
__device__ __forceinline__ void cp16(uint32_t smem_dst, const void* gmem_src) {
    asm volatile("cp.async.cg.shared.global [%0], [%1], 16;\n"
                 :: "r"(smem_dst), "l"(gmem_src));
}
__device__ __forceinline__ void cp_commit() {
    asm volatile("cp.async.commit_group;\n");
}
template <int N>
__device__ __forceinline__ void cp_wait() {
    asm volatile("cp.async.wait_group %0;\n" :: "n"(N));
}
__device__ __forceinline__ void split_bf16(float x, __nv_bfloat16& h, __nv_bfloat16& l) {
    h = __float2bfloat16_rn(x);
    l = __float2bfloat16_rn(x - __bfloat162float(h));
}
__device__ __forceinline__ void pack_hi_lo(float a, float b, uint32_t& hi, uint32_t& lo) {
    __nv_bfloat162 h2 = __floats2bfloat162_rn(a, b);     // low = a
    float ra = a - __low2float(h2);
    float rb = b - __high2float(h2);
    __nv_bfloat162 l2 = __floats2bfloat162_rn(ra, rb);
    hi = *reinterpret_cast<uint32_t*>(&h2);
    lo = *reinterpret_cast<uint32_t*>(&l2);
}
// fast exp on FMA pipe (no MUFU). valid for x <= 0.
__device__ __forceinline__ float fast_exp(float x) {
    float t = x * 1.4426950408889634f;
    t = fmaxf(t, -126.0f);
    float fi = rintf(t);
    float g = (t - fi) * 0.6931471805599453f;
    float p = 8.3333333e-3f;
    p = fmaf(p, g, 4.1666667e-2f);
    p = fmaf(p, g, 0.16666667f);
    p = fmaf(p, g, 0.5f);
    p = fmaf(p, g, 1.0f);
    p = fmaf(p, g, 1.0f);
    int ei = (int)fi;
    float sc = __int_as_float((ei + 127) << 23);
    return sc * p;
}

// ============================ LayerNorm -> hi/lo bf16 ============================
__global__ void __launch_bounds__(256) ln_kernel(
    const float* __restrict__ x,
    const float* __restrict__ gamma,
    const float* __restrict__ beta,
    __nv_bfloat16* __restrict__ out_hi,
    __nv_bfloat16* __restrict__ out_lo)
{
    int row = blockIdx.x;
    int t = threadIdx.x;
    const float4* xr = reinterpret_cast<const float4*>(x + (size_t)row * DIM);
    float4 v = xr[t];
    float s1 = v.x + v.y + v.z + v.w;
    float s2 = v.x*v.x + v.y*v.y + v.z*v.z + v.w*v.w;
    #pragma unroll
    for (int o = 16; o > 0; o >>= 1) {
        s1 += __shfl_xor_sync(0xffffffffu, s1, o);
        s2 += __shfl_xor_sync(0xffffffffu, s2, o);
    }
    __shared__ float r1[8], r2[8];
    __shared__ float sh_mu, sh_rstd;
    if ((t & 31) == 0) { r1[t >> 5] = s1; r2[t >> 5] = s2; }
    __syncthreads();
    if (t == 0) {
        float a = 0.f, b = 0.f;
        #pragma unroll
        for (int i = 0; i < 8; i++) { a += r1[i]; b += r2[i]; }
        float mu  = a * (1.0f / DIM);
        float var = b * (1.0f / DIM) - mu * mu;
        sh_mu = mu;
        sh_rstd = rsqrtf(var + 1e-6f);
    }
    __syncthreads();
    float mu = sh_mu, rstd = sh_rstd;
    float4 g = reinterpret_cast<const float4*>(gamma)[t];
    float4 b4 = reinterpret_cast<const float4*>(beta)[t];
    float o4[4];
    o4[0] = (v.x - mu) * rstd * g.x + b4.x;
    o4[1] = (v.y - mu) * rstd * g.y + b4.y;
    o4[2] = (v.z - mu) * rstd * g.z + b4.z;
    o4[3] = (v.w - mu) * rstd * g.w + b4.w;
    size_t base = (size_t)row * DIM + t * 4;
    #pragma unroll
    for (int i = 0; i < 4; i++) {
        __nv_bfloat16 h, l;
        split_bf16(o4[i], h, l);
        out_hi[base + i] = h;
        out_lo[base + i] = l;
    }
}

// ============================ weight decomposition ============================
__global__ void __launch_bounds__(256) decomp_kernel(
    const float* __restrict__ w,
    __nv_bfloat16* __restrict__ hi,
    __nv_bfloat16* __restrict__ lo,
    int n)
{
    int i = blockIdx.x * blockDim.x + threadIdx.x;
    int stride = gridDim.x * blockDim.x;
    for (; i < n; i += stride) {
        __nv_bfloat16 h, l;
        split_bf16(w[i], h, l);
        hi[i] = h;
        lo[i] = l;
    }
}

// ============================ bf16x3 MMA GEMM 128x128, 32-K slices, 3-stage cp.async ============================
// MODE 0: QKV — scatter bf16 hi/lo into q/k/v ([b,h,s,d]) with q-scale.
// MODE 1: plain fp32 C = A@B + bias.
#define GA_STRIDE 40                        // halves per A row (32 data + 8 pad)
#define GB_STRIDE 136                       // halves per B row (128 data + 8 pad)
#define GA_BYTES  (128 * GA_STRIDE * 2)     // 10240
#define GB_BYTES  (32 * GB_STRIDE * 2)      // 8704
#define GSTAGE    (2 * GA_BYTES + 2 * GB_BYTES)  // 37888
#define G_OFF_AL  GA_BYTES
#define G_OFF_BH  (2 * GA_BYTES)
#define G_OFF_BL  (2 * GA_BYTES + GB_BYTES)
template <int MODE>
__global__ void __launch_bounds__(256, 2) mma_gemm(
    const __nv_bfloat16* __restrict__ Ahg, const __nv_bfloat16* __restrict__ Alg,
    const __nv_bfloat16* __restrict__ Bhg, const __nv_bfloat16* __restrict__ Blg,
    const float* __restrict__ bias,
    float* __restrict__ Cout,
    int M, int N, int K,
    __nv_bfloat16* __restrict__ qh, __nv_bfloat16* __restrict__ ql,
    __nv_bfloat16* __restrict__ kh, __nv_bfloat16* __restrict__ kl,
    __nv_bfloat16* __restrict__ vh, __nv_bfloat16* __restrict__ vl)
{
    extern __shared__ __align__(16) char smem[];
    uint32_t smem_base = s2u(smem);

    int tid = threadIdx.x;
    int lane = tid & 31;
    int wid = tid >> 5;
    int wm = wid & 1;
    int wn = wid >> 1;
    int m0 = blockIdx.y * 128;
    int n0 = blockIdx.x * 128;

    // cp.async coords: A — 2 threads/row, 2 cp16 each; B — 8 threads/row, 2 cp16 each
    int arow = tid >> 1;
    int acol = (tid & 1) * 16;       // halves
    int brow = tid >> 3;             // 0..31
    int bcol = (tid & 7) * 16;       // halves

    const __nv_bfloat16* pAh = Ahg + (size_t)(m0 + arow) * K + acol;
    const __nv_bfloat16* pAl = Alg + (size_t)(m0 + arow) * K + acol;
    const __nv_bfloat16* pBh = Bhg + (size_t)brow * N + n0 + bcol;
    const __nv_bfloat16* pBl = Blg + (size_t)brow * N + n0 + bcol;
    uint32_t aoff = (arow * GA_STRIDE + acol) * 2;
    uint32_t boff = (brow * GB_STRIDE + bcol) * 2;

    float acc[4][4][4];
    #pragma unroll
    for (int i = 0; i < 4; i++)
        #pragma unroll
        for (int j = 0; j < 4; j++)
            #pragma unroll
            for (int e = 0; e < 4; e++) acc[i][j][e] = 0.f;

    int niter = K / 32;

    auto issue = [&](int kt, int s) {
        uint32_t st = smem_base + s * GSTAGE;
        int ko = kt * 32;
        const __nv_bfloat16* ah = pAh + ko;
        const __nv_bfloat16* al = pAl + ko;
        const __nv_bfloat16* bh = pBh + (size_t)ko * N;
        const __nv_bfloat16* bl = pBl + (size_t)ko * N;
        cp16(st + aoff,                 ah);
        cp16(st + aoff + 16,            ah + 8);
        cp16(st + G_OFF_AL + aoff,      al);
        cp16(st + G_OFF_AL + aoff + 16, al + 8);
        cp16(st + G_OFF_BH + boff,      bh);
        cp16(st + G_OFF_BH + boff + 16, bh + 8);
        cp16(st + G_OFF_BL + boff,      bl);
        cp16(st + G_OFF_BL + boff + 16, bl + 8);
        cp_commit();
    };

    issue(0, 0);
    issue(1, 1);

    // loop-invariant ldsm base addresses (stage 0, sub-slice 0)
    int lrow = lane & 15;
    int lcol = (lane >> 4) * 8;
    uint32_t baseA[4];
    #pragma unroll
    for (int i = 0; i < 4; i++)
        baseA[i] = smem_base + ((wm * 64 + i * 16 + lrow) * GA_STRIDE + lcol) * 2;
    uint32_t baseB[2];
    #pragma unroll
    for (int jj = 0; jj < 2; jj++)
        baseB[jj] = smem_base + G_OFF_BH + (lrow * GB_STRIDE + wn * 32 + jj * 16 + lcol) * 2;

    int s = 0;
    for (int kt = 0; kt < niter; kt++) {
        if (kt + 1 < niter) cp_wait<1>();
        else                cp_wait<0>();
        __syncthreads();                  // stage s ready; all warps done with stage (s+2)%3

        if (kt + 2 < niter) {
            int s2 = s + 2; if (s2 >= 3) s2 -= 3;
            issue(kt + 2, s2);
        }

        uint32_t offS = (uint32_t)(s * GSTAGE);
        #pragma unroll
        for (int ss = 0; ss < 2; ss++) {
            uint32_t aSub = offS + ss * 32;                       // +16 halves
            uint32_t bSub = offS + ss * 16 * GB_STRIDE * 2;       // +16 rows

            uint32_t ah[4][4], al[4][4], bb[4][2];
            #pragma unroll
            for (int i = 0; i < 4; i++) {
                ldsm4(ah[i], baseA[i] + aSub);
                ldsm4(al[i], baseA[i] + GA_BYTES + aSub);
            }
            #pragma unroll
            for (int jj = 0; jj < 2; jj++) {
                uint32_t r[4];
                ldsm4t(r, baseB[jj] + bSub);
                bb[jj * 2][0] = r[0]; bb[jj * 2][1] = r[1];
                bb[jj * 2 + 1][0] = r[2]; bb[jj * 2 + 1][1] = r[3];
            }
            #pragma unroll
            for (int i = 0; i < 4; i++)
                #pragma unroll
                for (int j = 0; j < 4; j++) {
                    mma_bf16(acc[i][j], ah[i], bb[j]);
                    mma_bf16(acc[i][j], al[i], bb[j]);
                }
            #pragma unroll
            for (int jj = 0; jj < 2; jj++) {
                uint32_t r[4];
                ldsm4t(r, baseB[jj] + GB_BYTES + bSub);
                bb[jj * 2][0] = r[0]; bb[jj * 2][1] = r[1];
                bb[jj * 2 + 1][0] = r[2]; bb[jj * 2 + 1][1] = r[3];
            }
            #pragma unroll
            for (int i = 0; i < 4; i++)
                #pragma unroll
                for (int j = 0; j < 4; j++)
                    mma_bf16(acc[i][j], ah[i], bb[j]);
        }
        s++; if (s == 3) s = 0;
    }

    int gid = lane >> 2, tig = lane & 3;
    #pragma unroll
    for (int i = 0; i < 4; i++) {
        #pragma unroll
        for (int j = 0; j < 4; j++) {
            int n = n0 + wn * 32 + j * 8 + 2 * tig;
            if (MODE == 0) {
                int hq = n / 192;
                int f = n - hq * 192;
                #pragma unroll
                for (int rh = 0; rh < 2; rh++) {
                    int m = m0 + wm * 64 + i * 16 + gid + rh * 8;
                    float v0 = acc[i][j][rh * 2 + 0] + bias[n];
                    float v1 = acc[i][j][rh * 2 + 1] + bias[n + 1];
                    int bb2 = m >> 11;
                    int ss2 = m & 2047;
                    size_t base = (((size_t)(bb2 * HEADS + hq)) * SEQ + ss2) * HD;
                    __nv_bfloat16 *dh, *dl;
                    int off;
                    if (f < 64)       { v0 *= 0.125f; v1 *= 0.125f; dh = qh; dl = ql; off = f; }
                    else if (f < 128) { dh = kh; dl = kl; off = f - 64; }
                    else              { dh = vh; dl = vl; off = f - 128; }
                    uint32_t hi, lo;
                    pack_hi_lo(v0, v1, hi, lo);
                    *reinterpret_cast<uint32_t*>(&dh[base + off]) = hi;
                    *reinterpret_cast<uint32_t*>(&dl[base + off]) = lo;
                }
            } else {
                #pragma unroll
                for (int rh = 0; rh < 2; rh++) {
                    int m = m0 + wm * 64 + i * 16 + gid + rh * 8;
                    float v0 = acc[i][j][rh * 2 + 0] + bias[n];
                    float v1 = acc[i][j][rh * 2 + 1] + bias[n + 1];
                    *reinterpret_cast<float2*>(&Cout[(size_t)m * N + n]) = make_float2(v0, v1);
                }
            }
        }
    }
}

// ============================ Tensor-core flash attention, 2-stage KV, 1 barrier/iter ============================
#define KVSTRIDE (64 * 72)
__global__ void __launch_bounds__(256) attn_mma_kernel(
    const __nv_bfloat16* __restrict__ qh_g, const __nv_bfloat16* __restrict__ ql_g,
    const __nv_bfloat16* __restrict__ kh_g, const __nv_bfloat16* __restrict__ kl_g,
    const __nv_bfloat16* __restrict__ vh_g, const __nv_bfloat16* __restrict__ vl_g,
    __nv_bfloat16* __restrict__ y_hi, __nv_bfloat16* __restrict__ y_lo)
{
    extern __shared__ __nv_bfloat16 smb[];
    __nv_bfloat16* sQh = smb;                      // [128][72]
    __nv_bfloat16* sQl = sQh + 128 * 72;
    __nv_bfloat16* sKh = sQl + 128 * 72;           // [2][64][72]
    __nv_bfloat16* sKl = sKh + 2 * KVSTRIDE;
    __nv_bfloat16* sVh = sKl + 2 * KVSTRIDE;
    __nv_bfloat16* sVl = sVh + 2 * KVSTRIDE;

    int bh = blockIdx.x;
    int qt = (gridDim.y - 1) - blockIdx.y;   // heavy tiles first
    int tid = threadIdx.x;
    int lane = tid & 31;
    int w = tid >> 5;
    int gid = lane >> 2, tig = lane & 3;
    int lrow = lane & 15, lcol = (lane >> 4) * 8;

    int q0 = qt * 128;
    const size_t bhoff = (size_t)bh * SEQ * HD;

    int kvr = tid >> 3;
    int kvd = (tid & 7) * 8;
    auto issue_kv = [&](int kt, int st) {
        int c0 = kt * 64;
        size_t base = st * KVSTRIDE;
        #pragma unroll
        for (int i = 0; i < 2; i++) {
            int r = kvr + i * 32;
            size_t g = bhoff + (size_t)(c0 + r) * HD + kvd;
            size_t sm = base + r * 72 + kvd;
            cp16(s2u(&sKh[sm]), &kh_g[g]);
            cp16(s2u(&sKl[sm]), &kl_g[g]);
            cp16(s2u(&sVh[sm]), &vh_g[g]);
            cp16(s2u(&sVl[sm]), &vl_g[g]);
        }
        cp_commit();
    };

    int ktmax = 2 * qt + 1;
    issue_kv(0, 0);

    #pragma unroll
    for (int i = 0; i < 4; i++) {
        int chunk = tid + i * 256;
        int r = chunk >> 3, d8 = (chunk & 7) * 8;
        size_t g = bhoff + (size_t)(q0 + r) * HD + d8;
        *reinterpret_cast<uint4*>(&sQh[r * 72 + d8]) = *reinterpret_cast<const uint4*>(&qh_g[g]);
        *reinterpret_cast<uint4*>(&sQl[r * 72 + d8]) = *reinterpret_cast<const uint4*>(&ql_g[g]);
    }
    __syncthreads();

    uint32_t qfh[4][4], qfl[4][4];
    #pragma unroll
    for (int kk = 0; kk < 4; kk++) {
        ldsm4(qfh[kk], s2u(&sQh[(w * 16 + lrow) * 72 + kk * 16 + lcol]));
        ldsm4(qfl[kk], s2u(&sQl[(w * 16 + lrow) * 72 + kk * 16 + lcol]));
    }

    float m_r[2] = {-1e30f, -1e30f};
    float l_r[2] = {0.f, 0.f};
    float o[8][4];
    #pragma unroll
    for (int j = 0; j < 8; j++)
        #pragma unroll
        for (int c = 0; c < 4; c++) o[j][c] = 0.f;

    for (int kt = 0; kt <= ktmax; kt++) {
        int c0 = kt * 64;
        int st = kt & 1;
        uint32_t offKV = (uint32_t)(st * KVSTRIDE * 2);

        cp_wait<0>();
        __syncthreads();   // stage st ready; all warps done reading the other stage

        if (kt < ktmax) issue_kv(kt + 1, (kt + 1) & 1);

        float s[8][4];
        #pragma unroll
        for (int j = 0; j < 8; j++)
            #pragma unroll
            for (int c = 0; c < 4; c++) s[j][c] = 0.f;

        #pragma unroll
        for (int kk = 0; kk < 4; kk++) {
            #pragma unroll
            for (int g2 = 0; g2 < 4; g2++) {
                uint32_t rh[4], rl[4];
                ldsm4(rh, s2u(&sKh[(g2 * 16 + lrow) * 72 + kk * 16 + lcol]) + offKV);
                ldsm4(rl, s2u(&sKl[(g2 * 16 + lrow) * 72 + kk * 16 + lcol]) + offKV);
                uint32_t b0h[2] = {rh[0], rh[2]}, b1h[2] = {rh[1], rh[3]};
                uint32_t b0l[2] = {rl[0], rl[2]}, b1l[2] = {rl[1], rl[3]};
                mma_bf16(s[g2 * 2],     qfh[kk], b0h);
                mma_bf16(s[g2 * 2],     qfl[kk], b0h);
                mma_bf16(s[g2 * 2],     qfh[kk], b0l);
                mma_bf16(s[g2 * 2 + 1], qfh[kk], b1h);
                mma_bf16(s[g2 * 2 + 1], qfl[kk], b1h);
                mma_bf16(s[g2 * 2 + 1], qfh[kk], b1l);
            }
        }

        if (kt >= 2 * qt) {
            int row0 = q0 + w * 16 + gid;
            #pragma unroll
            for (int j = 0; j < 8; j++) {
                int col = c0 + j * 8 + 2 * tig;
                if (col     > row0)     s[j][0] = -1e30f;
                if (col + 1 > row0)     s[j][1] = -1e30f;
                if (col     > row0 + 8) s[j][2] = -1e30f;
                if (col + 1 > row0 + 8) s[j][3] = -1e30f;
            }
        }

        float mx0 = -1e30f, mx1 = -1e30f;
        #pragma unroll
        for (int j = 0; j < 8; j++) {
            mx0 = fmaxf(mx0, fmaxf(s[j][0], s[j][1]));
            mx1 = fmaxf(mx1, fmaxf(s[j][2], s[j][3]));
        }
        mx0 = fmaxf(mx0, __shfl_xor_sync(0xffffffffu, mx0, 1));
        mx0 = fmaxf(mx0, __shfl_xor_sync(0xffffffffu, mx0, 2));
        mx1 = fmaxf(mx1, __shfl_xor_sync(0xffffffffu, mx1, 1));
        mx1 = fmaxf(mx1, __shfl_xor_sync(0xffffffffu, mx1, 2));
        float mn0 = fmaxf(m_r[0], mx0);
        float mn1 = fmaxf(m_r[1], mx1);
        float corr0 = fast_exp(m_r[0] - mn0);
        float corr1 = fast_exp(m_r[1] - mn1);
        float rs0 = 0.f, rs1 = 0.f;
        #pragma unroll
        for (int j = 0; j < 8; j++) {
            s[j][0] = fast_exp(s[j][0] - mn0); rs0 += s[j][0];
            s[j][1] = fast_exp(s[j][1] - mn0); rs0 += s[j][1];
            s[j][2] = fast_exp(s[j][2] - mn1); rs1 += s[j][2];
            s[j][3] = fast_exp(s[j][3] - mn1); rs1 += s[j][3];
        }
        rs0 += __shfl_xor_sync(0xffffffffu, rs0, 1);
        rs0 += __shfl_xor_sync(0xffffffffu, rs0, 2);
        rs1 += __shfl_xor_sync(0xffffffffu, rs1, 1);
        rs1 += __shfl_xor_sync(0xffffffffu, rs1, 2);
        l_r[0] = l_r[0] * corr0 + rs0;
        l_r[1] = l_r[1] * corr1 + rs1;
        m_r[0] = mn0; m_r[1] = mn1;
        #pragma unroll
        for (int j = 0; j < 8; j++) {
            o[j][0] *= corr0; o[j][1] *= corr0;
            o[j][2] *= corr1; o[j][3] *= corr1;
        }

        #pragma unroll
        for (int kk = 0; kk < 4; kk++) {
            uint32_t ph[4], pl[4];
            pack_hi_lo(s[2 * kk][0],     s[2 * kk][1],     ph[0], pl[0]);
            pack_hi_lo(s[2 * kk][2],     s[2 * kk][3],     ph[1], pl[1]);
            pack_hi_lo(s[2 * kk + 1][0], s[2 * kk + 1][1], ph[2], pl[2]);
            pack_hi_lo(s[2 * kk + 1][2], s[2 * kk + 1][3], ph[3], pl[3]);
            #pragma unroll
            for (int g2 = 0; g2 < 4; g2++) {
                uint32_t rvh[4], rvl[4];
                ldsm4t(rvh, s2u(&sVh[(kk * 16 + lrow) * 72 + g2 * 16 + lcol]) + offKV);
                ldsm4t(rvl, s2u(&sVl[(kk * 16 + lrow) * 72 + g2 * 16 + lcol]) + offKV);
                uint32_t bh0[2] = {rvh[0], rvh[1]}, bh1[2] = {rvh[2], rvh[3]};
                uint32_t bl0[2] = {rvl[0], rvl[1]}, bl1[2] = {rvl[2], rvl[3]};
                mma_bf16(o[g2 * 2],     ph, bh0);
                mma_bf16(o[g2 * 2],     pl, bh0);
                mma_bf16(o[g2 * 2],     ph, bl0);
                mma_bf16(o[g2 * 2 + 1], ph, bh1);
                mma_bf16(o[g2 * 2 + 1], pl, bh1);
                mma_bf16(o[g2 * 2 + 1], ph, bl1);
            }
        }
    }

    int b = bh >> 4, hh = bh & 15;
    float inv0 = 1.0f / l_r[0];
    float inv1 = 1.0f / l_r[1];
    #pragma unroll
    for (int h2 = 0; h2 < 2; h2++) {
        int srow = q0 + w * 16 + gid + h2 * 8;
        float inv = h2 ? inv1 : inv0;
        size_t base = (((size_t)(b * SEQ + srow)) * HEADS + hh) * HD;
        #pragma unroll
        for (int j = 0; j < 8; j++) {
            float a = o[j][h2 * 2 + 0] * inv;
            float c = o[j][h2 * 2 + 1] * inv;
            uint32_t hi, lo;
            pack_hi_lo(a, c, hi, lo);
            int d = j * 8 + 2 * tig;
            *reinterpret_cast<uint32_t*>(&y_hi[base + d]) = hi;
            *reinterpret_cast<uint32_t*>(&y_lo[base + d]) = lo;
        }
    }
}

// ============================ launch ============================
extern "C" void kernel_launch(void* const* d_in, const int* in_sizes, int n_in,
                              void* d_out, int out_size)
{
    const float* x        = (const float*)d_in[0];
    const float* ln_scale = (const float*)d_in[2];
    const float* ln_bias  = (const float*)d_in[3];
    const float* w_qkv    = (const float*)d_in[4];
    const float* b_qkv    = (const float*)d_in[5];
    const float* w_out    = (const float*)d_in[6];
    const float* b_out    = (const float*)d_in[7];
    float* out = (float*)d_out;

    __nv_bfloat16 *xn_hi, *xn_lo, *wq_hi, *wq_lo, *wo_hi, *wo_lo, *y_hi, *y_lo;
    __nv_bfloat16 *qh, *ql, *kh, *kl, *vh, *vl;
    cudaGetSymbolAddress((void**)&xn_hi, g_xn_hi);
    cudaGetSymbolAddress((void**)&xn_lo, g_xn_lo);
    cudaGetSymbolAddress((void**)&wq_hi, g_wq_hi);
    cudaGetSymbolAddress((void**)&wq_lo, g_wq_lo);
    cudaGetSymbolAddress((void**)&wo_hi, g_wo_hi);
    cudaGetSymbolAddress((void**)&wo_lo, g_wo_lo);
    cudaGetSymbolAddress((void**)&y_hi,  g_y_hi);
    cudaGetSymbolAddress((void**)&y_lo,  g_y_lo);
    cudaGetSymbolAddress((void**)&qh, g_qh);
    cudaGetSymbolAddress((void**)&ql, g_ql);
    cudaGetSymbolAddress((void**)&kh, g_kh);
    cudaGetSymbolAddress((void**)&kl, g_kl);
    cudaGetSymbolAddress((void**)&vh, g_vh);
    cudaGetSymbolAddress((void**)&vl, g_vl);

    // 1. LayerNorm -> bf16 hi/lo
    ln_kernel<<<ROWS, 256>>>(x, ln_scale, ln_bias, xn_hi, xn_lo);

    // 1b. weight decomposition
    decomp_kernel<<<512, 256>>>(w_qkv, wq_hi, wq_lo, DIM * QKV_N);
    decomp_kernel<<<256, 256>>>(w_out, wo_hi, wo_lo, DIM * DIM);

    int gemm_smem = 3 * GSTAGE;   // 113664

    // 2. QKV projection -> q/k/v bf16 hi/lo (q pre-scaled)
    {
        cudaFuncSetAttribute(mma_gemm<0>,
                             cudaFuncAttributeMaxDynamicSharedMemorySize, gemm_smem);
        dim3 grid(QKV_N / 128, ROWS / 128);  // (24, 64)
        mma_gemm<0><<<grid, 256, gemm_smem>>>(xn_hi, xn_lo, wq_hi, wq_lo, b_qkv, nullptr,
                                              ROWS, QKV_N, DIM, qh, ql, kh, kl, vh, vl);
    }

    // 3. tensor-core causal flash attention (2-stage KV, 1 barrier/iter)
    {
        int smem = (2 * 128 * 72 + 8 * KVSTRIDE) * sizeof(__nv_bfloat16);  // 110592
        cudaFuncSetAttribute(attn_mma_kernel,
                             cudaFuncAttributeMaxDynamicSharedMemorySize, smem);
        dim3 grid(BATCH * HEADS, SEQ / 128);  // (64, 16)
        attn_mma_kernel<<<grid, 256, smem>>>(qh, ql, kh, kl, vh, vl, y_hi, y_lo);
    }

    // 4. output projection -> d_out
    {
        cudaFuncSetAttribute(mma_gemm<1>,
                             cudaFuncAttributeMaxDynamicSharedMemorySize, gemm_smem);
        dim3 grid(DIM / 128, ROWS / 128);    // (8, 64)
        mma_gemm<1><<<grid, 256, gemm_smem>>>(y_hi, y_lo, wo_hi, wo_lo, b_out, out,
                                              ROWS, DIM, DIM,
                                              nullptr, nullptr, nullptr, nullptr, nullptr, nullptr);
    }
}

// round 7
// speedup vs baseline: 2.8861x; 1.0863x over previous
#include <cuda_runtime.h>
#include <cuda_fp16.h>
#include <cstdint>

// Problem constants
#define BATCH 4
#define SEQ   2048
#define DIM   1024
#define HEADS 16
#define HD    64
#define ROWS  (BATCH * SEQ)          // 8192
#define QKV_N (HEADS * 3 * HD)       // 3072
#define BHSD  (BATCH * HEADS * SEQ * HD)

// -------- scratch (static device globals; no allocation allowed) --------
__device__ __half g_xn_hi[ROWS * DIM];
__device__ __half g_xn_lo[ROWS * DIM];
__device__ __half g_wq_hi[DIM * QKV_N];
__device__ __half g_wq_lo[DIM * QKV_N];
__device__ __half g_wo_hi[DIM * DIM];
__device__ __half g_wo_lo[DIM * DIM];      // written by decomp, unused by 2-pass proj
__device__ __half g_qh[BHSD];   // [b,h,s,d] fp16 hi/lo
__device__ __half g_ql[BHSD];
__device__ __half g_kh[BHSD];
__device__ __half g_kl[BHSD];
__device__ __half g_vh[BHSD];   // V: hi only (2-pass PV)
__device__ __half g_y_hi[ROWS * DIM];   // attn out [b,s,h,d]
__device__ __half g_y_lo[ROWS * DIM];

// ============================ helpers ============================
__device__ __forceinline__ uint32_t s2u(const void* p) {
    return (uint32_t)__cvta_generic_to_shared(p);
}
__device__ __forceinline__ void ldsm4(uint32_t* r, uint32_t addr) {
    asm volatile("ldmatrix.sync.aligned.m8n8.x4.shared.b16 {%0,%1,%2,%3}, [%4];\n"
                 : "=r"(r[0]), "=r"(r[1]), "=r"(r[2]), "=r"(r[3]) : "r"(addr));
}
__device__ __forceinline__ void ldsm4t(uint32_t* r, uint32_t addr) {
    asm volatile("ldmatrix.sync.aligned.m8n8.x4.trans.shared.b16 {%0,%1,%2,%3}, [%4];\n"
                 : "=r"(r[0]), "=r"(r[1]), "=r"(r[2]), "=r"(r[3]) : "r"(addr));
}
__device__ __forceinline__ void mma_f16(float* c, const uint32_t* a, const uint32_t* b) {
    asm volatile(
        "mma.sync.aligned.m16n8k16.row.col.f32.f16.f16.f32 "
        "{%0,%1,%2,%3}, {%4,%5,%6,%7}, {%8,%9}, {%0,%1,%2,%3};\n"
        : "+f"(c[0]), "+f"(c[1]), "+f"(c[2]), "+f"(c[3])
        : "r"(a[0]), "r"(a[1]), "r"(a[2]), "r"(a[3]), "r"(b[0]), "r"(b[1]));
}
__device__ __forceinline__ void cp16(uint32_t smem_dst, const void* gmem_src) {
    asm volatile("cp.async.cg.shared.global [%0], [%1], 16;\n"
                 :: "r"(smem_dst), "l"(gmem_src));
}
__device__ __forceinline__ void cp_commit() {
    asm volatile("cp.async.commit_group;\n");
}
template <int N>
__device__ __forceinline__ void cp_wait() {
    asm volatile("cp.async.wait_group %0;\n" :: "n"(N));
}
__device__ __forceinline__ void split_f16(float x, __half& h, __half& l) {
    h = __float2half_rn(x);
    l = __float2half_rn(x - __half2float(h));
}
__device__ __forceinline__ void pack_hi_lo(float a, float b, uint32_t& hi, uint32_t& lo) {
    __half2 h2 = __floats2half2_rn(a, b);     // low = a
    float ra = a - __low2float(h2);
    float rb = b - __high2float(h2);
    __half2 l2 = __floats2half2_rn(ra, rb);
    hi = *reinterpret_cast<uint32_t*>(&h2);
    lo = *reinterpret_cast<uint32_t*>(&l2);
}
// fast exp on FMA pipe (no MUFU). valid for x <= 0.
__device__ __forceinline__ float fast_exp(float x) {
    float t = x * 1.4426950408889634f;
    t = fmaxf(t, -126.0f);
    float fi = rintf(t);
    float g = (t - fi) * 0.6931471805599453f;
    float p = 8.3333333e-3f;
    p = fmaf(p, g, 4.1666667e-2f);
    p = fmaf(p, g, 0.16666667f);
    p = fmaf(p, g, 0.5f);
    p = fmaf(p, g, 1.0f);
    p = fmaf(p, g, 1.0f);
    int ei = (int)fi;
    float sc = __int_as_float((ei + 127) << 23);
    return sc * p;
}

// ============================ LayerNorm -> hi/lo fp16 ============================
__global__ void __launch_bounds__(256) ln_kernel(
    const float* __restrict__ x,
    const float* __restrict__ gamma,
    const float* __restrict__ beta,
    __half* __restrict__ out_hi,
    __half* __restrict__ out_lo)
{
    int row = blockIdx.x;
    int t = threadIdx.x;
    const float4* xr = reinterpret_cast<const float4*>(x + (size_t)row * DIM);
    float4 v = xr[t];
    float s1 = v.x + v.y + v.z + v.w;
    float s2 = v.x*v.x + v.y*v.y + v.z*v.z + v.w*v.w;
    #pragma unroll
    for (int o = 16; o > 0; o >>= 1) {
        s1 += __shfl_xor_sync(0xffffffffu, s1, o);
        s2 += __shfl_xor_sync(0xffffffffu, s2, o);
    }
    __shared__ float r1[8], r2[8];
    __shared__ float sh_mu, sh_rstd;
    if ((t & 31) == 0) { r1[t >> 5] = s1; r2[t >> 5] = s2; }
    __syncthreads();
    if (t == 0) {
        float a = 0.f, b = 0.f;
        #pragma unroll
        for (int i = 0; i < 8; i++) { a += r1[i]; b += r2[i]; }
        float mu  = a * (1.0f / DIM);
        float var = b * (1.0f / DIM) - mu * mu;
        sh_mu = mu;
        sh_rstd = rsqrtf(var + 1e-6f);
    }
    __syncthreads();
    float mu = sh_mu, rstd = sh_rstd;
    float4 g = reinterpret_cast<const float4*>(gamma)[t];
    float4 b4 = reinterpret_cast<const float4*>(beta)[t];
    float o4[4];
    o4[0] = (v.x - mu) * rstd * g.x + b4.x;
    o4[1] = (v.y - mu) * rstd * g.y + b4.y;
    o4[2] = (v.z - mu) * rstd * g.z + b4.z;
    o4[3] = (v.w - mu) * rstd * g.w + b4.w;
    size_t base = (size_t)row * DIM + t * 4;
    #pragma unroll
    for (int i = 0; i < 4; i++) {
        __half h, l;
        split_f16(o4[i], h, l);
        out_hi[base + i] = h;
        out_lo[base + i] = l;
    }
}

// ============================ weight decomposition ============================
__global__ void __launch_bounds__(256) decomp_kernel(
    const float* __restrict__ w,
    __half* __restrict__ hi,
    __half* __restrict__ lo,
    int n)
{
    int i = blockIdx.x * blockDim.x + threadIdx.x;
    int stride = gridDim.x * blockDim.x;
    for (; i < n; i += stride) {
        __half h, l;
        split_f16(w[i], h, l);
        hi[i] = h;
        lo[i] = l;
    }
}

// ============================ fp16 compensated MMA GEMM 128x128, 32-K slices, 3-stage cp.async ============================
// MODE 0 (NPASS=3): QKV — scatter fp16 into q/k (hi+lo) and v (hi) with q-scale.
// MODE 1 (NPASS=2): fp32 C = (Ah+Al)@Bh + bias.
#define GA_STRIDE 40                        // halves per A row (32 data + 8 pad)
#define GB_STRIDE 136                       // halves per B row (128 data + 8 pad)
#define GA_BYTES  (128 * GA_STRIDE * 2)     // 10240
#define GB_BYTES  (32 * GB_STRIDE * 2)      // 8704
#define GSTAGE    (2 * GA_BYTES + 2 * GB_BYTES)  // 37888
#define G_OFF_AL  GA_BYTES
#define G_OFF_BH  (2 * GA_BYTES)
#define G_OFF_BL  (2 * GA_BYTES + GB_BYTES)
template <int MODE, int NPASS>
__global__ void __launch_bounds__(256, 2) mma_gemm(
    const __half* __restrict__ Ahg, const __half* __restrict__ Alg,
    const __half* __restrict__ Bhg, const __half* __restrict__ Blg,
    const float* __restrict__ bias,
    float* __restrict__ Cout,
    int M, int N, int K,
    __half* __restrict__ qh, __half* __restrict__ ql,
    __half* __restrict__ kh, __half* __restrict__ kl,
    __half* __restrict__ vh)
{
    extern __shared__ __align__(16) char smem[];
    uint32_t smem_base = s2u(smem);

    int tid = threadIdx.x;
    int lane = tid & 31;
    int wid = tid >> 5;
    int wm = wid & 1;
    int wn = wid >> 1;
    int m0 = blockIdx.y * 128;
    int n0 = blockIdx.x * 128;

    int arow = tid >> 1;
    int acol = (tid & 1) * 16;       // halves
    int brow = tid >> 3;             // 0..31
    int bcol = (tid & 7) * 16;       // halves

    const __half* pAh = Ahg + (size_t)(m0 + arow) * K + acol;
    const __half* pAl = Alg + (size_t)(m0 + arow) * K + acol;
    const __half* pBh = Bhg + (size_t)brow * N + n0 + bcol;
    const __half* pBl = Blg + (size_t)brow * N + n0 + bcol;
    uint32_t aoff = (arow * GA_STRIDE + acol) * 2;
    uint32_t boff = (brow * GB_STRIDE + bcol) * 2;

    float acc[4][4][4];
    #pragma unroll
    for (int i = 0; i < 4; i++)
        #pragma unroll
        for (int j = 0; j < 4; j++)
            #pragma unroll
            for (int e = 0; e < 4; e++) acc[i][j][e] = 0.f;

    int niter = K / 32;

    auto issue = [&](int kt, int s) {
        uint32_t st = smem_base + s * GSTAGE;
        int ko = kt * 32;
        const __half* ah = pAh + ko;
        const __half* al = pAl + ko;
        const __half* bh = pBh + (size_t)ko * N;
        cp16(st + aoff,                 ah);
        cp16(st + aoff + 16,            ah + 8);
        cp16(st + G_OFF_AL + aoff,      al);
        cp16(st + G_OFF_AL + aoff + 16, al + 8);
        cp16(st + G_OFF_BH + boff,      bh);
        cp16(st + G_OFF_BH + boff + 16, bh + 8);
        if (NPASS == 3) {
            const __half* bl = pBl + (size_t)ko * N;
            cp16(st + G_OFF_BL + boff,      bl);
            cp16(st + G_OFF_BL + boff + 16, bl + 8);
        }
        cp_commit();
    };

    issue(0, 0);
    issue(1, 1);

    int lrow = lane & 15;
    int lcol = (lane >> 4) * 8;
    uint32_t baseA[4];
    #pragma unroll
    for (int i = 0; i < 4; i++)
        baseA[i] = smem_base + ((wm * 64 + i * 16 + lrow) * GA_STRIDE + lcol) * 2;
    uint32_t baseB[2];
    #pragma unroll
    for (int jj = 0; jj < 2; jj++)
        baseB[jj] = smem_base + G_OFF_BH + (lrow * GB_STRIDE + wn * 32 + jj * 16 + lcol) * 2;

    int s = 0;
    for (int kt = 0; kt < niter; kt++) {
        if (kt + 1 < niter) cp_wait<1>();
        else                cp_wait<0>();
        __syncthreads();

        if (kt + 2 < niter) {
            int s2 = s + 2; if (s2 >= 3) s2 -= 3;
            issue(kt + 2, s2);
        }

        uint32_t offS = (uint32_t)(s * GSTAGE);
        #pragma unroll
        for (int ss = 0; ss < 2; ss++) {
            uint32_t aSub = offS + ss * 32;                       // +16 halves
            uint32_t bSub = offS + ss * 16 * GB_STRIDE * 2;       // +16 rows

            uint32_t ah[4][4], al[4][4], bb[4][2];
            #pragma unroll
            for (int i = 0; i < 4; i++) {
                ldsm4(ah[i], baseA[i] + aSub);
                ldsm4(al[i], baseA[i] + GA_BYTES + aSub);
            }
            #pragma unroll
            for (int jj = 0; jj < 2; jj++) {
                uint32_t r[4];
                ldsm4t(r, baseB[jj] + bSub);
                bb[jj * 2][0] = r[0]; bb[jj * 2][1] = r[1];
                bb[jj * 2 + 1][0] = r[2]; bb[jj * 2 + 1][1] = r[3];
            }
            #pragma unroll
            for (int i = 0; i < 4; i++)
                #pragma unroll
                for (int j = 0; j < 4; j++) {
                    mma_f16(acc[i][j], ah[i], bb[j]);
                    mma_f16(acc[i][j], al[i], bb[j]);
                }
            if (NPASS == 3) {
                #pragma unroll
                for (int jj = 0; jj < 2; jj++) {
                    uint32_t r[4];
                    ldsm4t(r, baseB[jj] + GB_BYTES + bSub);
                    bb[jj * 2][0] = r[0]; bb[jj * 2][1] = r[1];
                    bb[jj * 2 + 1][0] = r[2]; bb[jj * 2 + 1][1] = r[3];
                }
                #pragma unroll
                for (int i = 0; i < 4; i++)
                    #pragma unroll
                    for (int j = 0; j < 4; j++)
                        mma_f16(acc[i][j], ah[i], bb[j]);
            }
        }
        s++; if (s == 3) s = 0;
    }

    int gid = lane >> 2, tig = lane & 3;
    #pragma unroll
    for (int i = 0; i < 4; i++) {
        #pragma unroll
        for (int j = 0; j < 4; j++) {
            int n = n0 + wn * 32 + j * 8 + 2 * tig;
            if (MODE == 0) {
                int hq = n / 192;
                int f = n - hq * 192;
                #pragma unroll
                for (int rh = 0; rh < 2; rh++) {
                    int m = m0 + wm * 64 + i * 16 + gid + rh * 8;
                    float v0 = acc[i][j][rh * 2 + 0] + bias[n];
                    float v1 = acc[i][j][rh * 2 + 1] + bias[n + 1];
                    int bb2 = m >> 11;
                    int ss2 = m & 2047;
                    size_t base = (((size_t)(bb2 * HEADS + hq)) * SEQ + ss2) * HD;
                    if (f < 64) {
                        v0 *= 0.125f; v1 *= 0.125f;
                        uint32_t hi, lo;
                        pack_hi_lo(v0, v1, hi, lo);
                        *reinterpret_cast<uint32_t*>(&qh[base + f]) = hi;
                        *reinterpret_cast<uint32_t*>(&ql[base + f]) = lo;
                    } else if (f < 128) {
                        uint32_t hi, lo;
                        pack_hi_lo(v0, v1, hi, lo);
                        *reinterpret_cast<uint32_t*>(&kh[base + f - 64]) = hi;
                        *reinterpret_cast<uint32_t*>(&kl[base + f - 64]) = lo;
                    } else {
                        __half2 h2 = __floats2half2_rn(v0, v1);
                        *reinterpret_cast<uint32_t*>(&vh[base + f - 128]) =
                            *reinterpret_cast<uint32_t*>(&h2);
                    }
                }
            } else {
                #pragma unroll
                for (int rh = 0; rh < 2; rh++) {
                    int m = m0 + wm * 64 + i * 16 + gid + rh * 8;
                    float v0 = acc[i][j][rh * 2 + 0] + bias[n];
                    float v1 = acc[i][j][rh * 2 + 1] + bias[n + 1];
                    *reinterpret_cast<float2*>(&Cout[(size_t)m * N + n]) = make_float2(v0, v1);
                }
            }
        }
    }
}

// ============================ Tensor-core flash attention (fp16, 2-pass PV) ============================
#define KVSTRIDE (64 * 72)
__global__ void __launch_bounds__(256) attn_mma_kernel(
    const __half* __restrict__ qh_g, const __half* __restrict__ ql_g,
    const __half* __restrict__ kh_g, const __half* __restrict__ kl_g,
    const __half* __restrict__ vh_g,
    __half* __restrict__ y_hi, __half* __restrict__ y_lo)
{
    extern __shared__ __half smb[];
    __half* sQh = smb;                      // [128][72]
    __half* sQl = sQh + 128 * 72;
    __half* sKh = sQl + 128 * 72;           // [2][64][72]
    __half* sKl = sKh + 2 * KVSTRIDE;
    __half* sVh = sKl + 2 * KVSTRIDE;       // [2][64][72]

    int bh = blockIdx.x;
    int qt = (gridDim.y - 1) - blockIdx.y;   // heavy tiles first
    int tid = threadIdx.x;
    int lane = tid & 31;
    int w = tid >> 5;
    int gid = lane >> 2, tig = lane & 3;
    int lrow = lane & 15, lcol = (lane >> 4) * 8;

    int q0 = qt * 128;
    const size_t bhoff = (size_t)bh * SEQ * HD;

    int kvr = tid >> 3;
    int kvd = (tid & 7) * 8;
    auto issue_kv = [&](int kt, int st) {
        int c0 = kt * 64;
        size_t base = st * KVSTRIDE;
        #pragma unroll
        for (int i = 0; i < 2; i++) {
            int r = kvr + i * 32;
            size_t g = bhoff + (size_t)(c0 + r) * HD + kvd;
            size_t sm = base + r * 72 + kvd;
            cp16(s2u(&sKh[sm]), &kh_g[g]);
            cp16(s2u(&sKl[sm]), &kl_g[g]);
            cp16(s2u(&sVh[sm]), &vh_g[g]);
        }
        cp_commit();
    };

    int ktmax = 2 * qt + 1;
    issue_kv(0, 0);

    #pragma unroll
    for (int i = 0; i < 4; i++) {
        int chunk = tid + i * 256;
        int r = chunk >> 3, d8 = (chunk & 7) * 8;
        size_t g = bhoff + (size_t)(q0 + r) * HD + d8;
        *reinterpret_cast<uint4*>(&sQh[r * 72 + d8]) = *reinterpret_cast<const uint4*>(&qh_g[g]);
        *reinterpret_cast<uint4*>(&sQl[r * 72 + d8]) = *reinterpret_cast<const uint4*>(&ql_g[g]);
    }
    __syncthreads();

    uint32_t qfh[4][4], qfl[4][4];
    #pragma unroll
    for (int kk = 0; kk < 4; kk++) {
        ldsm4(qfh[kk], s2u(&sQh[(w * 16 + lrow) * 72 + kk * 16 + lcol]));
        ldsm4(qfl[kk], s2u(&sQl[(w * 16 + lrow) * 72 + kk * 16 + lcol]));
    }

    float m_r[2] = {-1e30f, -1e30f};
    float l_r[2] = {0.f, 0.f};
    float o[8][4];
    #pragma unroll
    for (int j = 0; j < 8; j++)
        #pragma unroll
        for (int c = 0; c < 4; c++) o[j][c] = 0.f;

    for (int kt = 0; kt <= ktmax; kt++) {
        int c0 = kt * 64;
        int st = kt & 1;
        uint32_t offKV = (uint32_t)(st * KVSTRIDE * 2);

        cp_wait<0>();
        __syncthreads();   // stage st ready; all warps done reading the other stage

        if (kt < ktmax) issue_kv(kt + 1, (kt + 1) & 1);

        float s[8][4];
        #pragma unroll
        for (int j = 0; j < 8; j++)
            #pragma unroll
            for (int c = 0; c < 4; c++) s[j][c] = 0.f;

        #pragma unroll
        for (int kk = 0; kk < 4; kk++) {
            #pragma unroll
            for (int g2 = 0; g2 < 4; g2++) {
                uint32_t rh[4], rl[4];
                ldsm4(rh, s2u(&sKh[(g2 * 16 + lrow) * 72 + kk * 16 + lcol]) + offKV);
                ldsm4(rl, s2u(&sKl[(g2 * 16 + lrow) * 72 + kk * 16 + lcol]) + offKV);
                uint32_t b0h[2] = {rh[0], rh[2]}, b1h[2] = {rh[1], rh[3]};
                uint32_t b0l[2] = {rl[0], rl[2]}, b1l[2] = {rl[1], rl[3]};
                mma_f16(s[g2 * 2],     qfh[kk], b0h);
                mma_f16(s[g2 * 2],     qfl[kk], b0h);
                mma_f16(s[g2 * 2],     qfh[kk], b0l);
                mma_f16(s[g2 * 2 + 1], qfh[kk], b1h);
                mma_f16(s[g2 * 2 + 1], qfl[kk], b1h);
                mma_f16(s[g2 * 2 + 1], qfh[kk], b1l);
            }
        }

        if (kt >= 2 * qt) {
            int row0 = q0 + w * 16 + gid;
            #pragma unroll
            for (int j = 0; j < 8; j++) {
                int col = c0 + j * 8 + 2 * tig;
                if (col     > row0)     s[j][0] = -1e30f;
                if (col + 1 > row0)     s[j][1] = -1e30f;
                if (col     > row0 + 8) s[j][2] = -1e30f;
                if (col + 1 > row0 + 8) s[j][3] = -1e30f;
            }
        }

        float mx0 = -1e30f, mx1 = -1e30f;
        #pragma unroll
        for (int j = 0; j < 8; j++) {
            mx0 = fmaxf(mx0, fmaxf(s[j][0], s[j][1]));
            mx1 = fmaxf(mx1, fmaxf(s[j][2], s[j][3]));
        }
        mx0 = fmaxf(mx0, __shfl_xor_sync(0xffffffffu, mx0, 1));
        mx0 = fmaxf(mx0, __shfl_xor_sync(0xffffffffu, mx0, 2));
        mx1 = fmaxf(mx1, __shfl_xor_sync(0xffffffffu, mx1, 1));
        mx1 = fmaxf(mx1, __shfl_xor_sync(0xffffffffu, mx1, 2));
        float mn0 = fmaxf(m_r[0], mx0);
        float mn1 = fmaxf(m_r[1], mx1);
        float corr0 = fast_exp(m_r[0] - mn0);
        float corr1 = fast_exp(m_r[1] - mn1);
        float rs0 = 0.f, rs1 = 0.f;
        #pragma unroll
        for (int j = 0; j < 8; j++) {
            s[j][0] = fast_exp(s[j][0] - mn0); rs0 += s[j][0];
            s[j][1] = fast_exp(s[j][1] - mn0); rs0 += s[j][1];
            s[j][2] = fast_exp(s[j][2] - mn1); rs1 += s[j][2];
            s[j][3] = fast_exp(s[j][3] - mn1); rs1 += s[j][3];
        }
        rs0 += __shfl_xor_sync(0xffffffffu, rs0, 1);
        rs0 += __shfl_xor_sync(0xffffffffu, rs0, 2);
        rs1 += __shfl_xor_sync(0xffffffffu, rs1, 1);
        rs1 += __shfl_xor_sync(0xffffffffu, rs1, 2);
        l_r[0] = l_r[0] * corr0 + rs0;
        l_r[1] = l_r[1] * corr1 + rs1;
        m_r[0] = mn0; m_r[1] = mn1;
        #pragma unroll
        for (int j = 0; j < 8; j++) {
            o[j][0] *= corr0; o[j][1] *= corr0;
            o[j][2] *= corr1; o[j][3] *= corr1;
        }

        // ---- O += P V (2-pass: PhVh + PlVh) ----
        #pragma unroll
        for (int kk = 0; kk < 4; kk++) {
            uint32_t ph[4], pl[4];
            pack_hi_lo(s[2 * kk][0],     s[2 * kk][1],     ph[0], pl[0]);
            pack_hi_lo(s[2 * kk][2],     s[2 * kk][3],     ph[1], pl[1]);
            pack_hi_lo(s[2 * kk + 1][0], s[2 * kk + 1][1], ph[2], pl[2]);
            pack_hi_lo(s[2 * kk + 1][2], s[2 * kk + 1][3], ph[3], pl[3]);
            #pragma unroll
            for (int g2 = 0; g2 < 4; g2++) {
                uint32_t rvh[4];
                ldsm4t(rvh, s2u(&sVh[(kk * 16 + lrow) * 72 + g2 * 16 + lcol]) + offKV);
                uint32_t bh0[2] = {rvh[0], rvh[1]}, bh1[2] = {rvh[2], rvh[3]};
                mma_f16(o[g2 * 2],     ph, bh0);
                mma_f16(o[g2 * 2],     pl, bh0);
                mma_f16(o[g2 * 2 + 1], ph, bh1);
                mma_f16(o[g2 * 2 + 1], pl, bh1);
            }
        }
    }

    int b = bh >> 4, hh = bh & 15;
    float inv0 = 1.0f / l_r[0];
    float inv1 = 1.0f / l_r[1];
    #pragma unroll
    for (int h2 = 0; h2 < 2; h2++) {
        int srow = q0 + w * 16 + gid + h2 * 8;
        float inv = h2 ? inv1 : inv0;
        size_t base = (((size_t)(b * SEQ + srow)) * HEADS + hh) * HD;
        #pragma unroll
        for (int j = 0; j < 8; j++) {
            float a = o[j][h2 * 2 + 0] * inv;
            float c = o[j][h2 * 2 + 1] * inv;
            uint32_t hi, lo;
            pack_hi_lo(a, c, hi, lo);
            int d = j * 8 + 2 * tig;
            *reinterpret_cast<uint32_t*>(&y_hi[base + d]) = hi;
            *reinterpret_cast<uint32_t*>(&y_lo[base + d]) = lo;
        }
    }
}

// ============================ launch ============================
extern "C" void kernel_launch(void* const* d_in, const int* in_sizes, int n_in,
                              void* d_out, int out_size)
{
    const float* x        = (const float*)d_in[0];
    const float* ln_scale = (const float*)d_in[2];
    const float* ln_bias  = (const float*)d_in[3];
    const float* w_qkv    = (const float*)d_in[4];
    const float* b_qkv    = (const float*)d_in[5];
    const float* w_out    = (const float*)d_in[6];
    const float* b_out    = (const float*)d_in[7];
    float* out = (float*)d_out;

    __half *xn_hi, *xn_lo, *wq_hi, *wq_lo, *wo_hi, *wo_lo, *y_hi, *y_lo;
    __half *qh, *ql, *kh, *kl, *vh;
    cudaGetSymbolAddress((void**)&xn_hi, g_xn_hi);
    cudaGetSymbolAddress((void**)&xn_lo, g_xn_lo);
    cudaGetSymbolAddress((void**)&wq_hi, g_wq_hi);
    cudaGetSymbolAddress((void**)&wq_lo, g_wq_lo);
    cudaGetSymbolAddress((void**)&wo_hi, g_wo_hi);
    cudaGetSymbolAddress((void**)&wo_lo, g_wo_lo);
    cudaGetSymbolAddress((void**)&y_hi,  g_y_hi);
    cudaGetSymbolAddress((void**)&y_lo,  g_y_lo);
    cudaGetSymbolAddress((void**)&qh, g_qh);
    cudaGetSymbolAddress((void**)&ql, g_ql);
    cudaGetSymbolAddress((void**)&kh, g_kh);
    cudaGetSymbolAddress((void**)&kl, g_kl);
    cudaGetSymbolAddress((void**)&vh, g_vh);

    // 1. LayerNorm -> fp16 hi/lo
    ln_kernel<<<ROWS, 256>>>(x, ln_scale, ln_bias, xn_hi, xn_lo);

    // 1b. weight decomposition
    decomp_kernel<<<512, 256>>>(w_qkv, wq_hi, wq_lo, DIM * QKV_N);
    decomp_kernel<<<256, 256>>>(w_out, wo_hi, wo_lo, DIM * DIM);

    int gemm_smem = 3 * GSTAGE;   // 113664

    // 2. QKV projection (3-pass) -> q/k fp16 hi/lo, v fp16 hi (q pre-scaled)
    {
        cudaFuncSetAttribute(mma_gemm<0, 3>,
                             cudaFuncAttributeMaxDynamicSharedMemorySize, gemm_smem);
        dim3 grid(QKV_N / 128, ROWS / 128);  // (24, 64)
        mma_gemm<0, 3><<<grid, 256, gemm_smem>>>(xn_hi, xn_lo, wq_hi, wq_lo, b_qkv, nullptr,
                                                 ROWS, QKV_N, DIM, qh, ql, kh, kl, vh);
    }

    // 3. tensor-core causal flash attention (3-pass QK, 2-pass PV)
    {
        int smem = (2 * 128 * 72 + 6 * KVSTRIDE) * sizeof(__half);  // 92160
        cudaFuncSetAttribute(attn_mma_kernel,
                             cudaFuncAttributeMaxDynamicSharedMemorySize, smem);
        dim3 grid(BATCH * HEADS, SEQ / 128);  // (64, 16)
        attn_mma_kernel<<<grid, 256, smem>>>(qh, ql, kh, kl, vh, y_hi, y_lo);
    }

    // 4. output projection (2-pass) -> d_out
    {
        cudaFuncSetAttribute(mma_gemm<1, 2>,
                             cudaFuncAttributeMaxDynamicSharedMemorySize, gemm_smem);
        dim3 grid(DIM / 128, ROWS / 128);    // (8, 64)
        mma_gemm<1, 2><<<grid, 256, gemm_smem>>>(y_hi, y_lo, wo_hi, wo_lo, b_out, out,
                                                 ROWS, DIM, DIM,
                                                 nullptr, nullptr, nullptr, nullptr, nullptr);
    }
}

// round 8
// speedup vs baseline: 3.8935x; 1.3491x over previous
#include <cuda_runtime.h>
#include <cuda_fp16.h>
#include <cstdint>

// Problem constants
#define BATCH 4
#define SEQ   2048
#define DIM   1024
#define HEADS 16
#define HD    64
#define ROWS  (BATCH * SEQ)          // 8192
#define QKV_N (HEADS * 3 * HD)       // 3072
#define BHSD  (BATCH * HEADS * SEQ * HD)

// -------- scratch (static device globals; no allocation allowed) --------
__device__ __half g_xn_hi[ROWS * DIM];
__device__ __half g_xn_lo[ROWS * DIM];
__device__ __half g_wq_hi[DIM * QKV_N];
__device__ __half g_wo_hi[DIM * DIM];
__device__ __half g_qh[BHSD];   // [b,h,s,d] fp16
__device__ __half g_ql[BHSD];
__device__ __half g_kh[BHSD];   // hi only (2-pass QK)
__device__ __half g_vh[BHSD];   // hi only (2-pass PV)
__device__ __half g_y_hi[ROWS * DIM];   // attn out [b,s,h,d]
__device__ __half g_y_lo[ROWS * DIM];

// ============================ helpers ============================
__device__ __forceinline__ uint32_t s2u(const void* p) {
    return (uint32_t)__cvta_generic_to_shared(p);
}
__device__ __forceinline__ void ldsm4(uint32_t* r, uint32_t addr) {
    asm volatile("ldmatrix.sync.aligned.m8n8.x4.shared.b16 {%0,%1,%2,%3}, [%4];\n"
                 : "=r"(r[0]), "=r"(r[1]), "=r"(r[2]), "=r"(r[3]) : "r"(addr));
}
__device__ __forceinline__ void ldsm4t(uint32_t* r, uint32_t addr) {
    asm volatile("ldmatrix.sync.aligned.m8n8.x4.trans.shared.b16 {%0,%1,%2,%3}, [%4];\n"
                 : "=r"(r[0]), "=r"(r[1]), "=r"(r[2]), "=r"(r[3]) : "r"(addr));
}
__device__ __forceinline__ void mma_f16(float* c, const uint32_t* a, const uint32_t* b) {
    asm volatile(
        "mma.sync.aligned.m16n8k16.row.col.f32.f16.f16.f32 "
        "{%0,%1,%2,%3}, {%4,%5,%6,%7}, {%8,%9}, {%0,%1,%2,%3};\n"
        : "+f"(c[0]), "+f"(c[1]), "+f"(c[2]), "+f"(c[3])
        : "r"(a[0]), "r"(a[1]), "r"(a[2]), "r"(a[3]), "r"(b[0]), "r"(b[1]));
}
__device__ __forceinline__ void cp16(uint32_t smem_dst, const void* gmem_src) {
    asm volatile("cp.async.cg.shared.global [%0], [%1], 16;\n"
                 :: "r"(smem_dst), "l"(gmem_src));
}
__device__ __forceinline__ void cp_commit() {
    asm volatile("cp.async.commit_group;\n");
}
template <int N>
__device__ __forceinline__ void cp_wait() {
    asm volatile("cp.async.wait_group %0;\n" :: "n"(N));
}
__device__ __forceinline__ void split_f16(float x, __half& h, __half& l) {
    h = __float2half_rn(x);
    l = __float2half_rn(x - __half2float(h));
}
__device__ __forceinline__ void pack_hi_lo(float a, float b, uint32_t& hi, uint32_t& lo) {
    __half2 h2 = __floats2half2_rn(a, b);     // low = a
    float ra = a - __low2float(h2);
    float rb = b - __high2float(h2);
    __half2 l2 = __floats2half2_rn(ra, rb);
    hi = *reinterpret_cast<uint32_t*>(&h2);
    lo = *reinterpret_cast<uint32_t*>(&l2);
}
// fast exp on FMA pipe (no MUFU). valid for x <= 0.
__device__ __forceinline__ float fast_exp(float x) {
    float t = x * 1.4426950408889634f;
    t = fmaxf(t, -126.0f);
    float fi = rintf(t);
    float g = (t - fi) * 0.6931471805599453f;
    float p = 8.3333333e-3f;
    p = fmaf(p, g, 4.1666667e-2f);
    p = fmaf(p, g, 0.16666667f);
    p = fmaf(p, g, 0.5f);
    p = fmaf(p, g, 1.0f);
    p = fmaf(p, g, 1.0f);
    int ei = (int)fi;
    float sc = __int_as_float((ei + 127) << 23);
    return sc * p;
}

// ============================ LayerNorm -> hi/lo fp16 ============================
__global__ void __launch_bounds__(256) ln_kernel(
    const float* __restrict__ x,
    const float* __restrict__ gamma,
    const float* __restrict__ beta,
    __half* __restrict__ out_hi,
    __half* __restrict__ out_lo)
{
    int row = blockIdx.x;
    int t = threadIdx.x;
    const float4* xr = reinterpret_cast<const float4*>(x + (size_t)row * DIM);
    float4 v = xr[t];
    float s1 = v.x + v.y + v.z + v.w;
    float s2 = v.x*v.x + v.y*v.y + v.z*v.z + v.w*v.w;
    #pragma unroll
    for (int o = 16; o > 0; o >>= 1) {
        s1 += __shfl_xor_sync(0xffffffffu, s1, o);
        s2 += __shfl_xor_sync(0xffffffffu, s2, o);
    }
    __shared__ float r1[8], r2[8];
    __shared__ float sh_mu, sh_rstd;
    if ((t & 31) == 0) { r1[t >> 5] = s1; r2[t >> 5] = s2; }
    __syncthreads();
    if (t == 0) {
        float a = 0.f, b = 0.f;
        #pragma unroll
        for (int i = 0; i < 8; i++) { a += r1[i]; b += r2[i]; }
        float mu  = a * (1.0f / DIM);
        float var = b * (1.0f / DIM) - mu * mu;
        sh_mu = mu;
        sh_rstd = rsqrtf(var + 1e-6f);
    }
    __syncthreads();
    float mu = sh_mu, rstd = sh_rstd;
    float4 g = reinterpret_cast<const float4*>(gamma)[t];
    float4 b4 = reinterpret_cast<const float4*>(beta)[t];
    float o4[4];
    o4[0] = (v.x - mu) * rstd * g.x + b4.x;
    o4[1] = (v.y - mu) * rstd * g.y + b4.y;
    o4[2] = (v.z - mu) * rstd * g.z + b4.z;
    o4[3] = (v.w - mu) * rstd * g.w + b4.w;
    size_t base = (size_t)row * DIM + t * 4;
    #pragma unroll
    for (int i = 0; i < 4; i++) {
        __half h, l;
        split_f16(o4[i], h, l);
        out_hi[base + i] = h;
        out_lo[base + i] = l;
    }
}

// ============================ fp32 -> fp16 convert (weights, hi only) ============================
__global__ void __launch_bounds__(256) convert_kernel(
    const float* __restrict__ w,
    __half* __restrict__ hi,
    int n)
{
    int i = blockIdx.x * blockDim.x + threadIdx.x;
    int stride = gridDim.x * blockDim.x;
    for (; i < n; i += stride)
        hi[i] = __float2half_rn(w[i]);
}

// ============================ fp16 2-pass MMA GEMM 128x128, 32-K slices, 3-stage cp.async ============================
// C = (Ah + Al) @ Bh (+ bias). Warp tile 32x64 (4x2 layout).
// MODE 0: QKV — scatter fp16 into q (hi+lo), k (hi), v (hi) with q-scale.
// MODE 1: fp32 C.
#define GA_STRIDE 40                        // halves per A row (32 data + 8 pad)
#define GB_STRIDE 136                       // halves per B row (128 data + 8 pad)
#define GA_BYTES  (128 * GA_STRIDE * 2)     // 10240
#define GB_BYTES  (32 * GB_STRIDE * 2)      // 8704
#define GSTAGE    (2 * GA_BYTES + GB_BYTES) // 29184
#define G_OFF_AL  GA_BYTES
#define G_OFF_BH  (2 * GA_BYTES)
template <int MODE>
__global__ void __launch_bounds__(256, 2) mma_gemm(
    const __half* __restrict__ Ahg, const __half* __restrict__ Alg,
    const __half* __restrict__ Bhg,
    const float* __restrict__ bias,
    float* __restrict__ Cout,
    int M, int N, int K,
    __half* __restrict__ qh, __half* __restrict__ ql,
    __half* __restrict__ kh, __half* __restrict__ vh)
{
    extern __shared__ __align__(16) char smem[];
    uint32_t smem_base = s2u(smem);

    int tid = threadIdx.x;
    int lane = tid & 31;
    int wid = tid >> 5;
    int wm = wid & 3;          // warp row (0..3) -> 32 rows each
    int wn = wid >> 2;         // warp col (0..1) -> 64 cols each
    int m0 = blockIdx.y * 128;
    int n0 = blockIdx.x * 128;

    int arow = tid >> 1;
    int acol = (tid & 1) * 16;       // halves
    int brow = tid >> 3;             // 0..31
    int bcol = (tid & 7) * 16;       // halves

    const __half* pAh = Ahg + (size_t)(m0 + arow) * K + acol;
    const __half* pAl = Alg + (size_t)(m0 + arow) * K + acol;
    const __half* pBh = Bhg + (size_t)brow * N + n0 + bcol;
    uint32_t aoff = (arow * GA_STRIDE + acol) * 2;
    uint32_t boff = (brow * GB_STRIDE + bcol) * 2;

    float acc[2][8][4];
    #pragma unroll
    for (int i = 0; i < 2; i++)
        #pragma unroll
        for (int j = 0; j < 8; j++)
            #pragma unroll
            for (int e = 0; e < 4; e++) acc[i][j][e] = 0.f;

    int niter = K / 32;

    auto issue = [&](int kt, int s) {
        uint32_t st = smem_base + s * GSTAGE;
        int ko = kt * 32;
        const __half* ah = pAh + ko;
        const __half* al = pAl + ko;
        const __half* bh = pBh + (size_t)ko * N;
        cp16(st + aoff,                 ah);
        cp16(st + aoff + 16,            ah + 8);
        cp16(st + G_OFF_AL + aoff,      al);
        cp16(st + G_OFF_AL + aoff + 16, al + 8);
        cp16(st + G_OFF_BH + boff,      bh);
        cp16(st + G_OFF_BH + boff + 16, bh + 8);
        cp_commit();
    };

    issue(0, 0);
    issue(1, 1);

    int lrow = lane & 15;
    int lcol = (lane >> 4) * 8;
    uint32_t baseA[2];
    #pragma unroll
    for (int i = 0; i < 2; i++)
        baseA[i] = smem_base + ((wm * 32 + i * 16 + lrow) * GA_STRIDE + lcol) * 2;
    uint32_t baseB[4];
    #pragma unroll
    for (int jj = 0; jj < 4; jj++)
        baseB[jj] = smem_base + G_OFF_BH + (lrow * GB_STRIDE + wn * 64 + jj * 16 + lcol) * 2;

    int s = 0;
    for (int kt = 0; kt < niter; kt++) {
        if (kt + 1 < niter) cp_wait<1>();
        else                cp_wait<0>();
        __syncthreads();

        if (kt + 2 < niter) {
            int s2 = s + 2; if (s2 >= 3) s2 -= 3;
            issue(kt + 2, s2);
        }

        uint32_t offS = (uint32_t)(s * GSTAGE);
        #pragma unroll
        for (int ss = 0; ss < 2; ss++) {
            uint32_t aSub = offS + ss * 32;                       // +16 halves
            uint32_t bSub = offS + ss * 16 * GB_STRIDE * 2;       // +16 rows

            uint32_t ah[2][4], al[2][4], bb[8][2];
            #pragma unroll
            for (int i = 0; i < 2; i++) {
                ldsm4(ah[i], baseA[i] + aSub);
                ldsm4(al[i], baseA[i] + GA_BYTES + aSub);
            }
            #pragma unroll
            for (int jj = 0; jj < 4; jj++) {
                uint32_t r[4];
                ldsm4t(r, baseB[jj] + bSub);
                bb[jj * 2][0] = r[0]; bb[jj * 2][1] = r[1];
                bb[jj * 2 + 1][0] = r[2]; bb[jj * 2 + 1][1] = r[3];
            }
            #pragma unroll
            for (int i = 0; i < 2; i++)
                #pragma unroll
                for (int j = 0; j < 8; j++) {
                    mma_f16(acc[i][j], ah[i], bb[j]);
                    mma_f16(acc[i][j], al[i], bb[j]);
                }
        }
        s++; if (s == 3) s = 0;
    }

    int gid = lane >> 2, tig = lane & 3;
    #pragma unroll
    for (int i = 0; i < 2; i++) {
        #pragma unroll
        for (int j = 0; j < 8; j++) {
            int n = n0 + wn * 64 + j * 8 + 2 * tig;
            if (MODE == 0) {
                int hq = n / 192;
                int f = n - hq * 192;
                #pragma unroll
                for (int rh = 0; rh < 2; rh++) {
                    int m = m0 + wm * 32 + i * 16 + gid + rh * 8;
                    float v0 = acc[i][j][rh * 2 + 0] + bias[n];
                    float v1 = acc[i][j][rh * 2 + 1] + bias[n + 1];
                    int bb2 = m >> 11;
                    int ss2 = m & 2047;
                    size_t base = (((size_t)(bb2 * HEADS + hq)) * SEQ + ss2) * HD;
                    if (f < 64) {
                        v0 *= 0.125f; v1 *= 0.125f;
                        uint32_t hi, lo;
                        pack_hi_lo(v0, v1, hi, lo);
                        *reinterpret_cast<uint32_t*>(&qh[base + f]) = hi;
                        *reinterpret_cast<uint32_t*>(&ql[base + f]) = lo;
                    } else if (f < 128) {
                        __half2 h2 = __floats2half2_rn(v0, v1);
                        *reinterpret_cast<uint32_t*>(&kh[base + f - 64]) =
                            *reinterpret_cast<uint32_t*>(&h2);
                    } else {
                        __half2 h2 = __floats2half2_rn(v0, v1);
                        *reinterpret_cast<uint32_t*>(&vh[base + f - 128]) =
                            *reinterpret_cast<uint32_t*>(&h2);
                    }
                }
            } else {
                #pragma unroll
                for (int rh = 0; rh < 2; rh++) {
                    int m = m0 + wm * 32 + i * 16 + gid + rh * 8;
                    float v0 = acc[i][j][rh * 2 + 0] + bias[n];
                    float v1 = acc[i][j][rh * 2 + 1] + bias[n + 1];
                    *reinterpret_cast<float2*>(&Cout[(size_t)m * N + n]) = make_float2(v0, v1);
                }
            }
        }
    }
}

// ============================ Tensor-core flash attention (2-pass QK, 2-pass PV) ============================
#define KVSTRIDE (64 * 72)
__global__ void __launch_bounds__(256) attn_mma_kernel(
    const __half* __restrict__ qh_g, const __half* __restrict__ ql_g,
    const __half* __restrict__ kh_g,
    const __half* __restrict__ vh_g,
    __half* __restrict__ y_hi, __half* __restrict__ y_lo)
{
    extern __shared__ __half smb[];
    __half* sQh = smb;                      // [128][72]
    __half* sQl = sQh + 128 * 72;
    __half* sKh = sQl + 128 * 72;           // [2][64][72]
    __half* sVh = sKh + 2 * KVSTRIDE;       // [2][64][72]

    int bh = blockIdx.x;
    int qt = (gridDim.y - 1) - blockIdx.y;   // heavy tiles first
    int tid = threadIdx.x;
    int lane = tid & 31;
    int w = tid >> 5;
    int gid = lane >> 2, tig = lane & 3;
    int lrow = lane & 15, lcol = (lane >> 4) * 8;

    int q0 = qt * 128;
    const size_t bhoff = (size_t)bh * SEQ * HD;

    int kvr = tid >> 3;
    int kvd = (tid & 7) * 8;
    auto issue_kv = [&](int kt, int st) {
        int c0 = kt * 64;
        size_t base = st * KVSTRIDE;
        #pragma unroll
        for (int i = 0; i < 2; i++) {
            int r = kvr + i * 32;
            size_t g = bhoff + (size_t)(c0 + r) * HD + kvd;
            size_t sm = base + r * 72 + kvd;
            cp16(s2u(&sKh[sm]), &kh_g[g]);
            cp16(s2u(&sVh[sm]), &vh_g[g]);
        }
        cp_commit();
    };

    int ktmax = 2 * qt + 1;
    issue_kv(0, 0);

    #pragma unroll
    for (int i = 0; i < 4; i++) {
        int chunk = tid + i * 256;
        int r = chunk >> 3, d8 = (chunk & 7) * 8;
        size_t g = bhoff + (size_t)(q0 + r) * HD + d8;
        *reinterpret_cast<uint4*>(&sQh[r * 72 + d8]) = *reinterpret_cast<const uint4*>(&qh_g[g]);
        *reinterpret_cast<uint4*>(&sQl[r * 72 + d8]) = *reinterpret_cast<const uint4*>(&ql_g[g]);
    }
    __syncthreads();

    uint32_t qfh[4][4], qfl[4][4];
    #pragma unroll
    for (int kk = 0; kk < 4; kk++) {
        ldsm4(qfh[kk], s2u(&sQh[(w * 16 + lrow) * 72 + kk * 16 + lcol]));
        ldsm4(qfl[kk], s2u(&sQl[(w * 16 + lrow) * 72 + kk * 16 + lcol]));
    }

    float m_r[2] = {-1e30f, -1e30f};
    float l_r[2] = {0.f, 0.f};
    float o[8][4];
    #pragma unroll
    for (int j = 0; j < 8; j++)
        #pragma unroll
        for (int c = 0; c < 4; c++) o[j][c] = 0.f;

    for (int kt = 0; kt <= ktmax; kt++) {
        int c0 = kt * 64;
        int st = kt & 1;
        uint32_t offKV = (uint32_t)(st * KVSTRIDE * 2);

        cp_wait<0>();
        __syncthreads();   // stage st ready; all warps done reading the other stage

        if (kt < ktmax) issue_kv(kt + 1, (kt + 1) & 1);

        float s[8][4];
        #pragma unroll
        for (int j = 0; j < 8; j++)
            #pragma unroll
            for (int c = 0; c < 4; c++) s[j][c] = 0.f;

        #pragma unroll
        for (int kk = 0; kk < 4; kk++) {
            #pragma unroll
            for (int g2 = 0; g2 < 4; g2++) {
                uint32_t rh[4];
                ldsm4(rh, s2u(&sKh[(g2 * 16 + lrow) * 72 + kk * 16 + lcol]) + offKV);
                uint32_t b0h[2] = {rh[0], rh[2]}, b1h[2] = {rh[1], rh[3]};
                mma_f16(s[g2 * 2],     qfh[kk], b0h);
                mma_f16(s[g2 * 2],     qfl[kk], b0h);
                mma_f16(s[g2 * 2 + 1], qfh[kk], b1h);
                mma_f16(s[g2 * 2 + 1], qfl[kk], b1h);
            }
        }

        if (kt >= 2 * qt) {
            int row0 = q0 + w * 16 + gid;
            #pragma unroll
            for (int j = 0; j < 8; j++) {
                int col = c0 + j * 8 + 2 * tig;
                if (col     > row0)     s[j][0] = -1e30f;
                if (col + 1 > row0)     s[j][1] = -1e30f;
                if (col     > row0 + 8) s[j][2] = -1e30f;
                if (col + 1 > row0 + 8) s[j][3] = -1e30f;
            }
        }

        float mx0 = -1e30f, mx1 = -1e30f;
        #pragma unroll
        for (int j = 0; j < 8; j++) {
            mx0 = fmaxf(mx0, fmaxf(s[j][0], s[j][1]));
            mx1 = fmaxf(mx1, fmaxf(s[j][2], s[j][3]));
        }
        mx0 = fmaxf(mx0, __shfl_xor_sync(0xffffffffu, mx0, 1));
        mx0 = fmaxf(mx0, __shfl_xor_sync(0xffffffffu, mx0, 2));
        mx1 = fmaxf(mx1, __shfl_xor_sync(0xffffffffu, mx1, 1));
        mx1 = fmaxf(mx1, __shfl_xor_sync(0xffffffffu, mx1, 2));
        float mn0 = fmaxf(m_r[0], mx0);
        float mn1 = fmaxf(m_r[1], mx1);
        float corr0 = fast_exp(m_r[0] - mn0);
        float corr1 = fast_exp(m_r[1] - mn1);
        float rs0 = 0.f, rs1 = 0.f;
        #pragma unroll
        for (int j = 0; j < 8; j++) {
            s[j][0] = fast_exp(s[j][0] - mn0); rs0 += s[j][0];
            s[j][1] = fast_exp(s[j][1] - mn0); rs0 += s[j][1];
            s[j][2] = fast_exp(s[j][2] - mn1); rs1 += s[j][2];
            s[j][3] = fast_exp(s[j][3] - mn1); rs1 += s[j][3];
        }
        rs0 += __shfl_xor_sync(0xffffffffu, rs0, 1);
        rs0 += __shfl_xor_sync(0xffffffffu, rs0, 2);
        rs1 += __shfl_xor_sync(0xffffffffu, rs1, 1);
        rs1 += __shfl_xor_sync(0xffffffffu, rs1, 2);
        l_r[0] = l_r[0] * corr0 + rs0;
        l_r[1] = l_r[1] * corr1 + rs1;
        m_r[0] = mn0; m_r[1] = mn1;
        #pragma unroll
        for (int j = 0; j < 8; j++) {
            o[j][0] *= corr0; o[j][1] *= corr0;
            o[j][2] *= corr1; o[j][3] *= corr1;
        }

        // ---- O += P V (2-pass: PhVh + PlVh) ----
        #pragma unroll
        for (int kk = 0; kk < 4; kk++) {
            uint32_t ph[4], pl[4];
            pack_hi_lo(s[2 * kk][0],     s[2 * kk][1],     ph[0], pl[0]);
            pack_hi_lo(s[2 * kk][2],     s[2 * kk][3],     ph[1], pl[1]);
            pack_hi_lo(s[2 * kk + 1][0], s[2 * kk + 1][1], ph[2], pl[2]);
            pack_hi_lo(s[2 * kk + 1][2], s[2 * kk + 1][3], ph[3], pl[3]);
            #pragma unroll
            for (int g2 = 0; g2 < 4; g2++) {
                uint32_t rvh[4];
                ldsm4t(rvh, s2u(&sVh[(kk * 16 + lrow) * 72 + g2 * 16 + lcol]) + offKV);
                uint32_t bh0[2] = {rvh[0], rvh[1]}, bh1[2] = {rvh[2], rvh[3]};
                mma_f16(o[g2 * 2],     ph, bh0);
                mma_f16(o[g2 * 2],     pl, bh0);
                mma_f16(o[g2 * 2 + 1], ph, bh1);
                mma_f16(o[g2 * 2 + 1], pl, bh1);
            }
        }
    }

    int b = bh >> 4, hh = bh & 15;
    float inv0 = 1.0f / l_r[0];
    float inv1 = 1.0f / l_r[1];
    #pragma unroll
    for (int h2 = 0; h2 < 2; h2++) {
        int srow = q0 + w * 16 + gid + h2 * 8;
        float inv = h2 ? inv1 : inv0;
        size_t base = (((size_t)(b * SEQ + srow)) * HEADS + hh) * HD;
        #pragma unroll
        for (int j = 0; j < 8; j++) {
            float a = o[j][h2 * 2 + 0] * inv;
            float c = o[j][h2 * 2 + 1] * inv;
            uint32_t hi, lo;
            pack_hi_lo(a, c, hi, lo);
            int d = j * 8 + 2 * tig;
            *reinterpret_cast<uint32_t*>(&y_hi[base + d]) = hi;
            *reinterpret_cast<uint32_t*>(&y_lo[base + d]) = lo;
        }
    }
}

// ============================ launch ============================
extern "C" void kernel_launch(void* const* d_in, const int* in_sizes, int n_in,
                              void* d_out, int out_size)
{
    const float* x        = (const float*)d_in[0];
    const float* ln_scale = (const float*)d_in[2];
    const float* ln_bias  = (const float*)d_in[3];
    const float* w_qkv    = (const float*)d_in[4];
    const float* b_qkv    = (const float*)d_in[5];
    const float* w_out    = (const float*)d_in[6];
    const float* b_out    = (const float*)d_in[7];
    float* out = (float*)d_out;

    __half *xn_hi, *xn_lo, *wq_hi, *wo_hi, *y_hi, *y_lo;
    __half *qh, *ql, *kh, *vh;
    cudaGetSymbolAddress((void**)&xn_hi, g_xn_hi);
    cudaGetSymbolAddress((void**)&xn_lo, g_xn_lo);
    cudaGetSymbolAddress((void**)&wq_hi, g_wq_hi);
    cudaGetSymbolAddress((void**)&wo_hi, g_wo_hi);
    cudaGetSymbolAddress((void**)&y_hi,  g_y_hi);
    cudaGetSymbolAddress((void**)&y_lo,  g_y_lo);
    cudaGetSymbolAddress((void**)&qh, g_qh);
    cudaGetSymbolAddress((void**)&ql, g_ql);
    cudaGetSymbolAddress((void**)&kh, g_kh);
    cudaGetSymbolAddress((void**)&vh, g_vh);

    // 1. LayerNorm -> fp16 hi/lo
    ln_kernel<<<ROWS, 256>>>(x, ln_scale, ln_bias, xn_hi, xn_lo);

    // 1b. weight conversion (hi only)
    convert_kernel<<<512, 256>>>(w_qkv, wq_hi, DIM * QKV_N);
    convert_kernel<<<256, 256>>>(w_out, wo_hi, DIM * DIM);

    int gemm_smem = 3 * GSTAGE;   // 87552

    // 2. QKV projection (2-pass) -> q fp16 hi/lo, k/v fp16 hi (q pre-scaled)
    {
        cudaFuncSetAttribute(mma_gemm<0>,
                             cudaFuncAttributeMaxDynamicSharedMemorySize, gemm_smem);
        dim3 grid(QKV_N / 128, ROWS / 128);  // (24, 64)
        mma_gemm<0><<<grid, 256, gemm_smem>>>(xn_hi, xn_lo, wq_hi, b_qkv, nullptr,
                                              ROWS, QKV_N, DIM, qh, ql, kh, vh);
    }

    // 3. tensor-core causal flash attention (2-pass QK, 2-pass PV)
    {
        int smem = (2 * 128 * 72 + 4 * KVSTRIDE) * sizeof(__half);  // 73728
        cudaFuncSetAttribute(attn_mma_kernel,
                             cudaFuncAttributeMaxDynamicSharedMemorySize, smem);
        dim3 grid(BATCH * HEADS, SEQ / 128);  // (64, 16)
        attn_mma_kernel<<<grid, 256, smem>>>(qh, ql, kh, vh, y_hi, y_lo);
    }

    // 4. output projection (2-pass) -> d_out
    {
        cudaFuncSetAttribute(mma_gemm<1>,
                             cudaFuncAttributeMaxDynamicSharedMemorySize, gemm_smem);
        dim3 grid(DIM / 128, ROWS / 128);    // (8, 64)
        mma_gemm<1><<<grid, 256, gemm_smem>>>(y_hi, y_lo, wo_hi, b_out, out,
                                              ROWS, DIM, DIM,
                                              nullptr, nullptr, nullptr, nullptr);
    }
}

// round 9
// speedup vs baseline: 4.6604x; 1.1970x over previous
#include <cuda_runtime.h>
#include <cuda_fp16.h>
#include <cstdint>

// Problem constants
#define BATCH 4
#define SEQ   2048
#define DIM   1024
#define HEADS 16
#define HD    64
#define ROWS  (BATCH * SEQ)          // 8192
#define QKV_N (HEADS * 3 * HD)       // 3072
#define BHSD  (BATCH * HEADS * SEQ * HD)

// -------- scratch (static device globals; no allocation allowed) --------
__device__ __half g_xn_hi[ROWS * DIM];
__device__ __half g_wq_hi[DIM * QKV_N];
__device__ __half g_wo_hi[DIM * DIM];
__device__ __half g_qh[BHSD];   // [b,h,s,d] fp16 hi/lo (q compensated for QK)
__device__ __half g_ql[BHSD];
__device__ __half g_kh[BHSD];   // hi only
__device__ __half g_vh[BHSD];   // hi only
__device__ __half g_y_hi[ROWS * DIM];   // attn out [b,s,h,d], hi only

// ============================ helpers ============================
__device__ __forceinline__ uint32_t s2u(const void* p) {
    return (uint32_t)__cvta_generic_to_shared(p);
}
__device__ __forceinline__ void ldsm4(uint32_t* r, uint32_t addr) {
    asm volatile("ldmatrix.sync.aligned.m8n8.x4.shared.b16 {%0,%1,%2,%3}, [%4];\n"
                 : "=r"(r[0]), "=r"(r[1]), "=r"(r[2]), "=r"(r[3]) : "r"(addr));
}
__device__ __forceinline__ void ldsm4t(uint32_t* r, uint32_t addr) {
    asm volatile("ldmatrix.sync.aligned.m8n8.x4.trans.shared.b16 {%0,%1,%2,%3}, [%4];\n"
                 : "=r"(r[0]), "=r"(r[1]), "=r"(r[2]), "=r"(r[3]) : "r"(addr));
}
__device__ __forceinline__ void mma_f16(float* c, const uint32_t* a, const uint32_t* b) {
    asm volatile(
        "mma.sync.aligned.m16n8k16.row.col.f32.f16.f16.f32 "
        "{%0,%1,%2,%3}, {%4,%5,%6,%7}, {%8,%9}, {%0,%1,%2,%3};\n"
        : "+f"(c[0]), "+f"(c[1]), "+f"(c[2]), "+f"(c[3])
        : "r"(a[0]), "r"(a[1]), "r"(a[2]), "r"(a[3]), "r"(b[0]), "r"(b[1]));
}
__device__ __forceinline__ void cp16(uint32_t smem_dst, const void* gmem_src) {
    asm volatile("cp.async.cg.shared.global [%0], [%1], 16;\n"
                 :: "r"(smem_dst), "l"(gmem_src));
}
__device__ __forceinline__ void cp_commit() {
    asm volatile("cp.async.commit_group;\n");
}
template <int N>
__device__ __forceinline__ void cp_wait() {
    asm volatile("cp.async.wait_group %0;\n" :: "n"(N));
}
__device__ __forceinline__ void pack_hi_lo(float a, float b, uint32_t& hi, uint32_t& lo) {
    __half2 h2 = __floats2half2_rn(a, b);     // low = a
    float ra = a - __low2float(h2);
    float rb = b - __high2float(h2);
    __half2 l2 = __floats2half2_rn(ra, rb);
    hi = *reinterpret_cast<uint32_t*>(&h2);
    lo = *reinterpret_cast<uint32_t*>(&l2);
}
// fast exp on FMA pipe (no MUFU). valid for x <= 0.
__device__ __forceinline__ float fast_exp(float x) {
    float t = x * 1.4426950408889634f;
    t = fmaxf(t, -126.0f);
    float fi = rintf(t);
    float g = (t - fi) * 0.6931471805599453f;
    float p = 8.3333333e-3f;
    p = fmaf(p, g, 4.1666667e-2f);
    p = fmaf(p, g, 0.16666667f);
    p = fmaf(p, g, 0.5f);
    p = fmaf(p, g, 1.0f);
    p = fmaf(p, g, 1.0f);
    int ei = (int)fi;
    float sc = __int_as_float((ei + 127) << 23);
    return sc * p;
}

// ============================ LayerNorm -> fp16 ============================
__global__ void __launch_bounds__(256) ln_kernel(
    const float* __restrict__ x,
    const float* __restrict__ gamma,
    const float* __restrict__ beta,
    __half* __restrict__ out_hi)
{
    int row = blockIdx.x;
    int t = threadIdx.x;
    const float4* xr = reinterpret_cast<const float4*>(x + (size_t)row * DIM);
    float4 v = xr[t];
    float s1 = v.x + v.y + v.z + v.w;
    float s2 = v.x*v.x + v.y*v.y + v.z*v.z + v.w*v.w;
    #pragma unroll
    for (int o = 16; o > 0; o >>= 1) {
        s1 += __shfl_xor_sync(0xffffffffu, s1, o);
        s2 += __shfl_xor_sync(0xffffffffu, s2, o);
    }
    __shared__ float r1[8], r2[8];
    __shared__ float sh_mu, sh_rstd;
    if ((t & 31) == 0) { r1[t >> 5] = s1; r2[t >> 5] = s2; }
    __syncthreads();
    if (t == 0) {
        float a = 0.f, b = 0.f;
        #pragma unroll
        for (int i = 0; i < 8; i++) { a += r1[i]; b += r2[i]; }
        float mu  = a * (1.0f / DIM);
        float var = b * (1.0f / DIM) - mu * mu;
        sh_mu = mu;
        sh_rstd = rsqrtf(var + 1e-6f);
    }
    __syncthreads();
    float mu = sh_mu, rstd = sh_rstd;
    float4 g = reinterpret_cast<const float4*>(gamma)[t];
    float4 b4 = reinterpret_cast<const float4*>(beta)[t];
    float o0 = (v.x - mu) * rstd * g.x + b4.x;
    float o1 = (v.y - mu) * rstd * g.y + b4.y;
    float o2 = (v.z - mu) * rstd * g.z + b4.z;
    float o3 = (v.w - mu) * rstd * g.w + b4.w;
    __half2 ha = __floats2half2_rn(o0, o1);
    __half2 hb = __floats2half2_rn(o2, o3);
    size_t base = (size_t)row * DIM + t * 4;
    *reinterpret_cast<__half2*>(&out_hi[base])     = ha;
    *reinterpret_cast<__half2*>(&out_hi[base + 2]) = hb;
}

// ============================ fp32 -> fp16 convert (weights) ============================
__global__ void __launch_bounds__(256) convert_kernel(
    const float* __restrict__ w,
    __half* __restrict__ hi,
    int n)
{
    int i = blockIdx.x * blockDim.x + threadIdx.x;
    int stride = gridDim.x * blockDim.x;
    for (; i < n; i += stride)
        hi[i] = __float2half_rn(w[i]);
}

// ============================ fp16 single-pass MMA GEMM 128x128, 32-K slices, 3-stage ============================
// C = A @ B (+ bias). Warp tile 32x64 (4x2 layout).
// MODE 0: QKV — scatter fp16 into q (hi+lo), k (hi), v (hi) with q-scale.
// MODE 1: fp32 C.
#define GA_STRIDE 40                        // halves per A row (32 data + 8 pad)
#define GB_STRIDE 136                       // halves per B row (128 data + 8 pad)
#define GA_BYTES  (128 * GA_STRIDE * 2)     // 10240
#define GB_BYTES  (32 * GB_STRIDE * 2)      // 8704
#define GSTAGE    (GA_BYTES + GB_BYTES)     // 18944
#define G_OFF_B   GA_BYTES
template <int MODE>
__global__ void __launch_bounds__(256, 2) mma_gemm(
    const __half* __restrict__ Ag,
    const __half* __restrict__ Bg,
    const float* __restrict__ bias,
    float* __restrict__ Cout,
    int M, int N, int K,
    __half* __restrict__ qh, __half* __restrict__ ql,
    __half* __restrict__ kh, __half* __restrict__ vh)
{
    extern __shared__ __align__(16) char smem[];
    uint32_t smem_base = s2u(smem);

    int tid = threadIdx.x;
    int lane = tid & 31;
    int wid = tid >> 5;
    int wm = wid & 3;          // warp row (0..3) -> 32 rows each
    int wn = wid >> 2;         // warp col (0..1) -> 64 cols each
    int m0 = blockIdx.y * 128;
    int n0 = blockIdx.x * 128;

    int arow = tid >> 1;
    int acol = (tid & 1) * 16;       // halves
    int brow = tid >> 3;             // 0..31
    int bcol = (tid & 7) * 16;       // halves

    const __half* pA = Ag + (size_t)(m0 + arow) * K + acol;
    const __half* pB = Bg + (size_t)brow * N + n0 + bcol;
    uint32_t aoff = (arow * GA_STRIDE + acol) * 2;
    uint32_t boff = (brow * GB_STRIDE + bcol) * 2;

    float acc[2][8][4];
    #pragma unroll
    for (int i = 0; i < 2; i++)
        #pragma unroll
        for (int j = 0; j < 8; j++)
            #pragma unroll
            for (int e = 0; e < 4; e++) acc[i][j][e] = 0.f;

    int niter = K / 32;

    auto issue = [&](int kt, int s) {
        uint32_t st = smem_base + s * GSTAGE;
        int ko = kt * 32;
        const __half* a = pA + ko;
        const __half* b = pB + (size_t)ko * N;
        cp16(st + aoff,              a);
        cp16(st + aoff + 16,         a + 8);
        cp16(st + G_OFF_B + boff,      b);
        cp16(st + G_OFF_B + boff + 16, b + 8);
        cp_commit();
    };

    issue(0, 0);
    issue(1, 1);

    int lrow = lane & 15;
    int lcol = (lane >> 4) * 8;
    uint32_t baseA[2];
    #pragma unroll
    for (int i = 0; i < 2; i++)
        baseA[i] = smem_base + ((wm * 32 + i * 16 + lrow) * GA_STRIDE + lcol) * 2;
    uint32_t baseB[4];
    #pragma unroll
    for (int jj = 0; jj < 4; jj++)
        baseB[jj] = smem_base + G_OFF_B + (lrow * GB_STRIDE + wn * 64 + jj * 16 + lcol) * 2;

    int s = 0;
    for (int kt = 0; kt < niter; kt++) {
        if (kt + 1 < niter) cp_wait<1>();
        else                cp_wait<0>();
        __syncthreads();

        if (kt + 2 < niter) {
            int s2 = s + 2; if (s2 >= 3) s2 -= 3;
            issue(kt + 2, s2);
        }

        uint32_t offS = (uint32_t)(s * GSTAGE);
        #pragma unroll
        for (int ss = 0; ss < 2; ss++) {
            uint32_t aSub = offS + ss * 32;                       // +16 halves
            uint32_t bSub = offS + ss * 16 * GB_STRIDE * 2;       // +16 rows

            uint32_t ah[2][4], bb[8][2];
            #pragma unroll
            for (int i = 0; i < 2; i++)
                ldsm4(ah[i], baseA[i] + aSub);
            #pragma unroll
            for (int jj = 0; jj < 4; jj++) {
                uint32_t r[4];
                ldsm4t(r, baseB[jj] + bSub);
                bb[jj * 2][0] = r[0]; bb[jj * 2][1] = r[1];
                bb[jj * 2 + 1][0] = r[2]; bb[jj * 2 + 1][1] = r[3];
            }
            #pragma unroll
            for (int i = 0; i < 2; i++)
                #pragma unroll
                for (int j = 0; j < 8; j++)
                    mma_f16(acc[i][j], ah[i], bb[j]);
        }
        s++; if (s == 3) s = 0;
    }

    int gid = lane >> 2, tig = lane & 3;
    #pragma unroll
    for (int i = 0; i < 2; i++) {
        #pragma unroll
        for (int j = 0; j < 8; j++) {
            int n = n0 + wn * 64 + j * 8 + 2 * tig;
            if (MODE == 0) {
                int hq = n / 192;
                int f = n - hq * 192;
                #pragma unroll
                for (int rh = 0; rh < 2; rh++) {
                    int m = m0 + wm * 32 + i * 16 + gid + rh * 8;
                    float v0 = acc[i][j][rh * 2 + 0] + bias[n];
                    float v1 = acc[i][j][rh * 2 + 1] + bias[n + 1];
                    int bb2 = m >> 11;
                    int ss2 = m & 2047;
                    size_t base = (((size_t)(bb2 * HEADS + hq)) * SEQ + ss2) * HD;
                    if (f < 64) {
                        v0 *= 0.125f; v1 *= 0.125f;
                        uint32_t hi, lo;
                        pack_hi_lo(v0, v1, hi, lo);
                        *reinterpret_cast<uint32_t*>(&qh[base + f]) = hi;
                        *reinterpret_cast<uint32_t*>(&ql[base + f]) = lo;
                    } else if (f < 128) {
                        __half2 h2 = __floats2half2_rn(v0, v1);
                        *reinterpret_cast<uint32_t*>(&kh[base + f - 64]) =
                            *reinterpret_cast<uint32_t*>(&h2);
                    } else {
                        __half2 h2 = __floats2half2_rn(v0, v1);
                        *reinterpret_cast<uint32_t*>(&vh[base + f - 128]) =
                            *reinterpret_cast<uint32_t*>(&h2);
                    }
                }
            } else {
                #pragma unroll
                for (int rh = 0; rh < 2; rh++) {
                    int m = m0 + wm * 32 + i * 16 + gid + rh * 8;
                    float v0 = acc[i][j][rh * 2 + 0] + bias[n];
                    float v1 = acc[i][j][rh * 2 + 1] + bias[n + 1];
                    *reinterpret_cast<float2*>(&Cout[(size_t)m * N + n]) = make_float2(v0, v1);
                }
            }
        }
    }
}

// ============================ Tensor-core flash attention (2-pass QK, 2-pass PV) ============================
#define KVSTRIDE (64 * 72)
__global__ void __launch_bounds__(256) attn_mma_kernel(
    const __half* __restrict__ qh_g, const __half* __restrict__ ql_g,
    const __half* __restrict__ kh_g,
    const __half* __restrict__ vh_g,
    __half* __restrict__ y_hi)
{
    extern __shared__ __half smb[];
    __half* sQh = smb;                      // [128][72]
    __half* sQl = sQh + 128 * 72;
    __half* sKh = sQl + 128 * 72;           // [2][64][72]
    __half* sVh = sKh + 2 * KVSTRIDE;       // [2][64][72]

    int bh = blockIdx.x;
    int qt = (gridDim.y - 1) - blockIdx.y;   // heavy tiles first
    int tid = threadIdx.x;
    int lane = tid & 31;
    int w = tid >> 5;
    int gid = lane >> 2, tig = lane & 3;
    int lrow = lane & 15, lcol = (lane >> 4) * 8;

    int q0 = qt * 128;
    const size_t bhoff = (size_t)bh * SEQ * HD;

    int kvr = tid >> 3;
    int kvd = (tid & 7) * 8;
    auto issue_kv = [&](int kt, int st) {
        int c0 = kt * 64;
        size_t base = st * KVSTRIDE;
        #pragma unroll
        for (int i = 0; i < 2; i++) {
            int r = kvr + i * 32;
            size_t g = bhoff + (size_t)(c0 + r) * HD + kvd;
            size_t sm = base + r * 72 + kvd;
            cp16(s2u(&sKh[sm]), &kh_g[g]);
            cp16(s2u(&sVh[sm]), &vh_g[g]);
        }
        cp_commit();
    };

    int ktmax = 2 * qt + 1;
    issue_kv(0, 0);

    #pragma unroll
    for (int i = 0; i < 4; i++) {
        int chunk = tid + i * 256;
        int r = chunk >> 3, d8 = (chunk & 7) * 8;
        size_t g = bhoff + (size_t)(q0 + r) * HD + d8;
        *reinterpret_cast<uint4*>(&sQh[r * 72 + d8]) = *reinterpret_cast<const uint4*>(&qh_g[g]);
        *reinterpret_cast<uint4*>(&sQl[r * 72 + d8]) = *reinterpret_cast<const uint4*>(&ql_g[g]);
    }
    __syncthreads();

    uint32_t qfh[4][4], qfl[4][4];
    #pragma unroll
    for (int kk = 0; kk < 4; kk++) {
        ldsm4(qfh[kk], s2u(&sQh[(w * 16 + lrow) * 72 + kk * 16 + lcol]));
        ldsm4(qfl[kk], s2u(&sQl[(w * 16 + lrow) * 72 + kk * 16 + lcol]));
    }

    float m_r[2] = {-1e30f, -1e30f};
    float l_r[2] = {0.f, 0.f};
    float o[8][4];
    #pragma unroll
    for (int j = 0; j < 8; j++)
        #pragma unroll
        for (int c = 0; c < 4; c++) o[j][c] = 0.f;

    for (int kt = 0; kt <= ktmax; kt++) {
        int c0 = kt * 64;
        int st = kt & 1;
        uint32_t offKV = (uint32_t)(st * KVSTRIDE * 2);

        cp_wait<0>();
        __syncthreads();   // stage st ready; all warps done reading the other stage

        if (kt < ktmax) issue_kv(kt + 1, (kt + 1) & 1);

        float s[8][4];
        #pragma unroll
        for (int j = 0; j < 8; j++)
            #pragma unroll
            for (int c = 0; c < 4; c++) s[j][c] = 0.f;

        #pragma unroll
        for (int kk = 0; kk < 4; kk++) {
            #pragma unroll
            for (int g2 = 0; g2 < 4; g2++) {
                uint32_t rh[4];
                ldsm4(rh, s2u(&sKh[(g2 * 16 + lrow) * 72 + kk * 16 + lcol]) + offKV);
                uint32_t b0h[2] = {rh[0], rh[2]}, b1h[2] = {rh[1], rh[3]};
                mma_f16(s[g2 * 2],     qfh[kk], b0h);
                mma_f16(s[g2 * 2],     qfl[kk], b0h);
                mma_f16(s[g2 * 2 + 1], qfh[kk], b1h);
                mma_f16(s[g2 * 2 + 1], qfl[kk], b1h);
            }
        }

        if (kt >= 2 * qt) {
            int row0 = q0 + w * 16 + gid;
            #pragma unroll
            for (int j = 0; j < 8; j++) {
                int col = c0 + j * 8 + 2 * tig;
                if (col     > row0)     s[j][0] = -1e30f;
                if (col + 1 > row0)     s[j][1] = -1e30f;
                if (col     > row0 + 8) s[j][2] = -1e30f;
                if (col + 1 > row0 + 8) s[j][3] = -1e30f;
            }
        }

        float mx0 = -1e30f, mx1 = -1e30f;
        #pragma unroll
        for (int j = 0; j < 8; j++) {
            mx0 = fmaxf(mx0, fmaxf(s[j][0], s[j][1]));
            mx1 = fmaxf(mx1, fmaxf(s[j][2], s[j][3]));
        }
        mx0 = fmaxf(mx0, __shfl_xor_sync(0xffffffffu, mx0, 1));
        mx0 = fmaxf(mx0, __shfl_xor_sync(0xffffffffu, mx0, 2));
        mx1 = fmaxf(mx1, __shfl_xor_sync(0xffffffffu, mx1, 1));
        mx1 = fmaxf(mx1, __shfl_xor_sync(0xffffffffu, mx1, 2));
        float mn0 = fmaxf(m_r[0], mx0);
        float mn1 = fmaxf(m_r[1], mx1);
        float corr0 = fast_exp(m_r[0] - mn0);
        float corr1 = fast_exp(m_r[1] - mn1);
        float rs0 = 0.f, rs1 = 0.f;
        #pragma unroll
        for (int j = 0; j < 8; j++) {
            s[j][0] = fast_exp(s[j][0] - mn0); rs0 += s[j][0];
            s[j][1] = fast_exp(s[j][1] - mn0); rs0 += s[j][1];
            s[j][2] = fast_exp(s[j][2] - mn1); rs1 += s[j][2];
            s[j][3] = fast_exp(s[j][3] - mn1); rs1 += s[j][3];
        }
        rs0 += __shfl_xor_sync(0xffffffffu, rs0, 1);
        rs0 += __shfl_xor_sync(0xffffffffu, rs0, 2);
        rs1 += __shfl_xor_sync(0xffffffffu, rs1, 1);
        rs1 += __shfl_xor_sync(0xffffffffu, rs1, 2);
        l_r[0] = l_r[0] * corr0 + rs0;
        l_r[1] = l_r[1] * corr1 + rs1;
        m_r[0] = mn0; m_r[1] = mn1;
        #pragma unroll
        for (int j = 0; j < 8; j++) {
            o[j][0] *= corr0; o[j][1] *= corr0;
            o[j][2] *= corr1; o[j][3] *= corr1;
        }

        // ---- O += P V (2-pass: PhVh + PlVh) ----
        #pragma unroll
        for (int kk = 0; kk < 4; kk++) {
            uint32_t ph[4], pl[4];
            pack_hi_lo(s[2 * kk][0],     s[2 * kk][1],     ph[0], pl[0]);
            pack_hi_lo(s[2 * kk][2],     s[2 * kk][3],     ph[1], pl[1]);
            pack_hi_lo(s[2 * kk + 1][0], s[2 * kk + 1][1], ph[2], pl[2]);
            pack_hi_lo(s[2 * kk + 1][2], s[2 * kk + 1][3], ph[3], pl[3]);
            #pragma unroll
            for (int g2 = 0; g2 < 4; g2++) {
                uint32_t rvh[4];
                ldsm4t(rvh, s2u(&sVh[(kk * 16 + lrow) * 72 + g2 * 16 + lcol]) + offKV);
                uint32_t bh0[2] = {rvh[0], rvh[1]}, bh1[2] = {rvh[2], rvh[3]};
                mma_f16(o[g2 * 2],     ph, bh0);
                mma_f16(o[g2 * 2],     pl, bh0);
                mma_f16(o[g2 * 2 + 1], ph, bh1);
                mma_f16(o[g2 * 2 + 1], pl, bh1);
            }
        }
    }

    int b = bh >> 4, hh = bh & 15;
    float inv0 = 1.0f / l_r[0];
    float inv1 = 1.0f / l_r[1];
    #pragma unroll
    for (int h2 = 0; h2 < 2; h2++) {
        int srow = q0 + w * 16 + gid + h2 * 8;
        float inv = h2 ? inv1 : inv0;
        size_t base = (((size_t)(b * SEQ + srow)) * HEADS + hh) * HD;
        #pragma unroll
        for (int j = 0; j < 8; j++) {
            float a = o[j][h2 * 2 + 0] * inv;
            float c = o[j][h2 * 2 + 1] * inv;
            __half2 h2v = __floats2half2_rn(a, c);
            int d = j * 8 + 2 * tig;
            *reinterpret_cast<uint32_t*>(&y_hi[base + d]) = *reinterpret_cast<uint32_t*>(&h2v);
        }
    }
}

// ============================ launch ============================
extern "C" void kernel_launch(void* const* d_in, const int* in_sizes, int n_in,
                              void* d_out, int out_size)
{
    const float* x        = (const float*)d_in[0];
    const float* ln_scale = (const float*)d_in[2];
    const float* ln_bias  = (const float*)d_in[3];
    const float* w_qkv    = (const float*)d_in[4];
    const float* b_qkv    = (const float*)d_in[5];
    const float* w_out    = (const float*)d_in[6];
    const float* b_out    = (const float*)d_in[7];
    float* out = (float*)d_out;

    __half *xn_hi, *wq_hi, *wo_hi, *y_hi;
    __half *qh, *ql, *kh, *vh;
    cudaGetSymbolAddress((void**)&xn_hi, g_xn_hi);
    cudaGetSymbolAddress((void**)&wq_hi, g_wq_hi);
    cudaGetSymbolAddress((void**)&wo_hi, g_wo_hi);
    cudaGetSymbolAddress((void**)&y_hi,  g_y_hi);
    cudaGetSymbolAddress((void**)&qh, g_qh);
    cudaGetSymbolAddress((void**)&ql, g_ql);
    cudaGetSymbolAddress((void**)&kh, g_kh);
    cudaGetSymbolAddress((void**)&vh, g_vh);

    // 1. LayerNorm -> fp16
    ln_kernel<<<ROWS, 256>>>(x, ln_scale, ln_bias, xn_hi);

    // 1b. weight conversion
    convert_kernel<<<512, 256>>>(w_qkv, wq_hi, DIM * QKV_N);
    convert_kernel<<<256, 256>>>(w_out, wo_hi, DIM * DIM);

    int gemm_smem = 3 * GSTAGE;   // 56832

    // 2. QKV projection (single-pass fp16) -> q fp16 hi/lo, k/v fp16 (q pre-scaled)
    {
        cudaFuncSetAttribute(mma_gemm<0>,
                             cudaFuncAttributeMaxDynamicSharedMemorySize, gemm_smem);
        dim3 grid(QKV_N / 128, ROWS / 128);  // (24, 64)
        mma_gemm<0><<<grid, 256, gemm_smem>>>(xn_hi, wq_hi, b_qkv, nullptr,
                                              ROWS, QKV_N, DIM, qh, ql, kh, vh);
    }

    // 3. tensor-core causal flash attention (2-pass QK, 2-pass PV)
    {
        int smem = (2 * 128 * 72 + 4 * KVSTRIDE) * sizeof(__half);  // 73728
        cudaFuncSetAttribute(attn_mma_kernel,
                             cudaFuncAttributeMaxDynamicSharedMemorySize, smem);
        dim3 grid(BATCH * HEADS, SEQ / 128);  // (64, 16)
        attn_mma_kernel<<<grid, 256, smem>>>(qh, ql, kh, vh, y_hi);
    }

    // 4. output projection (single-pass fp16) -> d_out
    {
        cudaFuncSetAttribute(mma_gemm<1>,
                             cudaFuncAttributeMaxDynamicSharedMemorySize, gemm_smem);
        dim3 grid(DIM / 128, ROWS / 128);    // (8, 64)
        mma_gemm<1><<<grid, 256, gemm_smem>>>(y_hi, wo_hi, b_out, out,
                                              ROWS, DIM, DIM,
                                              nullptr, nullptr, nullptr, nullptr);
    }
}

// round 10
// speedup vs baseline: 5.0250x; 1.0782x over previous
#include <cuda_runtime.h>
#include <cuda_fp16.h>
#include <cstdint>

// Problem constants
#define BATCH 4
#define SEQ   2048
#define DIM   1024
#define HEADS 16
#define HD    64
#define ROWS  (BATCH * SEQ)          // 8192
#define QKV_N (HEADS * 3 * HD)       // 3072
#define BHSD  (BATCH * HEADS * SEQ * HD)

// -------- scratch (static device globals; no allocation allowed) --------
__device__ __half g_xn_hi[ROWS * DIM];
__device__ __half g_wq_hi[DIM * QKV_N];
__device__ __half g_wo_hi[DIM * DIM];
__device__ __half g_qh[BHSD];   // [b,h,s,d] fp16 hi/lo (q compensated for QK)
__device__ __half g_ql[BHSD];
__device__ __half g_kh[BHSD];   // hi only
__device__ __half g_vh[BHSD];   // hi only
__device__ __half g_y_hi[ROWS * DIM];   // attn out [b,s,h,d], hi only

// ============================ helpers ============================
__device__ __forceinline__ uint32_t s2u(const void* p) {
    return (uint32_t)__cvta_generic_to_shared(p);
}
__device__ __forceinline__ void ldsm4(uint32_t* r, uint32_t addr) {
    asm volatile("ldmatrix.sync.aligned.m8n8.x4.shared.b16 {%0,%1,%2,%3}, [%4];\n"
                 : "=r"(r[0]), "=r"(r[1]), "=r"(r[2]), "=r"(r[3]) : "r"(addr));
}
__device__ __forceinline__ void ldsm4t(uint32_t* r, uint32_t addr) {
    asm volatile("ldmatrix.sync.aligned.m8n8.x4.trans.shared.b16 {%0,%1,%2,%3}, [%4];\n"
                 : "=r"(r[0]), "=r"(r[1]), "=r"(r[2]), "=r"(r[3]) : "r"(addr));
}
__device__ __forceinline__ void mma_f16(float* c, const uint32_t* a, const uint32_t* b) {
    asm volatile(
        "mma.sync.aligned.m16n8k16.row.col.f32.f16.f16.f32 "
        "{%0,%1,%2,%3}, {%4,%5,%6,%7}, {%8,%9}, {%0,%1,%2,%3};\n"
        : "+f"(c[0]), "+f"(c[1]), "+f"(c[2]), "+f"(c[3])
        : "r"(a[0]), "r"(a[1]), "r"(a[2]), "r"(a[3]), "r"(b[0]), "r"(b[1]));
}
__device__ __forceinline__ void cp16(uint32_t smem_dst, const void* gmem_src) {
    asm volatile("cp.async.cg.shared.global [%0], [%1], 16;\n"
                 :: "r"(smem_dst), "l"(gmem_src));
}
__device__ __forceinline__ void cp_commit() {
    asm volatile("cp.async.commit_group;\n");
}
template <int N>
__device__ __forceinline__ void cp_wait() {
    asm volatile("cp.async.wait_group %0;\n" :: "n"(N));
}
__device__ __forceinline__ void pack_hi_lo(float a, float b, uint32_t& hi, uint32_t& lo) {
    __half2 h2 = __floats2half2_rn(a, b);     // low = a
    float ra = a - __low2float(h2);
    float rb = b - __high2float(h2);
    __half2 l2 = __floats2half2_rn(ra, rb);
    hi = *reinterpret_cast<uint32_t*>(&h2);
    lo = *reinterpret_cast<uint32_t*>(&l2);
}
// fast exp on FMA pipe (no MUFU). valid for x <= 0.
__device__ __forceinline__ float fast_exp(float x) {
    float t = x * 1.4426950408889634f;
    t = fmaxf(t, -126.0f);
    float fi = rintf(t);
    float g = (t - fi) * 0.6931471805599453f;
    float p = 8.3333333e-3f;
    p = fmaf(p, g, 4.1666667e-2f);
    p = fmaf(p, g, 0.16666667f);
    p = fmaf(p, g, 0.5f);
    p = fmaf(p, g, 1.0f);
    p = fmaf(p, g, 1.0f);
    int ei = (int)fi;
    float sc = __int_as_float((ei + 127) << 23);
    return sc * p;
}

// ============================ LayerNorm -> fp16 ============================
__global__ void __launch_bounds__(256) ln_kernel(
    const float* __restrict__ x,
    const float* __restrict__ gamma,
    const float* __restrict__ beta,
    __half* __restrict__ out_hi)
{
    int row = blockIdx.x;
    int t = threadIdx.x;
    const float4* xr = reinterpret_cast<const float4*>(x + (size_t)row * DIM);
    float4 v = xr[t];
    float s1 = v.x + v.y + v.z + v.w;
    float s2 = v.x*v.x + v.y*v.y + v.z*v.z + v.w*v.w;
    #pragma unroll
    for (int o = 16; o > 0; o >>= 1) {
        s1 += __shfl_xor_sync(0xffffffffu, s1, o);
        s2 += __shfl_xor_sync(0xffffffffu, s2, o);
    }
    __shared__ float r1[8], r2[8];
    __shared__ float sh_mu, sh_rstd;
    if ((t & 31) == 0) { r1[t >> 5] = s1; r2[t >> 5] = s2; }
    __syncthreads();
    if (t == 0) {
        float a = 0.f, b = 0.f;
        #pragma unroll
        for (int i = 0; i < 8; i++) { a += r1[i]; b += r2[i]; }
        float mu  = a * (1.0f / DIM);
        float var = b * (1.0f / DIM) - mu * mu;
        sh_mu = mu;
        sh_rstd = rsqrtf(var + 1e-6f);
    }
    __syncthreads();
    float mu = sh_mu, rstd = sh_rstd;
    float4 g = reinterpret_cast<const float4*>(gamma)[t];
    float4 b4 = reinterpret_cast<const float4*>(beta)[t];
    float o0 = (v.x - mu) * rstd * g.x + b4.x;
    float o1 = (v.y - mu) * rstd * g.y + b4.y;
    float o2 = (v.z - mu) * rstd * g.z + b4.z;
    float o3 = (v.w - mu) * rstd * g.w + b4.w;
    __half2 ha = __floats2half2_rn(o0, o1);
    __half2 hb = __floats2half2_rn(o2, o3);
    size_t base = (size_t)row * DIM + t * 4;
    *reinterpret_cast<__half2*>(&out_hi[base])     = ha;
    *reinterpret_cast<__half2*>(&out_hi[base + 2]) = hb;
}

// ============================ fp32 -> fp16 convert (weights) ============================
__global__ void __launch_bounds__(256) convert_kernel(
    const float* __restrict__ w,
    __half* __restrict__ hi,
    int n)
{
    int i = blockIdx.x * blockDim.x + threadIdx.x;
    int stride = gridDim.x * blockDim.x;
    for (; i < n; i += stride)
        hi[i] = __float2half_rn(w[i]);
}

// ============================ fp16 single-pass MMA GEMM 128x128, 32-K slices, 3-stage ============================
// C = A @ B (+ bias). Warp tile 32x64 (4x2 layout).
// MODE 0: QKV — scatter fp16 into q (hi+lo), k (hi), v (hi) with q-scale.
// MODE 1: fp32 C.
#define GA_STRIDE 40                        // halves per A row (32 data + 8 pad)
#define GB_STRIDE 136                       // halves per B row (128 data + 8 pad)
#define GA_BYTES  (128 * GA_STRIDE * 2)     // 10240
#define GB_BYTES  (32 * GB_STRIDE * 2)      // 8704
#define GSTAGE    (GA_BYTES + GB_BYTES)     // 18944
#define G_OFF_B   GA_BYTES
template <int MODE>
__global__ void __launch_bounds__(256, 2) mma_gemm(
    const __half* __restrict__ Ag,
    const __half* __restrict__ Bg,
    const float* __restrict__ bias,
    float* __restrict__ Cout,
    int M, int N, int K,
    __half* __restrict__ qh, __half* __restrict__ ql,
    __half* __restrict__ kh, __half* __restrict__ vh)
{
    extern __shared__ __align__(16) char smem[];
    uint32_t smem_base = s2u(smem);

    int tid = threadIdx.x;
    int lane = tid & 31;
    int wid = tid >> 5;
    int wm = wid & 3;          // warp row (0..3) -> 32 rows each
    int wn = wid >> 2;         // warp col (0..1) -> 64 cols each
    int m0 = blockIdx.y * 128;
    int n0 = blockIdx.x * 128;

    int arow = tid >> 1;
    int acol = (tid & 1) * 16;       // halves
    int brow = tid >> 3;             // 0..31
    int bcol = (tid & 7) * 16;       // halves

    const __half* pA = Ag + (size_t)(m0 + arow) * K + acol;
    const __half* pB = Bg + (size_t)brow * N + n0 + bcol;
    uint32_t aoff = (arow * GA_STRIDE + acol) * 2;
    uint32_t boff = (brow * GB_STRIDE + bcol) * 2;

    float acc[2][8][4];
    #pragma unroll
    for (int i = 0; i < 2; i++)
        #pragma unroll
        for (int j = 0; j < 8; j++)
            #pragma unroll
            for (int e = 0; e < 4; e++) acc[i][j][e] = 0.f;

    int niter = K / 32;

    auto issue = [&](int kt, int s) {
        uint32_t st = smem_base + s * GSTAGE;
        int ko = kt * 32;
        const __half* a = pA + ko;
        const __half* b = pB + (size_t)ko * N;
        cp16(st + aoff,              a);
        cp16(st + aoff + 16,         a + 8);
        cp16(st + G_OFF_B + boff,      b);
        cp16(st + G_OFF_B + boff + 16, b + 8);
        cp_commit();
    };

    issue(0, 0);
    issue(1, 1);

    int lrow = lane & 15;
    int lcol = (lane >> 4) * 8;
    uint32_t baseA[2];
    #pragma unroll
    for (int i = 0; i < 2; i++)
        baseA[i] = smem_base + ((wm * 32 + i * 16 + lrow) * GA_STRIDE + lcol) * 2;
    uint32_t baseB[4];
    #pragma unroll
    for (int jj = 0; jj < 4; jj++)
        baseB[jj] = smem_base + G_OFF_B + (lrow * GB_STRIDE + wn * 64 + jj * 16 + lcol) * 2;

    int s = 0;
    for (int kt = 0; kt < niter; kt++) {
        if (kt + 1 < niter) cp_wait<1>();
        else                cp_wait<0>();
        __syncthreads();

        if (kt + 2 < niter) {
            int s2 = s + 2; if (s2 >= 3) s2 -= 3;
            issue(kt + 2, s2);
        }

        uint32_t offS = (uint32_t)(s * GSTAGE);
        #pragma unroll
        for (int ss = 0; ss < 2; ss++) {
            uint32_t aSub = offS + ss * 32;                       // +16 halves
            uint32_t bSub = offS + ss * 16 * GB_STRIDE * 2;       // +16 rows

            uint32_t ah[2][4], bb[8][2];
            #pragma unroll
            for (int i = 0; i < 2; i++)
                ldsm4(ah[i], baseA[i] + aSub);
            #pragma unroll
            for (int jj = 0; jj < 4; jj++) {
                uint32_t r[4];
                ldsm4t(r, baseB[jj] + bSub);
                bb[jj * 2][0] = r[0]; bb[jj * 2][1] = r[1];
                bb[jj * 2 + 1][0] = r[2]; bb[jj * 2 + 1][1] = r[3];
            }
            #pragma unroll
            for (int i = 0; i < 2; i++)
                #pragma unroll
                for (int j = 0; j < 8; j++)
                    mma_f16(acc[i][j], ah[i], bb[j]);
        }
        s++; if (s == 3) s = 0;
    }

    int gid = lane >> 2, tig = lane & 3;
    #pragma unroll
    for (int i = 0; i < 2; i++) {
        #pragma unroll
        for (int j = 0; j < 8; j++) {
            int n = n0 + wn * 64 + j * 8 + 2 * tig;
            if (MODE == 0) {
                int hq = n / 192;
                int f = n - hq * 192;
                #pragma unroll
                for (int rh = 0; rh < 2; rh++) {
                    int m = m0 + wm * 32 + i * 16 + gid + rh * 8;
                    float v0 = acc[i][j][rh * 2 + 0] + bias[n];
                    float v1 = acc[i][j][rh * 2 + 1] + bias[n + 1];
                    int bb2 = m >> 11;
                    int ss2 = m & 2047;
                    size_t base = (((size_t)(bb2 * HEADS + hq)) * SEQ + ss2) * HD;
                    if (f < 64) {
                        v0 *= 0.125f; v1 *= 0.125f;
                        uint32_t hi, lo;
                        pack_hi_lo(v0, v1, hi, lo);
                        *reinterpret_cast<uint32_t*>(&qh[base + f]) = hi;
                        *reinterpret_cast<uint32_t*>(&ql[base + f]) = lo;
                    } else if (f < 128) {
                        __half2 h2 = __floats2half2_rn(v0, v1);
                        *reinterpret_cast<uint32_t*>(&kh[base + f - 64]) =
                            *reinterpret_cast<uint32_t*>(&h2);
                    } else {
                        __half2 h2 = __floats2half2_rn(v0, v1);
                        *reinterpret_cast<uint32_t*>(&vh[base + f - 128]) =
                            *reinterpret_cast<uint32_t*>(&h2);
                    }
                }
            } else {
                #pragma unroll
                for (int rh = 0; rh < 2; rh++) {
                    int m = m0 + wm * 32 + i * 16 + gid + rh * 8;
                    float v0 = acc[i][j][rh * 2 + 0] + bias[n];
                    float v1 = acc[i][j][rh * 2 + 1] + bias[n + 1];
                    *reinterpret_cast<float2*>(&Cout[(size_t)m * N + n]) = make_float2(v0, v1);
                }
            }
        }
    }
}

// ============================ Tensor-core flash attention (2-pass QK, 1-pass PV) ============================
#define KVSTRIDE (64 * 72)
__global__ void __launch_bounds__(256) attn_mma_kernel(
    const __half* __restrict__ qh_g, const __half* __restrict__ ql_g,
    const __half* __restrict__ kh_g,
    const __half* __restrict__ vh_g,
    __half* __restrict__ y_hi)
{
    extern __shared__ __half smb[];
    __half* sQh = smb;                      // [128][72]
    __half* sQl = sQh + 128 * 72;
    __half* sKh = sQl + 128 * 72;           // [2][64][72]
    __half* sVh = sKh + 2 * KVSTRIDE;       // [2][64][72]

    int bh = blockIdx.x;
    int qt = (gridDim.y - 1) - blockIdx.y;   // heavy tiles first
    int tid = threadIdx.x;
    int lane = tid & 31;
    int w = tid >> 5;
    int gid = lane >> 2, tig = lane & 3;
    int lrow = lane & 15, lcol = (lane >> 4) * 8;

    int q0 = qt * 128;
    const size_t bhoff = (size_t)bh * SEQ * HD;

    int kvr = tid >> 3;
    int kvd = (tid & 7) * 8;
    auto issue_kv = [&](int kt, int st) {
        int c0 = kt * 64;
        size_t base = st * KVSTRIDE;
        #pragma unroll
        for (int i = 0; i < 2; i++) {
            int r = kvr + i * 32;
            size_t g = bhoff + (size_t)(c0 + r) * HD + kvd;
            size_t sm = base + r * 72 + kvd;
            cp16(s2u(&sKh[sm]), &kh_g[g]);
            cp16(s2u(&sVh[sm]), &vh_g[g]);
        }
        cp_commit();
    };

    int ktmax = 2 * qt + 1;
    issue_kv(0, 0);

    #pragma unroll
    for (int i = 0; i < 4; i++) {
        int chunk = tid + i * 256;
        int r = chunk >> 3, d8 = (chunk & 7) * 8;
        size_t g = bhoff + (size_t)(q0 + r) * HD + d8;
        *reinterpret_cast<uint4*>(&sQh[r * 72 + d8]) = *reinterpret_cast<const uint4*>(&qh_g[g]);
        *reinterpret_cast<uint4*>(&sQl[r * 72 + d8]) = *reinterpret_cast<const uint4*>(&ql_g[g]);
    }
    __syncthreads();

    uint32_t qfh[4][4], qfl[4][4];
    #pragma unroll
    for (int kk = 0; kk < 4; kk++) {
        ldsm4(qfh[kk], s2u(&sQh[(w * 16 + lrow) * 72 + kk * 16 + lcol]));
        ldsm4(qfl[kk], s2u(&sQl[(w * 16 + lrow) * 72 + kk * 16 + lcol]));
    }

    float m_r[2] = {-1e30f, -1e30f};
    float l_r[2] = {0.f, 0.f};
    float o[8][4];
    #pragma unroll
    for (int j = 0; j < 8; j++)
        #pragma unroll
        for (int c = 0; c < 4; c++) o[j][c] = 0.f;

    for (int kt = 0; kt <= ktmax; kt++) {
        int c0 = kt * 64;
        int st = kt & 1;
        uint32_t offKV = (uint32_t)(st * KVSTRIDE * 2);

        cp_wait<0>();
        __syncthreads();   // stage st ready; all warps done reading the other stage

        if (kt < ktmax) issue_kv(kt + 1, (kt + 1) & 1);

        float s[8][4];
        #pragma unroll
        for (int j = 0; j < 8; j++)
            #pragma unroll
            for (int c = 0; c < 4; c++) s[j][c] = 0.f;

        #pragma unroll
        for (int kk = 0; kk < 4; kk++) {
            #pragma unroll
            for (int g2 = 0; g2 < 4; g2++) {
                uint32_t rh[4];
                ldsm4(rh, s2u(&sKh[(g2 * 16 + lrow) * 72 + kk * 16 + lcol]) + offKV);
                uint32_t b0h[2] = {rh[0], rh[2]}, b1h[2] = {rh[1], rh[3]};
                mma_f16(s[g2 * 2],     qfh[kk], b0h);
                mma_f16(s[g2 * 2],     qfl[kk], b0h);
                mma_f16(s[g2 * 2 + 1], qfh[kk], b1h);
                mma_f16(s[g2 * 2 + 1], qfl[kk], b1h);
            }
        }

        if (kt >= 2 * qt) {
            int row0 = q0 + w * 16 + gid;
            #pragma unroll
            for (int j = 0; j < 8; j++) {
                int col = c0 + j * 8 + 2 * tig;
                if (col     > row0)     s[j][0] = -1e30f;
                if (col + 1 > row0)     s[j][1] = -1e30f;
                if (col     > row0 + 8) s[j][2] = -1e30f;
                if (col + 1 > row0 + 8) s[j][3] = -1e30f;
            }
        }

        float mx0 = -1e30f, mx1 = -1e30f;
        #pragma unroll
        for (int j = 0; j < 8; j++) {
            mx0 = fmaxf(mx0, fmaxf(s[j][0], s[j][1]));
            mx1 = fmaxf(mx1, fmaxf(s[j][2], s[j][3]));
        }
        mx0 = fmaxf(mx0, __shfl_xor_sync(0xffffffffu, mx0, 1));
        mx0 = fmaxf(mx0, __shfl_xor_sync(0xffffffffu, mx0, 2));
        mx1 = fmaxf(mx1, __shfl_xor_sync(0xffffffffu, mx1, 1));
        mx1 = fmaxf(mx1, __shfl_xor_sync(0xffffffffu, mx1, 2));
        float mn0 = fmaxf(m_r[0], mx0);
        float mn1 = fmaxf(m_r[1], mx1);
        float corr0 = fast_exp(m_r[0] - mn0);
        float corr1 = fast_exp(m_r[1] - mn1);
        float rs0 = 0.f, rs1 = 0.f;
        #pragma unroll
        for (int j = 0; j < 8; j++) {
            s[j][0] = fast_exp(s[j][0] - mn0); rs0 += s[j][0];
            s[j][1] = fast_exp(s[j][1] - mn0); rs0 += s[j][1];
            s[j][2] = fast_exp(s[j][2] - mn1); rs1 += s[j][2];
            s[j][3] = fast_exp(s[j][3] - mn1); rs1 += s[j][3];
        }
        rs0 += __shfl_xor_sync(0xffffffffu, rs0, 1);
        rs0 += __shfl_xor_sync(0xffffffffu, rs0, 2);
        rs1 += __shfl_xor_sync(0xffffffffu, rs1, 1);
        rs1 += __shfl_xor_sync(0xffffffffu, rs1, 2);
        l_r[0] = l_r[0] * corr0 + rs0;
        l_r[1] = l_r[1] * corr1 + rs1;
        m_r[0] = mn0; m_r[1] = mn1;
        #pragma unroll
        for (int j = 0; j < 8; j++) {
            o[j][0] *= corr0; o[j][1] *= corr0;
            o[j][2] *= corr1; o[j][3] *= corr1;
        }

        // ---- O += P V (1-pass: P fp16) ----
        #pragma unroll
        for (int kk = 0; kk < 4; kk++) {
            uint32_t ph[4];
            __half2 p0 = __floats2half2_rn(s[2 * kk][0],     s[2 * kk][1]);
            __half2 p1 = __floats2half2_rn(s[2 * kk][2],     s[2 * kk][3]);
            __half2 p2 = __floats2half2_rn(s[2 * kk + 1][0], s[2 * kk + 1][1]);
            __half2 p3 = __floats2half2_rn(s[2 * kk + 1][2], s[2 * kk + 1][3]);
            ph[0] = *reinterpret_cast<uint32_t*>(&p0);
            ph[1] = *reinterpret_cast<uint32_t*>(&p1);
            ph[2] = *reinterpret_cast<uint32_t*>(&p2);
            ph[3] = *reinterpret_cast<uint32_t*>(&p3);
            #pragma unroll
            for (int g2 = 0; g2 < 4; g2++) {
                uint32_t rvh[4];
                ldsm4t(rvh, s2u(&sVh[(kk * 16 + lrow) * 72 + g2 * 16 + lcol]) + offKV);
                uint32_t bh0[2] = {rvh[0], rvh[1]}, bh1[2] = {rvh[2], rvh[3]};
                mma_f16(o[g2 * 2],     ph, bh0);
                mma_f16(o[g2 * 2 + 1], ph, bh1);
            }
        }
    }

    int b = bh >> 4, hh = bh & 15;
    float inv0 = 1.0f / l_r[0];
    float inv1 = 1.0f / l_r[1];
    #pragma unroll
    for (int h2 = 0; h2 < 2; h2++) {
        int srow = q0 + w * 16 + gid + h2 * 8;
        float inv = h2 ? inv1 : inv0;
        size_t base = (((size_t)(b * SEQ + srow)) * HEADS + hh) * HD;
        #pragma unroll
        for (int j = 0; j < 8; j++) {
            float a = o[j][h2 * 2 + 0] * inv;
            float c = o[j][h2 * 2 + 1] * inv;
            __half2 h2v = __floats2half2_rn(a, c);
            int d = j * 8 + 2 * tig;
            *reinterpret_cast<uint32_t*>(&y_hi[base + d]) = *reinterpret_cast<uint32_t*>(&h2v);
        }
    }
}

// ============================ launch ============================
extern "C" void kernel_launch(void* const* d_in, const int* in_sizes, int n_in,
                              void* d_out, int out_size)
{
    const float* x        = (const float*)d_in[0];
    const float* ln_scale = (const float*)d_in[2];
    const float* ln_bias  = (const float*)d_in[3];
    const float* w_qkv    = (const float*)d_in[4];
    const float* b_qkv    = (const float*)d_in[5];
    const float* w_out    = (const float*)d_in[6];
    const float* b_out    = (const float*)d_in[7];
    float* out = (float*)d_out;

    __half *xn_hi, *wq_hi, *wo_hi, *y_hi;
    __half *qh, *ql, *kh, *vh;
    cudaGetSymbolAddress((void**)&xn_hi, g_xn_hi);
    cudaGetSymbolAddress((void**)&wq_hi, g_wq_hi);
    cudaGetSymbolAddress((void**)&wo_hi, g_wo_hi);
    cudaGetSymbolAddress((void**)&y_hi,  g_y_hi);
    cudaGetSymbolAddress((void**)&qh, g_qh);
    cudaGetSymbolAddress((void**)&ql, g_ql);
    cudaGetSymbolAddress((void**)&kh, g_kh);
    cudaGetSymbolAddress((void**)&vh, g_vh);

    // 1. LayerNorm -> fp16
    ln_kernel<<<ROWS, 256>>>(x, ln_scale, ln_bias, xn_hi);

    // 1b. weight conversion
    convert_kernel<<<512, 256>>>(w_qkv, wq_hi, DIM * QKV_N);
    convert_kernel<<<256, 256>>>(w_out, wo_hi, DIM * DIM);

    int gemm_smem = 3 * GSTAGE;   // 56832

    // 2. QKV projection (single-pass fp16) -> q fp16 hi/lo, k/v fp16 (q pre-scaled)
    {
        cudaFuncSetAttribute(mma_gemm<0>,
                             cudaFuncAttributeMaxDynamicSharedMemorySize, gemm_smem);
        dim3 grid(QKV_N / 128, ROWS / 128);  // (24, 64)
        mma_gemm<0><<<grid, 256, gemm_smem>>>(xn_hi, wq_hi, b_qkv, nullptr,
                                              ROWS, QKV_N, DIM, qh, ql, kh, vh);
    }

    // 3. tensor-core causal flash attention (2-pass QK, 1-pass PV)
    {
        int smem = (2 * 128 * 72 + 4 * KVSTRIDE) * sizeof(__half);  // 73728
        cudaFuncSetAttribute(attn_mma_kernel,
                             cudaFuncAttributeMaxDynamicSharedMemorySize, smem);
        dim3 grid(BATCH * HEADS, SEQ / 128);  // (64, 16)
        attn_mma_kernel<<<grid, 256, smem>>>(qh, ql, kh, vh, y_hi);
    }

    // 4. output projection (single-pass fp16) -> d_out
    {
        cudaFuncSetAttribute(mma_gemm<1>,
                             cudaFuncAttributeMaxDynamicSharedMemorySize, gemm_smem);
        dim3 grid(DIM / 128, ROWS / 128);    // (8, 64)
        mma_gemm<1><<<grid, 256, gemm_smem>>>(y_hi, wo_hi, b_out, out,
                                              ROWS, DIM, DIM,
                                              nullptr, nullptr, nullptr, nullptr);
    }
}

// round 11
// speedup vs baseline: 6.0706x; 1.2081x over previous
#include <cuda_runtime.h>
#include <cuda_fp16.h>
#include <cstdint>

// Problem constants
#define BATCH 4
#define SEQ   2048
#define DIM   1024
#define HEADS 16
#define HD    64
#define ROWS  (BATCH * SEQ)          // 8192
#define QKV_N (HEADS * 3 * HD)       // 3072
#define BHSD  (BATCH * HEADS * SEQ * HD)

// -------- scratch (static device globals; no allocation allowed) --------
__device__ __half g_xn_hi[ROWS * DIM];
__device__ __half g_wq_hi[DIM * QKV_N];
__device__ __half g_wo_hi[DIM * DIM];
__device__ __half g_qh[BHSD];   // [b,h,s,d] fp16 (pre-scaled)
__device__ __half g_kh[BHSD];
__device__ __half g_vh[BHSD];
__device__ __half g_y_hi[ROWS * DIM];   // attn out [b,s,h,d]

// ============================ helpers ============================
__device__ __forceinline__ uint32_t s2u(const void* p) {
    return (uint32_t)__cvta_generic_to_shared(p);
}
__device__ __forceinline__ void ldsm4(uint32_t* r, uint32_t addr) {
    asm volatile("ldmatrix.sync.aligned.m8n8.x4.shared.b16 {%0,%1,%2,%3}, [%4];\n"
                 : "=r"(r[0]), "=r"(r[1]), "=r"(r[2]), "=r"(r[3]) : "r"(addr));
}
__device__ __forceinline__ void ldsm4t(uint32_t* r, uint32_t addr) {
    asm volatile("ldmatrix.sync.aligned.m8n8.x4.trans.shared.b16 {%0,%1,%2,%3}, [%4];\n"
                 : "=r"(r[0]), "=r"(r[1]), "=r"(r[2]), "=r"(r[3]) : "r"(addr));
}
__device__ __forceinline__ void mma_f16(float* c, const uint32_t* a, const uint32_t* b) {
    asm volatile(
        "mma.sync.aligned.m16n8k16.row.col.f32.f16.f16.f32 "
        "{%0,%1,%2,%3}, {%4,%5,%6,%7}, {%8,%9}, {%0,%1,%2,%3};\n"
        : "+f"(c[0]), "+f"(c[1]), "+f"(c[2]), "+f"(c[3])
        : "r"(a[0]), "r"(a[1]), "r"(a[2]), "r"(a[3]), "r"(b[0]), "r"(b[1]));
}
__device__ __forceinline__ void cp16(uint32_t smem_dst, const void* gmem_src) {
    asm volatile("cp.async.cg.shared.global [%0], [%1], 16;\n"
                 :: "r"(smem_dst), "l"(gmem_src));
}
__device__ __forceinline__ void cp_commit() {
    asm volatile("cp.async.commit_group;\n");
}
template <int N>
__device__ __forceinline__ void cp_wait() {
    asm volatile("cp.async.wait_group %0;\n" :: "n"(N));
}
// fast exp on FMA pipe (no MUFU). valid for x <= 0.
__device__ __forceinline__ float fast_exp(float x) {
    float t = x * 1.4426950408889634f;
    t = fmaxf(t, -126.0f);
    float fi = rintf(t);
    float g = (t - fi) * 0.6931471805599453f;
    float p = 8.3333333e-3f;
    p = fmaf(p, g, 4.1666667e-2f);
    p = fmaf(p, g, 0.16666667f);
    p = fmaf(p, g, 0.5f);
    p = fmaf(p, g, 1.0f);
    p = fmaf(p, g, 1.0f);
    int ei = (int)fi;
    float sc = __int_as_float((ei + 127) << 23);
    return sc * p;
}

// ============================ LayerNorm -> fp16 ============================
__global__ void __launch_bounds__(256) ln_kernel(
    const float* __restrict__ x,
    const float* __restrict__ gamma,
    const float* __restrict__ beta,
    __half* __restrict__ out_hi)
{
    int row = blockIdx.x;
    int t = threadIdx.x;
    const float4* xr = reinterpret_cast<const float4*>(x + (size_t)row * DIM);
    float4 v = xr[t];
    float s1 = v.x + v.y + v.z + v.w;
    float s2 = v.x*v.x + v.y*v.y + v.z*v.z + v.w*v.w;
    #pragma unroll
    for (int o = 16; o > 0; o >>= 1) {
        s1 += __shfl_xor_sync(0xffffffffu, s1, o);
        s2 += __shfl_xor_sync(0xffffffffu, s2, o);
    }
    __shared__ float r1[8], r2[8];
    __shared__ float sh_mu, sh_rstd;
    if ((t & 31) == 0) { r1[t >> 5] = s1; r2[t >> 5] = s2; }
    __syncthreads();
    if (t == 0) {
        float a = 0.f, b = 0.f;
        #pragma unroll
        for (int i = 0; i < 8; i++) { a += r1[i]; b += r2[i]; }
        float mu  = a * (1.0f / DIM);
        float var = b * (1.0f / DIM) - mu * mu;
        sh_mu = mu;
        sh_rstd = rsqrtf(var + 1e-6f);
    }
    __syncthreads();
    float mu = sh_mu, rstd = sh_rstd;
    float4 g = reinterpret_cast<const float4*>(gamma)[t];
    float4 b4 = reinterpret_cast<const float4*>(beta)[t];
    float o0 = (v.x - mu) * rstd * g.x + b4.x;
    float o1 = (v.y - mu) * rstd * g.y + b4.y;
    float o2 = (v.z - mu) * rstd * g.z + b4.z;
    float o3 = (v.w - mu) * rstd * g.w + b4.w;
    __half2 ha = __floats2half2_rn(o0, o1);
    __half2 hb = __floats2half2_rn(o2, o3);
    size_t base = (size_t)row * DIM + t * 4;
    *reinterpret_cast<__half2*>(&out_hi[base])     = ha;
    *reinterpret_cast<__half2*>(&out_hi[base + 2]) = hb;
}

// ============================ fp32 -> fp16 convert (weights) ============================
__global__ void __launch_bounds__(256) convert_kernel(
    const float* __restrict__ w,
    __half* __restrict__ hi,
    int n)
{
    int i = blockIdx.x * blockDim.x + threadIdx.x;
    int stride = gridDim.x * blockDim.x;
    for (; i < n; i += stride)
        hi[i] = __float2half_rn(w[i]);
}

// ============================ fp16 single-pass MMA GEMM 128x128, 32-K slices, 3-stage ============================
// C = A @ B (+ bias). Warp tile 32x64 (4x2 layout).
// MODE 0: QKV — scatter fp16 into q/k/v ([b,h,s,d]) with q-scale.
// MODE 1: fp32 C.
#define GA_STRIDE 40                        // halves per A row (32 data + 8 pad)
#define GB_STRIDE 136                       // halves per B row (128 data + 8 pad)
#define GA_BYTES  (128 * GA_STRIDE * 2)     // 10240
#define GB_BYTES  (32 * GB_STRIDE * 2)      // 8704
#define GSTAGE    (GA_BYTES + GB_BYTES)     // 18944
#define G_OFF_B   GA_BYTES
template <int MODE>
__global__ void __launch_bounds__(256, 2) mma_gemm(
    const __half* __restrict__ Ag,
    const __half* __restrict__ Bg,
    const float* __restrict__ bias,
    float* __restrict__ Cout,
    int M, int N, int K,
    __half* __restrict__ qh, __half* __restrict__ kh, __half* __restrict__ vh)
{
    extern __shared__ __align__(16) char smem[];
    uint32_t smem_base = s2u(smem);

    int tid = threadIdx.x;
    int lane = tid & 31;
    int wid = tid >> 5;
    int wm = wid & 3;          // warp row (0..3) -> 32 rows each
    int wn = wid >> 2;         // warp col (0..1) -> 64 cols each
    int m0 = blockIdx.y * 128;
    int n0 = blockIdx.x * 128;

    int arow = tid >> 1;
    int acol = (tid & 1) * 16;       // halves
    int brow = tid >> 3;             // 0..31
    int bcol = (tid & 7) * 16;       // halves

    const __half* pA = Ag + (size_t)(m0 + arow) * K + acol;
    const __half* pB = Bg + (size_t)brow * N + n0 + bcol;
    uint32_t aoff = (arow * GA_STRIDE + acol) * 2;
    uint32_t boff = (brow * GB_STRIDE + bcol) * 2;

    float acc[2][8][4];
    #pragma unroll
    for (int i = 0; i < 2; i++)
        #pragma unroll
        for (int j = 0; j < 8; j++)
            #pragma unroll
            for (int e = 0; e < 4; e++) acc[i][j][e] = 0.f;

    int niter = K / 32;

    auto issue = [&](int kt, int s) {
        uint32_t st = smem_base + s * GSTAGE;
        int ko = kt * 32;
        const __half* a = pA + ko;
        const __half* b = pB + (size_t)ko * N;
        cp16(st + aoff,              a);
        cp16(st + aoff + 16,         a + 8);
        cp16(st + G_OFF_B + boff,      b);
        cp16(st + G_OFF_B + boff + 16, b + 8);
        cp_commit();
    };

    issue(0, 0);
    issue(1, 1);

    int lrow = lane & 15;
    int lcol = (lane >> 4) * 8;
    uint32_t baseA[2];
    #pragma unroll
    for (int i = 0; i < 2; i++)
        baseA[i] = smem_base + ((wm * 32 + i * 16 + lrow) * GA_STRIDE + lcol) * 2;
    uint32_t baseB[4];
    #pragma unroll
    for (int jj = 0; jj < 4; jj++)
        baseB[jj] = smem_base + G_OFF_B + (lrow * GB_STRIDE + wn * 64 + jj * 16 + lcol) * 2;

    int s = 0;
    for (int kt = 0; kt < niter; kt++) {
        if (kt + 1 < niter) cp_wait<1>();
        else                cp_wait<0>();
        __syncthreads();

        if (kt + 2 < niter) {
            int s2 = s + 2; if (s2 >= 3) s2 -= 3;
            issue(kt + 2, s2);
        }

        uint32_t offS = (uint32_t)(s * GSTAGE);
        #pragma unroll
        for (int ss = 0; ss < 2; ss++) {
            uint32_t aSub = offS + ss * 32;                       // +16 halves
            uint32_t bSub = offS + ss * 16 * GB_STRIDE * 2;       // +16 rows

            uint32_t ah[2][4], bb[8][2];
            #pragma unroll
            for (int i = 0; i < 2; i++)
                ldsm4(ah[i], baseA[i] + aSub);
            #pragma unroll
            for (int jj = 0; jj < 4; jj++) {
                uint32_t r[4];
                ldsm4t(r, baseB[jj] + bSub);
                bb[jj * 2][0] = r[0]; bb[jj * 2][1] = r[1];
                bb[jj * 2 + 1][0] = r[2]; bb[jj * 2 + 1][1] = r[3];
            }
            #pragma unroll
            for (int i = 0; i < 2; i++)
                #pragma unroll
                for (int j = 0; j < 8; j++)
                    mma_f16(acc[i][j], ah[i], bb[j]);
        }
        s++; if (s == 3) s = 0;
    }

    int gid = lane >> 2, tig = lane & 3;
    #pragma unroll
    for (int i = 0; i < 2; i++) {
        #pragma unroll
        for (int j = 0; j < 8; j++) {
            int n = n0 + wn * 64 + j * 8 + 2 * tig;
            if (MODE == 0) {
                int hq = n / 192;
                int f = n - hq * 192;
                __half* dst;
                float sc;
                int off;
                if (f < 64)       { dst = qh; sc = 0.125f; off = f; }
                else if (f < 128) { dst = kh; sc = 1.0f;   off = f - 64; }
                else              { dst = vh; sc = 1.0f;   off = f - 128; }
                #pragma unroll
                for (int rh = 0; rh < 2; rh++) {
                    int m = m0 + wm * 32 + i * 16 + gid + rh * 8;
                    float v0 = (acc[i][j][rh * 2 + 0] + bias[n])     * sc;
                    float v1 = (acc[i][j][rh * 2 + 1] + bias[n + 1]) * sc;
                    int bb2 = m >> 11;
                    int ss2 = m & 2047;
                    size_t base = (((size_t)(bb2 * HEADS + hq)) * SEQ + ss2) * HD;
                    __half2 h2 = __floats2half2_rn(v0, v1);
                    *reinterpret_cast<uint32_t*>(&dst[base + off]) =
                        *reinterpret_cast<uint32_t*>(&h2);
                }
            } else {
                #pragma unroll
                for (int rh = 0; rh < 2; rh++) {
                    int m = m0 + wm * 32 + i * 16 + gid + rh * 8;
                    float v0 = acc[i][j][rh * 2 + 0] + bias[n];
                    float v1 = acc[i][j][rh * 2 + 1] + bias[n + 1];
                    *reinterpret_cast<float2*>(&Cout[(size_t)m * N + n]) = make_float2(v0, v1);
                }
            }
        }
    }
}

// ============================ Tensor-core flash attention (1-pass QK, 1-pass PV) ============================
#define KVSTRIDE (64 * 72)
__global__ void __launch_bounds__(256) attn_mma_kernel(
    const __half* __restrict__ qh_g,
    const __half* __restrict__ kh_g,
    const __half* __restrict__ vh_g,
    __half* __restrict__ y_hi)
{
    extern __shared__ __half smb[];
    __half* sQh = smb;                      // [128][72]
    __half* sKh = sQh + 128 * 72;           // [2][64][72]
    __half* sVh = sKh + 2 * KVSTRIDE;       // [2][64][72]

    int bh = blockIdx.x;
    int qt = (gridDim.y - 1) - blockIdx.y;   // heavy tiles first
    int tid = threadIdx.x;
    int lane = tid & 31;
    int w = tid >> 5;
    int gid = lane >> 2, tig = lane & 3;
    int lrow = lane & 15, lcol = (lane >> 4) * 8;

    int q0 = qt * 128;
    const size_t bhoff = (size_t)bh * SEQ * HD;

    int kvr = tid >> 3;
    int kvd = (tid & 7) * 8;
    auto issue_kv = [&](int kt, int st) {
        int c0 = kt * 64;
        size_t base = st * KVSTRIDE;
        #pragma unroll
        for (int i = 0; i < 2; i++) {
            int r = kvr + i * 32;
            size_t g = bhoff + (size_t)(c0 + r) * HD + kvd;
            size_t sm = base + r * 72 + kvd;
            cp16(s2u(&sKh[sm]), &kh_g[g]);
            cp16(s2u(&sVh[sm]), &vh_g[g]);
        }
        cp_commit();
    };

    int ktmax = 2 * qt + 1;
    issue_kv(0, 0);

    #pragma unroll
    for (int i = 0; i < 4; i++) {
        int chunk = tid + i * 256;
        int r = chunk >> 3, d8 = (chunk & 7) * 8;
        size_t g = bhoff + (size_t)(q0 + r) * HD + d8;
        *reinterpret_cast<uint4*>(&sQh[r * 72 + d8]) = *reinterpret_cast<const uint4*>(&qh_g[g]);
    }
    __syncthreads();

    uint32_t qfh[4][4];
    #pragma unroll
    for (int kk = 0; kk < 4; kk++)
        ldsm4(qfh[kk], s2u(&sQh[(w * 16 + lrow) * 72 + kk * 16 + lcol]));

    float m_r[2] = {-1e30f, -1e30f};
    float l_r[2] = {0.f, 0.f};
    float o[8][4];
    #pragma unroll
    for (int j = 0; j < 8; j++)
        #pragma unroll
        for (int c = 0; c < 4; c++) o[j][c] = 0.f;

    for (int kt = 0; kt <= ktmax; kt++) {
        int c0 = kt * 64;
        int st = kt & 1;
        uint32_t offKV = (uint32_t)(st * KVSTRIDE * 2);

        cp_wait<0>();
        __syncthreads();   // stage st ready; all warps done reading the other stage

        if (kt < ktmax) issue_kv(kt + 1, (kt + 1) & 1);

        float s[8][4];
        #pragma unroll
        for (int j = 0; j < 8; j++)
            #pragma unroll
            for (int c = 0; c < 4; c++) s[j][c] = 0.f;

        #pragma unroll
        for (int kk = 0; kk < 4; kk++) {
            #pragma unroll
            for (int g2 = 0; g2 < 4; g2++) {
                uint32_t rh[4];
                ldsm4(rh, s2u(&sKh[(g2 * 16 + lrow) * 72 + kk * 16 + lcol]) + offKV);
                uint32_t b0h[2] = {rh[0], rh[2]}, b1h[2] = {rh[1], rh[3]};
                mma_f16(s[g2 * 2],     qfh[kk], b0h);
                mma_f16(s[g2 * 2 + 1], qfh[kk], b1h);
            }
        }

        if (kt >= 2 * qt) {
            int row0 = q0 + w * 16 + gid;
            #pragma unroll
            for (int j = 0; j < 8; j++) {
                int col = c0 + j * 8 + 2 * tig;
                if (col     > row0)     s[j][0] = -1e30f;
                if (col + 1 > row0)     s[j][1] = -1e30f;
                if (col     > row0 + 8) s[j][2] = -1e30f;
                if (col + 1 > row0 + 8) s[j][3] = -1e30f;
            }
        }

        float mx0 = -1e30f, mx1 = -1e30f;
        #pragma unroll
        for (int j = 0; j < 8; j++) {
            mx0 = fmaxf(mx0, fmaxf(s[j][0], s[j][1]));
            mx1 = fmaxf(mx1, fmaxf(s[j][2], s[j][3]));
        }
        mx0 = fmaxf(mx0, __shfl_xor_sync(0xffffffffu, mx0, 1));
        mx0 = fmaxf(mx0, __shfl_xor_sync(0xffffffffu, mx0, 2));
        mx1 = fmaxf(mx1, __shfl_xor_sync(0xffffffffu, mx1, 1));
        mx1 = fmaxf(mx1, __shfl_xor_sync(0xffffffffu, mx1, 2));
        float mn0 = fmaxf(m_r[0], mx0);
        float mn1 = fmaxf(m_r[1], mx1);
        float corr0 = fast_exp(m_r[0] - mn0);
        float corr1 = fast_exp(m_r[1] - mn1);
        float rs0 = 0.f, rs1 = 0.f;
        #pragma unroll
        for (int j = 0; j < 8; j++) {
            s[j][0] = fast_exp(s[j][0] - mn0); rs0 += s[j][0];
            s[j][1] = fast_exp(s[j][1] - mn0); rs0 += s[j][1];
            s[j][2] = fast_exp(s[j][2] - mn1); rs1 += s[j][2];
            s[j][3] = fast_exp(s[j][3] - mn1); rs1 += s[j][3];
        }
        rs0 += __shfl_xor_sync(0xffffffffu, rs0, 1);
        rs0 += __shfl_xor_sync(0xffffffffu, rs0, 2);
        rs1 += __shfl_xor_sync(0xffffffffu, rs1, 1);
        rs1 += __shfl_xor_sync(0xffffffffu, rs1, 2);
        l_r[0] = l_r[0] * corr0 + rs0;
        l_r[1] = l_r[1] * corr1 + rs1;
        m_r[0] = mn0; m_r[1] = mn1;
        #pragma unroll
        for (int j = 0; j < 8; j++) {
            o[j][0] *= corr0; o[j][1] *= corr0;
            o[j][2] *= corr1; o[j][3] *= corr1;
        }

        // ---- O += P V (1-pass: P fp16) ----
        #pragma unroll
        for (int kk = 0; kk < 4; kk++) {
            uint32_t ph[4];
            __half2 p0 = __floats2half2_rn(s[2 * kk][0],     s[2 * kk][1]);
            __half2 p1 = __floats2half2_rn(s[2 * kk][2],     s[2 * kk][3]);
            __half2 p2 = __floats2half2_rn(s[2 * kk + 1][0], s[2 * kk + 1][1]);
            __half2 p3 = __floats2half2_rn(s[2 * kk + 1][2], s[2 * kk + 1][3]);
            ph[0] = *reinterpret_cast<uint32_t*>(&p0);
            ph[1] = *reinterpret_cast<uint32_t*>(&p1);
            ph[2] = *reinterpret_cast<uint32_t*>(&p2);
            ph[3] = *reinterpret_cast<uint32_t*>(&p3);
            #pragma unroll
            for (int g2 = 0; g2 < 4; g2++) {
                uint32_t rvh[4];
                ldsm4t(rvh, s2u(&sVh[(kk * 16 + lrow) * 72 + g2 * 16 + lcol]) + offKV);
                uint32_t bh0[2] = {rvh[0], rvh[1]}, bh1[2] = {rvh[2], rvh[3]};
                mma_f16(o[g2 * 2],     ph, bh0);
                mma_f16(o[g2 * 2 + 1], ph, bh1);
            }
        }
    }

    int b = bh >> 4, hh = bh & 15;
    float inv0 = 1.0f / l_r[0];
    float inv1 = 1.0f / l_r[1];
    #pragma unroll
    for (int h2 = 0; h2 < 2; h2++) {
        int srow = q0 + w * 16 + gid + h2 * 8;
        float inv = h2 ? inv1 : inv0;
        size_t base = (((size_t)(b * SEQ + srow)) * HEADS + hh) * HD;
        #pragma unroll
        for (int j = 0; j < 8; j++) {
            float a = o[j][h2 * 2 + 0] * inv;
            float c = o[j][h2 * 2 + 1] * inv;
            __half2 h2v = __floats2half2_rn(a, c);
            int d = j * 8 + 2 * tig;
            *reinterpret_cast<uint32_t*>(&y_hi[base + d]) = *reinterpret_cast<uint32_t*>(&h2v);
        }
    }
}

// ============================ launch ============================
extern "C" void kernel_launch(void* const* d_in, const int* in_sizes, int n_in,
                              void* d_out, int out_size)
{
    const float* x        = (const float*)d_in[0];
    const float* ln_scale = (const float*)d_in[2];
    const float* ln_bias  = (const float*)d_in[3];
    const float* w_qkv    = (const float*)d_in[4];
    const float* b_qkv    = (const float*)d_in[5];
    const float* w_out    = (const float*)d_in[6];
    const float* b_out    = (const float*)d_in[7];
    float* out = (float*)d_out;

    __half *xn_hi, *wq_hi, *wo_hi, *y_hi;
    __half *qh, *kh, *vh;
    cudaGetSymbolAddress((void**)&xn_hi, g_xn_hi);
    cudaGetSymbolAddress((void**)&wq_hi, g_wq_hi);
    cudaGetSymbolAddress((void**)&wo_hi, g_wo_hi);
    cudaGetSymbolAddress((void**)&y_hi,  g_y_hi);
    cudaGetSymbolAddress((void**)&qh, g_qh);
    cudaGetSymbolAddress((void**)&kh, g_kh);
    cudaGetSymbolAddress((void**)&vh, g_vh);

    // 1. LayerNorm -> fp16
    ln_kernel<<<ROWS, 256>>>(x, ln_scale, ln_bias, xn_hi);

    // 1b. weight conversion
    convert_kernel<<<512, 256>>>(w_qkv, wq_hi, DIM * QKV_N);
    convert_kernel<<<256, 256>>>(w_out, wo_hi, DIM * DIM);

    int gemm_smem = 3 * GSTAGE;   // 56832

    // 2. QKV projection (single-pass fp16) -> q/k/v fp16 (q pre-scaled)
    {
        cudaFuncSetAttribute(mma_gemm<0>,
                             cudaFuncAttributeMaxDynamicSharedMemorySize, gemm_smem);
        dim3 grid(QKV_N / 128, ROWS / 128);  // (24, 64)
        mma_gemm<0><<<grid, 256, gemm_smem>>>(xn_hi, wq_hi, b_qkv, nullptr,
                                              ROWS, QKV_N, DIM, qh, kh, vh);
    }

    // 3. tensor-core causal flash attention (1-pass QK, 1-pass PV)
    {
        int smem = (128 * 72 + 4 * KVSTRIDE) * sizeof(__half);  // 55296
        cudaFuncSetAttribute(attn_mma_kernel,
                             cudaFuncAttributeMaxDynamicSharedMemorySize, smem);
        dim3 grid(BATCH * HEADS, SEQ / 128);  // (64, 16)
        attn_mma_kernel<<<grid, 256, smem>>>(qh, kh, vh, y_hi);
    }

    // 4. output projection (single-pass fp16) -> d_out
    {
        cudaFuncSetAttribute(mma_gemm<1>,
                             cudaFuncAttributeMaxDynamicSharedMemorySize, gemm_smem);
        dim3 grid(DIM / 128, ROWS / 128);    // (8, 64)
        mma_gemm<1><<<grid, 256, gemm_smem>>>(y_hi, wo_hi, b_out, out,
                                              ROWS, DIM, DIM,
                                              nullptr, nullptr, nullptr);
    }
}

// round 12
// speedup vs baseline: 6.7047x; 1.1045x over previous
#include <cuda_runtime.h>
#include <cuda_fp16.h>
#include <cstdint>

// Problem constants
#define BATCH 4
#define SEQ   2048
#define DIM   1024
#define HEADS 16
#define HD    64
#define ROWS  (BATCH * SEQ)          // 8192
#define QKV_N (HEADS * 3 * HD)       // 3072
#define BHSD  (BATCH * HEADS * SEQ * HD)

// -------- scratch (static device globals; no allocation allowed) --------
__device__ __half g_xn_hi[ROWS * DIM];
__device__ __half g_wq_hi[DIM * QKV_N];
__device__ __half g_wo_hi[DIM * DIM];
__device__ __half g_qh[BHSD];   // [b,h,s,d] fp16 (pre-scaled by 0.125*log2e)
__device__ __half g_kh[BHSD];
__device__ __half g_vh[BHSD];
__device__ __half g_y_hi[ROWS * DIM];   // attn out [b,s,h,d]

// ============================ helpers ============================
__device__ __forceinline__ uint32_t s2u(const void* p) {
    return (uint32_t)__cvta_generic_to_shared(p);
}
__device__ __forceinline__ void ldsm4(uint32_t* r, uint32_t addr) {
    asm volatile("ldmatrix.sync.aligned.m8n8.x4.shared.b16 {%0,%1,%2,%3}, [%4];\n"
                 : "=r"(r[0]), "=r"(r[1]), "=r"(r[2]), "=r"(r[3]) : "r"(addr));
}
__device__ __forceinline__ void ldsm4t(uint32_t* r, uint32_t addr) {
    asm volatile("ldmatrix.sync.aligned.m8n8.x4.trans.shared.b16 {%0,%1,%2,%3}, [%4];\n"
                 : "=r"(r[0]), "=r"(r[1]), "=r"(r[2]), "=r"(r[3]) : "r"(addr));
}
__device__ __forceinline__ void mma_f16(float* c, const uint32_t* a, const uint32_t* b) {
    asm volatile(
        "mma.sync.aligned.m16n8k16.row.col.f32.f16.f16.f32 "
        "{%0,%1,%2,%3}, {%4,%5,%6,%7}, {%8,%9}, {%0,%1,%2,%3};\n"
        : "+f"(c[0]), "+f"(c[1]), "+f"(c[2]), "+f"(c[3])
        : "r"(a[0]), "r"(a[1]), "r"(a[2]), "r"(a[3]), "r"(b[0]), "r"(b[1]));
}
__device__ __forceinline__ void cp16(uint32_t smem_dst, const void* gmem_src) {
    asm volatile("cp.async.cg.shared.global [%0], [%1], 16;\n"
                 :: "r"(smem_dst), "l"(gmem_src));
}
__device__ __forceinline__ void cp_commit() {
    asm volatile("cp.async.commit_group;\n");
}
template <int N>
__device__ __forceinline__ void cp_wait() {
    asm volatile("cp.async.wait_group %0;\n" :: "n"(N));
}
// MUFU ex2: single-instruction 2^x (log2-domain softmax)
__device__ __forceinline__ float ex2(float x) {
    float r;
    asm("ex2.approx.f32 %0, %1;" : "=f"(r) : "f"(x));
    return r;
}

// ============================ LayerNorm -> fp16 ============================
__global__ void __launch_bounds__(256) ln_kernel(
    const float* __restrict__ x,
    const float* __restrict__ gamma,
    const float* __restrict__ beta,
    __half* __restrict__ out_hi)
{
    int row = blockIdx.x;
    int t = threadIdx.x;
    const float4* xr = reinterpret_cast<const float4*>(x + (size_t)row * DIM);
    float4 v = xr[t];
    float s1 = v.x + v.y + v.z + v.w;
    float s2 = v.x*v.x + v.y*v.y + v.z*v.z + v.w*v.w;
    #pragma unroll
    for (int o = 16; o > 0; o >>= 1) {
        s1 += __shfl_xor_sync(0xffffffffu, s1, o);
        s2 += __shfl_xor_sync(0xffffffffu, s2, o);
    }
    __shared__ float r1[8], r2[8];
    __shared__ float sh_mu, sh_rstd;
    if ((t & 31) == 0) { r1[t >> 5] = s1; r2[t >> 5] = s2; }
    __syncthreads();
    if (t == 0) {
        float a = 0.f, b = 0.f;
        #pragma unroll
        for (int i = 0; i < 8; i++) { a += r1[i]; b += r2[i]; }
        float mu  = a * (1.0f / DIM);
        float var = b * (1.0f / DIM) - mu * mu;
        sh_mu = mu;
        sh_rstd = rsqrtf(var + 1e-6f);
    }
    __syncthreads();
    float mu = sh_mu, rstd = sh_rstd;
    float4 g = reinterpret_cast<const float4*>(gamma)[t];
    float4 b4 = reinterpret_cast<const float4*>(beta)[t];
    float o0 = (v.x - mu) * rstd * g.x + b4.x;
    float o1 = (v.y - mu) * rstd * g.y + b4.y;
    float o2 = (v.z - mu) * rstd * g.z + b4.z;
    float o3 = (v.w - mu) * rstd * g.w + b4.w;
    __half2 ha = __floats2half2_rn(o0, o1);
    __half2 hb = __floats2half2_rn(o2, o3);
    size_t base = (size_t)row * DIM + t * 4;
    *reinterpret_cast<__half2*>(&out_hi[base])     = ha;
    *reinterpret_cast<__half2*>(&out_hi[base + 2]) = hb;
}

// ============================ fp32 -> fp16 convert (weights) ============================
__global__ void __launch_bounds__(256) convert_kernel(
    const float* __restrict__ w,
    __half* __restrict__ hi,
    int n)
{
    int i = blockIdx.x * blockDim.x + threadIdx.x;
    int stride = gridDim.x * blockDim.x;
    for (; i < n; i += stride)
        hi[i] = __float2half_rn(w[i]);
}

// ============================ fp16 single-pass MMA GEMM 128x128, 32-K slices, 3-stage ============================
// C = A @ B (+ bias). Warp tile 32x64 (4x2 layout).
// MODE 0: QKV — scatter fp16 into q/k/v ([b,h,s,d]); q scaled by 0.125*log2e.
// MODE 1: fp32 C.
#define GA_STRIDE 40                        // halves per A row (32 data + 8 pad)
#define GB_STRIDE 136                       // halves per B row (128 data + 8 pad)
#define GA_BYTES  (128 * GA_STRIDE * 2)     // 10240
#define GB_BYTES  (32 * GB_STRIDE * 2)      // 8704
#define GSTAGE    (GA_BYTES + GB_BYTES)     // 18944
#define G_OFF_B   GA_BYTES
#define Q_SCALE   (0.125f * 1.4426950408889634f)
template <int MODE>
__global__ void __launch_bounds__(256, 2) mma_gemm(
    const __half* __restrict__ Ag,
    const __half* __restrict__ Bg,
    const float* __restrict__ bias,
    float* __restrict__ Cout,
    int M, int N, int K,
    __half* __restrict__ qh, __half* __restrict__ kh, __half* __restrict__ vh)
{
    extern __shared__ __align__(16) char smem[];
    uint32_t smem_base = s2u(smem);

    int tid = threadIdx.x;
    int lane = tid & 31;
    int wid = tid >> 5;
    int wm = wid & 3;          // warp row (0..3) -> 32 rows each
    int wn = wid >> 2;         // warp col (0..1) -> 64 cols each
    int m0 = blockIdx.y * 128;
    int n0 = blockIdx.x * 128;

    int arow = tid >> 1;
    int acol = (tid & 1) * 16;       // halves
    int brow = tid >> 3;             // 0..31
    int bcol = (tid & 7) * 16;       // halves

    const __half* pA = Ag + (size_t)(m0 + arow) * K + acol;
    const __half* pB = Bg + (size_t)brow * N + n0 + bcol;
    uint32_t aoff = (arow * GA_STRIDE + acol) * 2;
    uint32_t boff = (brow * GB_STRIDE + bcol) * 2;

    float acc[2][8][4];
    #pragma unroll
    for (int i = 0; i < 2; i++)
        #pragma unroll
        for (int j = 0; j < 8; j++)
            #pragma unroll
            for (int e = 0; e < 4; e++) acc[i][j][e] = 0.f;

    int niter = K / 32;

    auto issue = [&](int kt, int s) {
        uint32_t st = smem_base + s * GSTAGE;
        int ko = kt * 32;
        const __half* a = pA + ko;
        const __half* b = pB + (size_t)ko * N;
        cp16(st + aoff,              a);
        cp16(st + aoff + 16,         a + 8);
        cp16(st + G_OFF_B + boff,      b);
        cp16(st + G_OFF_B + boff + 16, b + 8);
        cp_commit();
    };

    issue(0, 0);
    issue(1, 1);

    int lrow = lane & 15;
    int lcol = (lane >> 4) * 8;
    uint32_t baseA[2];
    #pragma unroll
    for (int i = 0; i < 2; i++)
        baseA[i] = smem_base + ((wm * 32 + i * 16 + lrow) * GA_STRIDE + lcol) * 2;
    uint32_t baseB[4];
    #pragma unroll
    for (int jj = 0; jj < 4; jj++)
        baseB[jj] = smem_base + G_OFF_B + (lrow * GB_STRIDE + wn * 64 + jj * 16 + lcol) * 2;

    int s = 0;
    for (int kt = 0; kt < niter; kt++) {
        if (kt + 1 < niter) cp_wait<1>();
        else                cp_wait<0>();
        __syncthreads();

        if (kt + 2 < niter) {
            int s2 = s + 2; if (s2 >= 3) s2 -= 3;
            issue(kt + 2, s2);
        }

        uint32_t offS = (uint32_t)(s * GSTAGE);
        #pragma unroll
        for (int ss = 0; ss < 2; ss++) {
            uint32_t aSub = offS + ss * 32;                       // +16 halves
            uint32_t bSub = offS + ss * 16 * GB_STRIDE * 2;       // +16 rows

            uint32_t ah[2][4], bb[8][2];
            #pragma unroll
            for (int i = 0; i < 2; i++)
                ldsm4(ah[i], baseA[i] + aSub);
            #pragma unroll
            for (int jj = 0; jj < 4; jj++) {
                uint32_t r[4];
                ldsm4t(r, baseB[jj] + bSub);
                bb[jj * 2][0] = r[0]; bb[jj * 2][1] = r[1];
                bb[jj * 2 + 1][0] = r[2]; bb[jj * 2 + 1][1] = r[3];
            }
            #pragma unroll
            for (int i = 0; i < 2; i++)
                #pragma unroll
                for (int j = 0; j < 8; j++)
                    mma_f16(acc[i][j], ah[i], bb[j]);
        }
        s++; if (s == 3) s = 0;
    }

    int gid = lane >> 2, tig = lane & 3;
    #pragma unroll
    for (int i = 0; i < 2; i++) {
        #pragma unroll
        for (int j = 0; j < 8; j++) {
            int n = n0 + wn * 64 + j * 8 + 2 * tig;
            if (MODE == 0) {
                int hq = n / 192;
                int f = n - hq * 192;
                __half* dst;
                float sc;
                int off;
                if (f < 64)       { dst = qh; sc = Q_SCALE; off = f; }
                else if (f < 128) { dst = kh; sc = 1.0f;    off = f - 64; }
                else              { dst = vh; sc = 1.0f;    off = f - 128; }
                #pragma unroll
                for (int rh = 0; rh < 2; rh++) {
                    int m = m0 + wm * 32 + i * 16 + gid + rh * 8;
                    float v0 = (acc[i][j][rh * 2 + 0] + bias[n])     * sc;
                    float v1 = (acc[i][j][rh * 2 + 1] + bias[n + 1]) * sc;
                    int bb2 = m >> 11;
                    int ss2 = m & 2047;
                    size_t base = (((size_t)(bb2 * HEADS + hq)) * SEQ + ss2) * HD;
                    __half2 h2 = __floats2half2_rn(v0, v1);
                    *reinterpret_cast<uint32_t*>(&dst[base + off]) =
                        *reinterpret_cast<uint32_t*>(&h2);
                }
            } else {
                #pragma unroll
                for (int rh = 0; rh < 2; rh++) {
                    int m = m0 + wm * 32 + i * 16 + gid + rh * 8;
                    float v0 = acc[i][j][rh * 2 + 0] + bias[n];
                    float v1 = acc[i][j][rh * 2 + 1] + bias[n + 1];
                    *reinterpret_cast<float2*>(&Cout[(size_t)m * N + n]) = make_float2(v0, v1);
                }
            }
        }
    }
}

// ============================ Tensor-core flash attention (log2-domain softmax, MUFU ex2) ============================
#define KVSTRIDE (64 * 72)
__global__ void __launch_bounds__(256) attn_mma_kernel(
    const __half* __restrict__ qh_g,
    const __half* __restrict__ kh_g,
    const __half* __restrict__ vh_g,
    __half* __restrict__ y_hi)
{
    extern __shared__ __half smb[];
    __half* sQh = smb;                      // [128][72]
    __half* sKh = sQh + 128 * 72;           // [2][64][72]
    __half* sVh = sKh + 2 * KVSTRIDE;       // [2][64][72]

    int bh = blockIdx.x;
    int qt = (gridDim.y - 1) - blockIdx.y;   // heavy tiles first
    int tid = threadIdx.x;
    int lane = tid & 31;
    int w = tid >> 5;
    int gid = lane >> 2, tig = lane & 3;
    int lrow = lane & 15, lcol = (lane >> 4) * 8;

    int q0 = qt * 128;
    const size_t bhoff = (size_t)bh * SEQ * HD;

    int kvr = tid >> 3;
    int kvd = (tid & 7) * 8;
    auto issue_kv = [&](int kt, int st) {
        int c0 = kt * 64;
        size_t base = st * KVSTRIDE;
        #pragma unroll
        for (int i = 0; i < 2; i++) {
            int r = kvr + i * 32;
            size_t g = bhoff + (size_t)(c0 + r) * HD + kvd;
            size_t sm = base + r * 72 + kvd;
            cp16(s2u(&sKh[sm]), &kh_g[g]);
            cp16(s2u(&sVh[sm]), &vh_g[g]);
        }
        cp_commit();
    };

    int ktmax = 2 * qt + 1;
    issue_kv(0, 0);

    #pragma unroll
    for (int i = 0; i < 4; i++) {
        int chunk = tid + i * 256;
        int r = chunk >> 3, d8 = (chunk & 7) * 8;
        size_t g = bhoff + (size_t)(q0 + r) * HD + d8;
        *reinterpret_cast<uint4*>(&sQh[r * 72 + d8]) = *reinterpret_cast<const uint4*>(&qh_g[g]);
    }
    __syncthreads();

    uint32_t qfh[4][4];
    #pragma unroll
    for (int kk = 0; kk < 4; kk++)
        ldsm4(qfh[kk], s2u(&sQh[(w * 16 + lrow) * 72 + kk * 16 + lcol]));

    float m_r[2] = {-1e30f, -1e30f};
    float l_r[2] = {0.f, 0.f};
    float o[8][4];
    #pragma unroll
    for (int j = 0; j < 8; j++)
        #pragma unroll
        for (int c = 0; c < 4; c++) o[j][c] = 0.f;

    for (int kt = 0; kt <= ktmax; kt++) {
        int c0 = kt * 64;
        int st = kt & 1;
        uint32_t offKV = (uint32_t)(st * KVSTRIDE * 2);

        cp_wait<0>();
        __syncthreads();   // stage st ready; all warps done reading the other stage

        if (kt < ktmax) issue_kv(kt + 1, (kt + 1) & 1);

        float s[8][4];
        #pragma unroll
        for (int j = 0; j < 8; j++)
            #pragma unroll
            for (int c = 0; c < 4; c++) s[j][c] = 0.f;

        #pragma unroll
        for (int kk = 0; kk < 4; kk++) {
            #pragma unroll
            for (int g2 = 0; g2 < 4; g2++) {
                uint32_t rh[4];
                ldsm4(rh, s2u(&sKh[(g2 * 16 + lrow) * 72 + kk * 16 + lcol]) + offKV);
                uint32_t b0h[2] = {rh[0], rh[2]}, b1h[2] = {rh[1], rh[3]};
                mma_f16(s[g2 * 2],     qfh[kk], b0h);
                mma_f16(s[g2 * 2 + 1], qfh[kk], b1h);
            }
        }

        if (kt >= 2 * qt) {
            int row0 = q0 + w * 16 + gid;
            #pragma unroll
            for (int j = 0; j < 8; j++) {
                int col = c0 + j * 8 + 2 * tig;
                if (col     > row0)     s[j][0] = -1e30f;
                if (col + 1 > row0)     s[j][1] = -1e30f;
                if (col     > row0 + 8) s[j][2] = -1e30f;
                if (col + 1 > row0 + 8) s[j][3] = -1e30f;
            }
        }

        // ---- online softmax in log2 domain (exp -> MUFU ex2) ----
        float mx0 = -1e30f, mx1 = -1e30f;
        #pragma unroll
        for (int j = 0; j < 8; j++) {
            mx0 = fmaxf(mx0, fmaxf(s[j][0], s[j][1]));
            mx1 = fmaxf(mx1, fmaxf(s[j][2], s[j][3]));
        }
        mx0 = fmaxf(mx0, __shfl_xor_sync(0xffffffffu, mx0, 1));
        mx0 = fmaxf(mx0, __shfl_xor_sync(0xffffffffu, mx0, 2));
        mx1 = fmaxf(mx1, __shfl_xor_sync(0xffffffffu, mx1, 1));
        mx1 = fmaxf(mx1, __shfl_xor_sync(0xffffffffu, mx1, 2));
        float mn0 = fmaxf(m_r[0], mx0);
        float mn1 = fmaxf(m_r[1], mx1);
        float corr0 = ex2(m_r[0] - mn0);
        float corr1 = ex2(m_r[1] - mn1);
        float rs0 = 0.f, rs1 = 0.f;
        #pragma unroll
        for (int j = 0; j < 8; j++) {
            s[j][0] = ex2(s[j][0] - mn0); rs0 += s[j][0];
            s[j][1] = ex2(s[j][1] - mn0); rs0 += s[j][1];
            s[j][2] = ex2(s[j][2] - mn1); rs1 += s[j][2];
            s[j][3] = ex2(s[j][3] - mn1); rs1 += s[j][3];
        }
        rs0 += __shfl_xor_sync(0xffffffffu, rs0, 1);
        rs0 += __shfl_xor_sync(0xffffffffu, rs0, 2);
        rs1 += __shfl_xor_sync(0xffffffffu, rs1, 1);
        rs1 += __shfl_xor_sync(0xffffffffu, rs1, 2);
        l_r[0] = l_r[0] * corr0 + rs0;
        l_r[1] = l_r[1] * corr1 + rs1;
        m_r[0] = mn0; m_r[1] = mn1;
        #pragma unroll
        for (int j = 0; j < 8; j++) {
            o[j][0] *= corr0; o[j][1] *= corr0;
            o[j][2] *= corr1; o[j][3] *= corr1;
        }

        // ---- O += P V (1-pass: P fp16) ----
        #pragma unroll
        for (int kk = 0; kk < 4; kk++) {
            uint32_t ph[4];
            __half2 p0 = __floats2half2_rn(s[2 * kk][0],     s[2 * kk][1]);
            __half2 p1 = __floats2half2_rn(s[2 * kk][2],     s[2 * kk][3]);
            __half2 p2 = __floats2half2_rn(s[2 * kk + 1][0], s[2 * kk + 1][1]);
            __half2 p3 = __floats2half2_rn(s[2 * kk + 1][2], s[2 * kk + 1][3]);
            ph[0] = *reinterpret_cast<uint32_t*>(&p0);
            ph[1] = *reinterpret_cast<uint32_t*>(&p1);
            ph[2] = *reinterpret_cast<uint32_t*>(&p2);
            ph[3] = *reinterpret_cast<uint32_t*>(&p3);
            #pragma unroll
            for (int g2 = 0; g2 < 4; g2++) {
                uint32_t rvh[4];
                ldsm4t(rvh, s2u(&sVh[(kk * 16 + lrow) * 72 + g2 * 16 + lcol]) + offKV);
                uint32_t bh0[2] = {rvh[0], rvh[1]}, bh1[2] = {rvh[2], rvh[3]};
                mma_f16(o[g2 * 2],     ph, bh0);
                mma_f16(o[g2 * 2 + 1], ph, bh1);
            }
        }
    }

    int b = bh >> 4, hh = bh & 15;
    float inv0 = 1.0f / l_r[0];
    float inv1 = 1.0f / l_r[1];
    #pragma unroll
    for (int h2 = 0; h2 < 2; h2++) {
        int srow = q0 + w * 16 + gid + h2 * 8;
        float inv = h2 ? inv1 : inv0;
        size_t base = (((size_t)(b * SEQ + srow)) * HEADS + hh) * HD;
        #pragma unroll
        for (int j = 0; j < 8; j++) {
            float a = o[j][h2 * 2 + 0] * inv;
            float c = o[j][h2 * 2 + 1] * inv;
            __half2 h2v = __floats2half2_rn(a, c);
            int d = j * 8 + 2 * tig;
            *reinterpret_cast<uint32_t*>(&y_hi[base + d]) = *reinterpret_cast<uint32_t*>(&h2v);
        }
    }
}

// ============================ launch ============================
extern "C" void kernel_launch(void* const* d_in, const int* in_sizes, int n_in,
                              void* d_out, int out_size)
{
    const float* x        = (const float*)d_in[0];
    const float* ln_scale = (const float*)d_in[2];
    const float* ln_bias  = (const float*)d_in[3];
    const float* w_qkv    = (const float*)d_in[4];
    const float* b_qkv    = (const float*)d_in[5];
    const float* w_out    = (const float*)d_in[6];
    const float* b_out    = (const float*)d_in[7];
    float* out = (float*)d_out;

    __half *xn_hi, *wq_hi, *wo_hi, *y_hi;
    __half *qh, *kh, *vh;
    cudaGetSymbolAddress((void**)&xn_hi, g_xn_hi);
    cudaGetSymbolAddress((void**)&wq_hi, g_wq_hi);
    cudaGetSymbolAddress((void**)&wo_hi, g_wo_hi);
    cudaGetSymbolAddress((void**)&y_hi,  g_y_hi);
    cudaGetSymbolAddress((void**)&qh, g_qh);
    cudaGetSymbolAddress((void**)&kh, g_kh);
    cudaGetSymbolAddress((void**)&vh, g_vh);

    // 1. LayerNorm -> fp16
    ln_kernel<<<ROWS, 256>>>(x, ln_scale, ln_bias, xn_hi);

    // 1b. weight conversion
    convert_kernel<<<512, 256>>>(w_qkv, wq_hi, DIM * QKV_N);
    convert_kernel<<<256, 256>>>(w_out, wo_hi, DIM * DIM);

    int gemm_smem = 3 * GSTAGE;   // 56832

    // 2. QKV projection (single-pass fp16) -> q/k/v fp16 (q scaled by 0.125*log2e)
    {
        cudaFuncSetAttribute(mma_gemm<0>,
                             cudaFuncAttributeMaxDynamicSharedMemorySize, gemm_smem);
        dim3 grid(QKV_N / 128, ROWS / 128);  // (24, 64)
        mma_gemm<0><<<grid, 256, gemm_smem>>>(xn_hi, wq_hi, b_qkv, nullptr,
                                              ROWS, QKV_N, DIM, qh, kh, vh);
    }

    // 3. tensor-core causal flash attention (log2-domain softmax)
    {
        int smem = (128 * 72 + 4 * KVSTRIDE) * sizeof(__half);  // 55296
        cudaFuncSetAttribute(attn_mma_kernel,
                             cudaFuncAttributeMaxDynamicSharedMemorySize, smem);
        dim3 grid(BATCH * HEADS, SEQ / 128);  // (64, 16)
        attn_mma_kernel<<<grid, 256, smem>>>(qh, kh, vh, y_hi);
    }

    // 4. output projection (single-pass fp16) -> d_out
    {
        cudaFuncSetAttribute(mma_gemm<1>,
                             cudaFuncAttributeMaxDynamicSharedMemorySize, gemm_smem);
        dim3 grid(DIM / 128, ROWS / 128);    // (8, 64)
        mma_gemm<1><<<grid, 256, gemm_smem>>>(y_hi, wo_hi, b_out, out,
                                              ROWS, DIM, DIM,
                                              nullptr, nullptr, nullptr);
    }
}